// round 2
// baseline (speedup 1.0000x reference)
#include <cuda_runtime.h>
#include <cuda_bf16.h>
#include <math.h>

// ---------------- problem constants ----------------
#define BATCH 2
#define SEQ   4096
#define DIM   1024
#define NHEAD 16
#define KVHEAD 4
#define HEADD 64
#define FFD   2816
#define NSEG  256
#define SEGLEN 16
#define KSEG  76
#define KTOK  (KSEG*SEGLEN)      // 1216
#define BT    (BATCH*KTOK)       // 2432 = 19*128
#define NLAYER 12
#define NBLK  2
#define BPL   6
#define RANKR 16
#define NQRY  8

// ---------------- scratch (device globals; no allocs allowed) ----------------
__device__ float g_x   [BT*DIM];
__device__ float g_h   [BT*DIM];
__device__ float g_q   [BT*DIM];
__device__ float g_k   [BT*(KVHEAD*HEADD)];
__device__ float g_v   [BT*(KVHEAD*HEADD)];
__device__ float g_o   [BT*DIM];
__device__ float g_gate[BT*FFD];
__device__ float g_up  [BT*FFD];
__device__ float g_pool[BATCH*NSEG*DIM];
__device__ float g_scores[BATCH*NSEG];
__device__ int   g_tok [BATCH*KTOK];

// ---------------- embed gather ----------------
__global__ void embed_kernel(const int* __restrict__ ids,
                             const float* __restrict__ emb,
                             float* __restrict__ hidden) {
    int row = blockIdx.x;                      // B*S rows
    int id  = ids[row];
    const float4* src = (const float4*)(emb + (size_t)id * DIM);
    float4* dst = (float4*)(hidden + (size_t)row * DIM);
    dst[threadIdx.x] = src[threadIdx.x];       // 256 threads * float4 = 1024
}

// ---------------- segment mean pool ----------------
__global__ void pool_kernel(const float* __restrict__ hidden,
                            float* __restrict__ pooled) {
    int b = blockIdx.x >> 8, n = blockIdx.x & 255;
    const float* base = hidden + ((size_t)b * SEQ + n * SEGLEN) * DIM + threadIdx.x * 4;
    float4 acc = make_float4(0.f, 0.f, 0.f, 0.f);
#pragma unroll
    for (int t = 0; t < SEGLEN; t++) {
        float4 v = *(const float4*)(base + (size_t)t * DIM);
        acc.x += v.x; acc.y += v.y; acc.z += v.z; acc.w += v.w;
    }
    const float s = 1.f / SEGLEN;
    acc.x *= s; acc.y *= s; acc.z *= s; acc.w *= s;
    *(float4*)(pooled + ((size_t)b * NSEG + n) * DIM + threadIdx.x * 4) = acc;
}

// ---------------- multi-query router scores ----------------
__global__ void router_kernel(const float* __restrict__ pooled,
                              const float* __restrict__ rk,   // [DIM,RANKR] for this block
                              const float* __restrict__ rq,   // [NQRY,RANKR]
                              float* __restrict__ scores) {
    int n = blockIdx.x, b = blockIdx.y;
    const float* p = pooled + ((size_t)b * NSEG + n) * DIM;
    __shared__ float part[128];
    int tid = threadIdx.x;                 // 128 threads
    int r = tid & 15, g = tid >> 4;        // 8 d-groups x 16 ranks
    float sum = 0.f;
    int d0 = g * 128;
    for (int d = d0; d < d0 + 128; d++) sum += p[d] * rk[d * RANKR + r];
    part[tid] = sum;
    __syncthreads();
    if (tid < RANKR) {
        float key = 0.f;
        for (int gg = 0; gg < 8; gg++) key += part[gg * 16 + tid];
        part[tid] = key;
    }
    __syncthreads();
    if (tid == 0) {
        float best = -1e30f;
        for (int qq = 0; qq < NQRY; qq++) {
            float dv = 0.f;
            for (int rr = 0; rr < RANKR; rr++) dv += rq[qq * RANKR + rr] * part[rr];
            best = fmaxf(best, dv);
        }
        scores[b * NSEG + n] = best;
    }
}

// ---------------- top-k select (rank-based, matches lax.top_k tie-break) ----------------
__global__ void select_kernel(const float* __restrict__ scores,
                              int* __restrict__ tok) {
    int b = blockIdx.x;
    __shared__ float s[NSEG];
    __shared__ int pf[NSEG];
    int i = threadIdx.x;                   // 256 threads
    float mine = scores[b * NSEG + i];
    s[i] = mine;
    __syncthreads();
    int rank = 0;
    for (int j = 0; j < NSEG; j++) {
        float o = s[j];
        rank += (o > mine) || (o == mine && j < i);
    }
    int sel = (rank < KSEG) ? 1 : 0;
    pf[i] = sel;
    __syncthreads();
    for (int off = 1; off < NSEG; off <<= 1) {   // inclusive Hillis-Steele scan
        int add = (i >= off) ? pf[i - off] : 0;
        __syncthreads();
        pf[i] += add;
        __syncthreads();
    }
    if (sel) {
        int p = pf[i] - 1;                 // ascending segment order => sorted indices
        int* dst = tok + b * KTOK + p * SEGLEN;
        int base = i * SEGLEN;
#pragma unroll
        for (int t = 0; t < SEGLEN; t++) dst[t] = base + t;
    }
}

// ---------------- gather / scatter ----------------
__global__ void gather_kernel(const float* __restrict__ hidden,
                              const int* __restrict__ tok,
                              float* __restrict__ x) {
    int row = blockIdx.x;                  // BT rows
    int b = row / KTOK;
    int tk = tok[row];
    const float4* src = (const float4*)(hidden + ((size_t)b * SEQ + tk) * DIM);
    float4* dst = (float4*)(x + (size_t)row * DIM);
    dst[threadIdx.x] = src[threadIdx.x];
}
__global__ void scatter_kernel(const float* __restrict__ x,
                               const int* __restrict__ tok,
                               float* __restrict__ hidden) {
    int row = blockIdx.x;
    int b = row / KTOK;
    int tk = tok[row];
    const float4* src = (const float4*)(x + (size_t)row * DIM);
    float4* dst = (float4*)(hidden + ((size_t)b * SEQ + tk) * DIM);
    dst[threadIdx.x] = src[threadIdx.x];
}

// ---------------- RMSNorm ----------------
__global__ void rmsnorm_kernel(const float* __restrict__ x,
                               const float* __restrict__ w,
                               float* __restrict__ out) {
    int row = blockIdx.x;
    int t = threadIdx.x;                   // 256
    const float4* xr = (const float4*)(x + (size_t)row * DIM);
    float4 v = xr[t];
    float ss = v.x * v.x + v.y * v.y + v.z * v.z + v.w * v.w;
#pragma unroll
    for (int d = 16; d >= 1; d >>= 1) ss += __shfl_xor_sync(0xffffffffu, ss, d);
    __shared__ float ws[8];
    __shared__ float tot;
    if ((t & 31) == 0) ws[t >> 5] = ss;
    __syncthreads();
    if (t == 0) {
        float a = 0.f;
        for (int wgi = 0; wgi < 8; wgi++) a += ws[wgi];
        tot = a;
    }
    __syncthreads();
    float inv = rsqrtf(tot * (1.f / DIM) + 1e-6f);
    float4 wv = ((const float4*)w)[t];
    float4 o;
    o.x = v.x * inv * wv.x; o.y = v.y * inv * wv.y;
    o.z = v.z * inv * wv.z; o.w = v.w * inv * wv.w;
    ((float4*)(out + (size_t)row * DIM))[t] = o;
}

// ---------------- RoPE (NeoX style, in place on q and k) ----------------
__global__ void rope_kernel(float* __restrict__ q, float* __restrict__ k,
                            const int* __restrict__ tok) {
    int row = blockIdx.x;                  // BT
    float pos = (float)tok[row];
    int t = threadIdx.x;                   // 256
    // q: 16 heads * 32 pairs = 512 pairs
    for (int pidx = t; pidx < NHEAD * 32; pidx += 256) {
        int hh = pidx >> 5, i = pidx & 31;
        float inv = __powf(10000.f, -(float)(2 * i) / (float)HEADD);
        float ang = pos * inv;
        float sn, cs;
        sincosf(ang, &sn, &cs);
        float* qp = q + (size_t)row * DIM + hh * HEADD;
        float x1 = qp[i], x2 = qp[i + 32];
        qp[i]      = x1 * cs - x2 * sn;
        qp[i + 32] = x2 * cs + x1 * sn;
    }
    if (t < KVHEAD * 32) {
        int hh = t >> 5, i = t & 31;
        float inv = __powf(10000.f, -(float)(2 * i) / (float)HEADD);
        float ang = pos * inv;
        float sn, cs;
        sincosf(ang, &sn, &cs);
        float* kp = k + (size_t)row * (KVHEAD * HEADD) + hh * HEADD;
        float x1 = kp[i], x2 = kp[i + 32];
        kp[i]      = x1 * cs - x2 * sn;
        kp[i + 32] = x2 * cs + x1 * sn;
    }
}

// ---------------- SGEMM: C[M,N] = A[M,K] @ W[K,N] (+bias)(+residual) ----------------
// 128x128 tile, TK=8, 256 threads, 8x8 microtile split as 2x2 blocks of 4x4.
template <int FLAGS>   // bit0: add bias, bit1: add existing C (residual)
__global__ void sgemm_kernel(const float* __restrict__ A,
                             const float* __restrict__ W,
                             const float* __restrict__ bias,
                             float* __restrict__ C,
                             int M, int N, int K) {
    __shared__ float As[8][128];
    __shared__ float Bs[8][128];
    int tid = threadIdx.x;
    int m0 = blockIdx.y * 128, n0 = blockIdx.x * 128;
    int arow = tid >> 1, acol = (tid & 1) * 4;
    int brow = tid >> 5, bcol = (tid & 31) * 4;
    int tx = tid & 15, ty = tid >> 4;

    float acc[8][8];
#pragma unroll
    for (int i = 0; i < 8; i++)
#pragma unroll
        for (int j = 0; j < 8; j++) acc[i][j] = 0.f;

    const float* Aptr = A + (size_t)(m0 + arow) * K + acol;
    const float* Wptr = W + (size_t)brow * N + n0 + bcol;

    for (int k0 = 0; k0 < K; k0 += 8) {
        float4 av = *(const float4*)Aptr;  Aptr += 8;
        float4 bv = *(const float4*)Wptr;  Wptr += (size_t)8 * N;
        __syncthreads();
        As[acol + 0][arow] = av.x;
        As[acol + 1][arow] = av.y;
        As[acol + 2][arow] = av.z;
        As[acol + 3][arow] = av.w;
        *(float4*)&Bs[brow][bcol] = bv;
        __syncthreads();
#pragma unroll
        for (int k = 0; k < 8; k++) {
            float a[8], b[8];
            *(float4*)(a)     = *(float4*)&As[k][ty * 4];
            *(float4*)(a + 4) = *(float4*)&As[k][64 + ty * 4];
            *(float4*)(b)     = *(float4*)&Bs[k][tx * 4];
            *(float4*)(b + 4) = *(float4*)&Bs[k][64 + tx * 4];
#pragma unroll
            for (int i = 0; i < 8; i++)
#pragma unroll
                for (int j = 0; j < 8; j++) acc[i][j] += a[i] * b[j];
        }
    }
    // epilogue
#pragma unroll
    for (int i = 0; i < 8; i++) {
        int row = m0 + ((i & 4) ? 64 : 0) + ty * 4 + (i & 3);
        float* Crow = C + (size_t)row * N + n0;
#pragma unroll
        for (int half = 0; half < 2; half++) {
            int cb = half * 64 + tx * 4;
            float4 r;
            r.x = acc[i][half * 4 + 0]; r.y = acc[i][half * 4 + 1];
            r.z = acc[i][half * 4 + 2]; r.w = acc[i][half * 4 + 3];
            if (FLAGS & 1) {
                float4 bb = *(const float4*)&bias[n0 + cb];
                r.x += bb.x; r.y += bb.y; r.z += bb.z; r.w += bb.w;
            }
            if (FLAGS & 2) {
                float4 cc = *(const float4*)&Crow[cb];
                r.x += cc.x; r.y += cc.y; r.z += cc.z; r.w += cc.w;
            }
            *(float4*)&Crow[cb] = r;
        }
    }
}

// ---------------- flash attention (fp32, causal, GQA) ----------------
// grid (T/64, NHEAD, BATCH), 256 threads, dynamic smem 4*64*68*4 = 69632 B
#define AT_STRIDE 68
#define SMEM_ATTN (4 * 64 * AT_STRIDE * 4)
__global__ void flash_attn_kernel(const float* __restrict__ q,
                                  const float* __restrict__ kk,
                                  const float* __restrict__ vv,
                                  float* __restrict__ o) {
    extern __shared__ float sm[];
    float* Qs = sm;                        // [64][68] row-major (token, d)
    float* Ks = sm + 64 * AT_STRIDE;       // [64][68] row-major (token, d)
    float* Vt = sm + 2 * 64 * AT_STRIDE;   // [64][68] transposed (d, token)
    float* Ps = sm + 3 * 64 * AT_STRIDE;   // [64][68] row-major (qrow, kcol)
    const int T = KTOK;
    int qt = blockIdx.x, h = blockIdx.y, b = blockIdx.z;
    int kh = h >> 2;
    int tid = threadIdx.x, tx = tid & 15, ty = tid >> 4;
    const float scale = 0.125f;            // 1/sqrt(64)

    // load Q tile (scaled)
    for (int i = tid; i < 1024; i += 256) {
        int row = i >> 4, c4 = (i & 15) << 2;
        float4 v = *(const float4*)&q[((size_t)(b * T + qt * 64 + row)) * DIM + h * HEADD + c4];
        float* dst = &Qs[row * AT_STRIDE + c4];
        dst[0] = v.x * scale; dst[1] = v.y * scale;
        dst[2] = v.z * scale; dst[3] = v.w * scale;
    }
    float acc[4][4];
    float m_i[4], l_i[4];
#pragma unroll
    for (int i = 0; i < 4; i++) {
        m_i[i] = -1e30f; l_i[i] = 0.f;
#pragma unroll
        for (int c = 0; c < 4; c++) acc[i][c] = 0.f;
    }

    for (int kt = 0; kt <= qt; kt++) {
        // load K row-major + V transposed
        for (int i = tid; i < 1024; i += 256) {
            int row = i >> 4, c4 = (i & 15) << 2;
            size_t base = ((size_t)(b * T + kt * 64 + row)) * (KVHEAD * HEADD) + kh * HEADD + c4;
            float4 k4 = *(const float4*)&kk[base];
            *(float4*)&Ks[row * AT_STRIDE + c4] = k4;
            float4 v4 = *(const float4*)&vv[base];
            Vt[(c4 + 0) * AT_STRIDE + row] = v4.x;
            Vt[(c4 + 1) * AT_STRIDE + row] = v4.y;
            Vt[(c4 + 2) * AT_STRIDE + row] = v4.z;
            Vt[(c4 + 3) * AT_STRIDE + row] = v4.w;
        }
        __syncthreads();

        // S = Q K^T : rows ty*4+i, cols tx+16*j
        float s[4][4];
#pragma unroll
        for (int i = 0; i < 4; i++)
#pragma unroll
            for (int j = 0; j < 4; j++) s[i][j] = 0.f;
        for (int kd = 0; kd < 64; kd += 4) {
            float4 qa[4], kb[4];
#pragma unroll
            for (int i = 0; i < 4; i++) qa[i] = *(float4*)&Qs[(ty * 4 + i) * AT_STRIDE + kd];
#pragma unroll
            for (int j = 0; j < 4; j++) kb[j] = *(float4*)&Ks[(tx + 16 * j) * AT_STRIDE + kd];
#pragma unroll
            for (int i = 0; i < 4; i++)
#pragma unroll
                for (int j = 0; j < 4; j++)
                    s[i][j] += qa[i].x * kb[j].x + qa[i].y * kb[j].y +
                               qa[i].z * kb[j].z + qa[i].w * kb[j].w;
        }
        if (kt == qt) {
#pragma unroll
            for (int i = 0; i < 4; i++)
#pragma unroll
                for (int j = 0; j < 4; j++)
                    if (tx + 16 * j > ty * 4 + i) s[i][j] = -1e30f;
        }
        // online softmax update
#pragma unroll
        for (int i = 0; i < 4; i++) {
            float mx = fmaxf(fmaxf(s[i][0], s[i][1]), fmaxf(s[i][2], s[i][3]));
#pragma unroll
            for (int d = 1; d < 16; d <<= 1) mx = fmaxf(mx, __shfl_xor_sync(0xffffffffu, mx, d));
            float mnew = fmaxf(m_i[i], mx);
            float corr = __expf(m_i[i] - mnew);
            float psum = 0.f;
#pragma unroll
            for (int j = 0; j < 4; j++) {
                float p = __expf(s[i][j] - mnew);
                s[i][j] = p;
                psum += p;
            }
#pragma unroll
            for (int d = 1; d < 16; d <<= 1) psum += __shfl_xor_sync(0xffffffffu, psum, d);
            l_i[i] = l_i[i] * corr + psum;
            m_i[i] = mnew;
#pragma unroll
            for (int c = 0; c < 4; c++) acc[i][c] *= corr;
#pragma unroll
            for (int j = 0; j < 4; j++) Ps[(ty * 4 + i) * AT_STRIDE + tx + 16 * j] = s[i][j];
        }
        __syncthreads();
        // O += P V
        for (int jr = 0; jr < 64; jr += 4) {
            float4 p4[4], v4[4];
#pragma unroll
            for (int i = 0; i < 4; i++) p4[i] = *(float4*)&Ps[(ty * 4 + i) * AT_STRIDE + jr];
#pragma unroll
            for (int c = 0; c < 4; c++) v4[c] = *(float4*)&Vt[(tx + 16 * c) * AT_STRIDE + jr];
#pragma unroll
            for (int i = 0; i < 4; i++)
#pragma unroll
                for (int c = 0; c < 4; c++)
                    acc[i][c] += p4[i].x * v4[c].x + p4[i].y * v4[c].y +
                                 p4[i].z * v4[c].z + p4[i].w * v4[c].w;
        }
        __syncthreads();
    }
    // write O (normalized)
#pragma unroll
    for (int i = 0; i < 4; i++) {
        float inv = 1.f / l_i[i];
        size_t rbase = ((size_t)(b * T + qt * 64 + ty * 4 + i)) * DIM + h * HEADD;
#pragma unroll
        for (int c = 0; c < 4; c++) o[rbase + tx + 16 * c] = acc[i][c] * inv;
    }
}

// ---------------- silu(gate)*up (in place into gate) ----------------
__global__ void silu_mul_kernel(float* __restrict__ g, const float* __restrict__ u, int n4) {
    int i = blockIdx.x * blockDim.x + threadIdx.x;
    if (i >= n4) return;
    float4 x = ((float4*)g)[i];
    float4 y = ((const float4*)u)[i];
    x.x = x.x / (1.f + __expf(-x.x)) * y.x;
    x.y = x.y / (1.f + __expf(-x.y)) * y.y;
    x.z = x.z / (1.f + __expf(-x.z)) * y.z;
    x.w = x.w / (1.f + __expf(-x.w)) * y.w;
    ((float4*)g)[i] = x;
}

// ---------------- launch ----------------
extern "C" void kernel_launch(void* const* d_in, const int* in_sizes, int n_in,
                              void* d_out, int out_size) {
    const int*   ids      = (const int*)d_in[0];
    const float* emb      = (const float*)d_in[1];
    const float* router_k = (const float*)d_in[2];
    const float* router_q = (const float*)d_in[3];
    const float* ln1      = (const float*)d_in[4];
    const float* ln2      = (const float*)d_in[5];
    const float* wq       = (const float*)d_in[6];
    const float* bq       = (const float*)d_in[7];
    const float* wk       = (const float*)d_in[8];
    const float* bk       = (const float*)d_in[9];
    const float* wv       = (const float*)d_in[10];
    const float* bv       = (const float*)d_in[11];
    const float* wo       = (const float*)d_in[12];
    const float* wg       = (const float*)d_in[13];
    const float* wu       = (const float*)d_in[14];
    const float* wd       = (const float*)d_in[15];
    float* hidden = (float*)d_out;

    float *x, *h, *q, *k, *v, *o, *gate, *up, *pooled, *scores;
    int* tok;
    cudaGetSymbolAddress((void**)&x, g_x);
    cudaGetSymbolAddress((void**)&h, g_h);
    cudaGetSymbolAddress((void**)&q, g_q);
    cudaGetSymbolAddress((void**)&k, g_k);
    cudaGetSymbolAddress((void**)&v, g_v);
    cudaGetSymbolAddress((void**)&o, g_o);
    cudaGetSymbolAddress((void**)&gate, g_gate);
    cudaGetSymbolAddress((void**)&up, g_up);
    cudaGetSymbolAddress((void**)&pooled, g_pool);
    cudaGetSymbolAddress((void**)&scores, g_scores);
    cudaGetSymbolAddress((void**)&tok, g_tok);

    cudaFuncSetAttribute(flash_attn_kernel,
                         cudaFuncAttributeMaxDynamicSharedMemorySize, SMEM_ATTN);

    embed_kernel<<<BATCH * SEQ, 256>>>(ids, emb, hidden);

    for (int blk = 0; blk < NBLK; blk++) {
        pool_kernel<<<BATCH * NSEG, 256>>>(hidden, pooled);
        router_kernel<<<dim3(NSEG, BATCH), 128>>>(
            pooled, router_k + (size_t)blk * DIM * RANKR,
            router_q + (size_t)blk * NQRY * RANKR, scores);
        select_kernel<<<BATCH, 256>>>(scores, tok);
        gather_kernel<<<BT, 256>>>(hidden, tok, x);

        for (int j = 0; j < BPL; j++) {
            int li = blk * BPL + j;
            rmsnorm_kernel<<<BT, 256>>>(x, ln1 + (size_t)li * DIM, h);
            sgemm_kernel<1><<<dim3(DIM / 128, BT / 128), 256>>>(
                h, wq + (size_t)li * DIM * DIM, bq + (size_t)li * DIM, q, BT, DIM, DIM);
            sgemm_kernel<1><<<dim3((KVHEAD * HEADD) / 128, BT / 128), 256>>>(
                h, wk + (size_t)li * DIM * KVHEAD * HEADD, bk + (size_t)li * KVHEAD * HEADD,
                k, BT, KVHEAD * HEADD, DIM);
            sgemm_kernel<1><<<dim3((KVHEAD * HEADD) / 128, BT / 128), 256>>>(
                h, wv + (size_t)li * DIM * KVHEAD * HEADD, bv + (size_t)li * KVHEAD * HEADD,
                v, BT, KVHEAD * HEADD, DIM);
            rope_kernel<<<BT, 256>>>(q, k, tok);
            flash_attn_kernel<<<dim3(KTOK / 64, NHEAD, BATCH), 256, SMEM_ATTN>>>(q, k, v, o);
            sgemm_kernel<2><<<dim3(DIM / 128, BT / 128), 256>>>(
                o, wo + (size_t)li * DIM * DIM, nullptr, x, BT, DIM, DIM);
            rmsnorm_kernel<<<BT, 256>>>(x, ln2 + (size_t)li * DIM, h);
            sgemm_kernel<0><<<dim3(FFD / 128, BT / 128), 256>>>(
                h, wg + (size_t)li * DIM * FFD, nullptr, gate, BT, FFD, DIM);
            sgemm_kernel<0><<<dim3(FFD / 128, BT / 128), 256>>>(
                h, wu + (size_t)li * DIM * FFD, nullptr, up, BT, FFD, DIM);
            int n4 = BT * FFD / 4;
            silu_mul_kernel<<<(n4 + 255) / 256, 256>>>(gate, up, n4);
            sgemm_kernel<2><<<dim3(DIM / 128, BT / 128), 256>>>(
                gate, wd + (size_t)li * FFD * DIM, nullptr, x, BT, DIM, FFD);
        }
        scatter_kernel<<<BT, 256>>>(x, tok, hidden);
    }
}

// round 9
// speedup vs baseline: 1.6603x; 1.6603x over previous
#include <cuda_runtime.h>
#include <cuda_bf16.h>
#include <math.h>
#include <stdint.h>

// ---------------- problem constants ----------------
#define BATCH 2
#define SEQ   4096
#define DIM   1024
#define NHEAD 16
#define KVHEAD 4
#define HEADD 64
#define FFD   2816
#define NSEG  256
#define SEGLEN 16
#define KSEG  76
#define KTOK  (KSEG*SEGLEN)      // 1216
#define BT    (BATCH*KTOK)       // 2432 = 19*128
#define NLAYER 12
#define NBLK  2
#define BPL   6
#define RANKR 16
#define NQRY  8

// ---------------- scratch (device globals; no allocs allowed) ----------------
__device__ float g_x   [BT*DIM];
__device__ float g_h   [BT*DIM];
__device__ float g_q   [BT*DIM];
__device__ float g_k   [BT*(KVHEAD*HEADD)];
__device__ float g_v   [BT*(KVHEAD*HEADD)];
__device__ float g_o   [BT*DIM];
__device__ float g_gate[BT*FFD];
__device__ float g_up  [BT*FFD];
__device__ float g_pool[BATCH*NSEG*DIM];
__device__ float g_scores[BATCH*NSEG];
__device__ int   g_tok [BATCH*KTOK];

// ---------------- embed gather ----------------
__global__ void embed_kernel(const int* __restrict__ ids,
                             const float* __restrict__ emb,
                             float* __restrict__ hidden) {
    int row = blockIdx.x;
    int id  = ids[row];
    const float4* src = (const float4*)(emb + (size_t)id * DIM);
    float4* dst = (float4*)(hidden + (size_t)row * DIM);
    dst[threadIdx.x] = src[threadIdx.x];
}

// ---------------- segment mean pool ----------------
__global__ void pool_kernel(const float* __restrict__ hidden,
                            float* __restrict__ pooled) {
    int b = blockIdx.x >> 8, n = blockIdx.x & 255;
    const float* base = hidden + ((size_t)b * SEQ + n * SEGLEN) * DIM + threadIdx.x * 4;
    float4 acc = make_float4(0.f, 0.f, 0.f, 0.f);
#pragma unroll
    for (int t = 0; t < SEGLEN; t++) {
        float4 v = *(const float4*)(base + (size_t)t * DIM);
        acc.x += v.x; acc.y += v.y; acc.z += v.z; acc.w += v.w;
    }
    const float s = 1.f / SEGLEN;
    acc.x *= s; acc.y *= s; acc.z *= s; acc.w *= s;
    *(float4*)(pooled + ((size_t)b * NSEG + n) * DIM + threadIdx.x * 4) = acc;
}

// ---------------- multi-query router scores ----------------
__global__ void router_kernel(const float* __restrict__ pooled,
                              const float* __restrict__ rk,
                              const float* __restrict__ rq,
                              float* __restrict__ scores) {
    int n = blockIdx.x, b = blockIdx.y;
    const float* p = pooled + ((size_t)b * NSEG + n) * DIM;
    __shared__ float part[128];
    int tid = threadIdx.x;
    int r = tid & 15, g = tid >> 4;
    float sum = 0.f;
    int d0 = g * 128;
    for (int d = d0; d < d0 + 128; d++) sum += p[d] * rk[d * RANKR + r];
    part[tid] = sum;
    __syncthreads();
    if (tid < RANKR) {
        float key = 0.f;
        for (int gg = 0; gg < 8; gg++) key += part[gg * 16 + tid];
        part[tid] = key;
    }
    __syncthreads();
    if (tid == 0) {
        float best = -1e30f;
        for (int qq = 0; qq < NQRY; qq++) {
            float dv = 0.f;
            for (int rr = 0; rr < RANKR; rr++) dv += rq[qq * RANKR + rr] * part[rr];
            best = fmaxf(best, dv);
        }
        scores[b * NSEG + n] = best;
    }
}

// ---------------- top-k select ----------------
__global__ void select_kernel(const float* __restrict__ scores,
                              int* __restrict__ tok) {
    int b = blockIdx.x;
    __shared__ float s[NSEG];
    __shared__ int pf[NSEG];
    int i = threadIdx.x;
    float mine = scores[b * NSEG + i];
    s[i] = mine;
    __syncthreads();
    int rank = 0;
    for (int j = 0; j < NSEG; j++) {
        float o = s[j];
        rank += (o > mine) || (o == mine && j < i);
    }
    int sel = (rank < KSEG) ? 1 : 0;
    pf[i] = sel;
    __syncthreads();
    for (int off = 1; off < NSEG; off <<= 1) {
        int add = (i >= off) ? pf[i - off] : 0;
        __syncthreads();
        pf[i] += add;
        __syncthreads();
    }
    if (sel) {
        int p = pf[i] - 1;
        int* dst = tok + b * KTOK + p * SEGLEN;
        int base = i * SEGLEN;
#pragma unroll
        for (int t = 0; t < SEGLEN; t++) dst[t] = base + t;
    }
}

// ---------------- gather / scatter ----------------
__global__ void gather_kernel(const float* __restrict__ hidden,
                              const int* __restrict__ tok,
                              float* __restrict__ x) {
    int row = blockIdx.x;
    int b = row / KTOK;
    int tk = tok[row];
    const float4* src = (const float4*)(hidden + ((size_t)b * SEQ + tk) * DIM);
    float4* dst = (float4*)(x + (size_t)row * DIM);
    dst[threadIdx.x] = src[threadIdx.x];
}
__global__ void scatter_kernel(const float* __restrict__ x,
                               const int* __restrict__ tok,
                               float* __restrict__ hidden) {
    int row = blockIdx.x;
    int b = row / KTOK;
    int tk = tok[row];
    const float4* src = (const float4*)(x + (size_t)row * DIM);
    float4* dst = (float4*)(hidden + ((size_t)b * SEQ + tk) * DIM);
    dst[threadIdx.x] = src[threadIdx.x];
}

// ---------------- RMSNorm ----------------
__global__ void rmsnorm_kernel(const float* __restrict__ x,
                               const float* __restrict__ w,
                               float* __restrict__ out) {
    int row = blockIdx.x;
    int t = threadIdx.x;
    const float4* xr = (const float4*)(x + (size_t)row * DIM);
    float4 v = xr[t];
    float ss = v.x * v.x + v.y * v.y + v.z * v.z + v.w * v.w;
#pragma unroll
    for (int d = 16; d >= 1; d >>= 1) ss += __shfl_xor_sync(0xffffffffu, ss, d);
    __shared__ float ws[8];
    __shared__ float tot;
    if ((t & 31) == 0) ws[t >> 5] = ss;
    __syncthreads();
    if (t == 0) {
        float a = 0.f;
        for (int wgi = 0; wgi < 8; wgi++) a += ws[wgi];
        tot = a;
    }
    __syncthreads();
    float inv = rsqrtf(tot * (1.f / DIM) + 1e-6f);
    float4 wv = ((const float4*)w)[t];
    float4 o;
    o.x = v.x * inv * wv.x; o.y = v.y * inv * wv.y;
    o.z = v.z * inv * wv.z; o.w = v.w * inv * wv.w;
    ((float4*)(out + (size_t)row * DIM))[t] = o;
}

// ---------------- RoPE ----------------
__global__ void rope_kernel(float* __restrict__ q, float* __restrict__ k,
                            const int* __restrict__ tok) {
    int row = blockIdx.x;
    float pos = (float)tok[row];
    int t = threadIdx.x;
    for (int pidx = t; pidx < NHEAD * 32; pidx += 256) {
        int hh = pidx >> 5, i = pidx & 31;
        float inv = __powf(10000.f, -(float)(2 * i) / (float)HEADD);
        float ang = pos * inv;
        float sn, cs;
        sincosf(ang, &sn, &cs);
        float* qp = q + (size_t)row * DIM + hh * HEADD;
        float x1 = qp[i], x2 = qp[i + 32];
        qp[i]      = x1 * cs - x2 * sn;
        qp[i + 32] = x2 * cs + x1 * sn;
    }
    if (t < KVHEAD * 32) {
        int hh = t >> 5, i = t & 31;
        float inv = __powf(10000.f, -(float)(2 * i) / (float)HEADD);
        float ang = pos * inv;
        float sn, cs;
        sincosf(ang, &sn, &cs);
        float* kp = k + (size_t)row * (KVHEAD * HEADD) + hh * HEADD;
        float x1 = kp[i], x2 = kp[i + 32];
        kp[i]      = x1 * cs - x2 * sn;
        kp[i + 32] = x2 * cs + x1 * sn;
    }
}

// ---------------- split-bf16 (3xMMA) tensor-core GEMM ----------------
// C[M,N] = A[M,K] @ W[K,N] (+bias)(+residual), fp32-accurate via
// A*B ~= Ah*Bh + Al*Bh + Ah*Bl (bf16 hi/lo splitting, err ~2^-18).
// 128x128 CTA tile, K-tile 32, 256 threads = 2(M) x 4(N) warps, 64x32 warp tile.
// mma.sync.aligned.m16n8k16.row.col.f32.bf16.bf16.f32
#define ASU 20     // u32 stride for A pairs: banks 20g+t distinct over 8x4 lanes
#define BSU 136    // u32 stride for B pairs: banks 8t+g distinct over 4x8 lanes

__device__ __forceinline__ uint32_t pack_bf16(float a, float b) {
    uint16_t lo = __bfloat16_as_ushort(__float2bfloat16_rn(a));
    uint16_t hi = __bfloat16_as_ushort(__float2bfloat16_rn(b));
    return (uint32_t)lo | ((uint32_t)hi << 16);
}
__device__ __forceinline__ void split2(float x, float& h, float& l) {
    __nv_bfloat16 hb = __float2bfloat16_rn(x);
    h = __bfloat162float(hb);
    l = x - h;
}
__device__ __forceinline__ void mma_bf16(float c[4], const uint32_t a[4], const uint32_t b[2]) {
    asm volatile(
        "mma.sync.aligned.m16n8k16.row.col.f32.bf16.bf16.f32 "
        "{%0,%1,%2,%3}, {%4,%5,%6,%7}, {%8,%9}, {%0,%1,%2,%3};\n"
        : "+f"(c[0]), "+f"(c[1]), "+f"(c[2]), "+f"(c[3])
        : "r"(a[0]), "r"(a[1]), "r"(a[2]), "r"(a[3]), "r"(b[0]), "r"(b[1]));
}

template <int FLAGS>   // bit0: add bias, bit1: add existing C (residual)
__global__ void __launch_bounds__(256)
bf16x3_gemm_kernel(const float* __restrict__ A,
                   const float* __restrict__ W,
                   const float* __restrict__ bias,
                   float* __restrict__ C,
                   int M, int N, int K) {
    __shared__ uint32_t Ah[128 * ASU];
    __shared__ uint32_t Al[128 * ASU];
    __shared__ uint32_t Bh[16 * BSU];
    __shared__ uint32_t Bl[16 * BSU];
    int tid = threadIdx.x, lane = tid & 31, warp = tid >> 5;
    int warpM = warp & 1, warpN = warp >> 1;
    int m0 = blockIdx.y * 128, n0 = blockIdx.x * 128;
    int gid = lane >> 2, tig = lane & 3;

    float c[4][4][4];
#pragma unroll
    for (int i = 0; i < 4; i++)
#pragma unroll
        for (int j = 0; j < 4; j++)
#pragma unroll
            for (int f = 0; f < 4; f++) c[i][j][f] = 0.f;

    for (int k0 = 0; k0 < K; k0 += 32) {
        // ---- global prefetch into regs ----
        float4 aV[4];                       // A: 128x32 = 1024 float4
#pragma unroll
        for (int i = 0; i < 4; i++) {
            int f = tid + 256 * i;
            aV[i] = *(const float4*)&A[(size_t)(m0 + (f >> 3)) * K + k0 + (f & 7) * 4];
        }
        float4 b0V[2], b1V[2];              // B: 16 pair-rows x 32 col-groups
#pragma unroll
        for (int i = 0; i < 2; i++) {
            int t = tid + 256 * i;
            int pr = t >> 5, cg = t & 31;
            b0V[i] = *(const float4*)&W[(size_t)(k0 + 2 * pr) * N + n0 + cg * 4];
            b1V[i] = *(const float4*)&W[(size_t)(k0 + 2 * pr + 1) * N + n0 + cg * 4];
        }
        __syncthreads();
        // ---- split + pack + store to smem ----
#pragma unroll
        for (int i = 0; i < 4; i++) {
            int f = tid + 256 * i;
            int row = f >> 3, pb = (f & 7) * 2;
            float hx, lx, hy, ly, hz, lz, hw, lw;
            split2(aV[i].x, hx, lx); split2(aV[i].y, hy, ly);
            split2(aV[i].z, hz, lz); split2(aV[i].w, hw, lw);
            uint2 hu = make_uint2(pack_bf16(hx, hy), pack_bf16(hz, hw));
            uint2 lu = make_uint2(pack_bf16(lx, ly), pack_bf16(lz, lw));
            *(uint2*)&Ah[row * ASU + pb] = hu;
            *(uint2*)&Al[row * ASU + pb] = lu;
        }
#pragma unroll
        for (int i = 0; i < 2; i++) {
            int t = tid + 256 * i;
            int pr = t >> 5, cg = t & 31;
            float h0, l0, h1, l1;
            uint4 hu, lu;
            split2(b0V[i].x, h0, l0); split2(b1V[i].x, h1, l1);
            hu.x = pack_bf16(h0, h1); lu.x = pack_bf16(l0, l1);
            split2(b0V[i].y, h0, l0); split2(b1V[i].y, h1, l1);
            hu.y = pack_bf16(h0, h1); lu.y = pack_bf16(l0, l1);
            split2(b0V[i].z, h0, l0); split2(b1V[i].z, h1, l1);
            hu.z = pack_bf16(h0, h1); lu.z = pack_bf16(l0, l1);
            split2(b0V[i].w, h0, l0); split2(b1V[i].w, h1, l1);
            hu.w = pack_bf16(h0, h1); lu.w = pack_bf16(l0, l1);
            *(uint4*)&Bh[pr * BSU + cg * 4] = hu;
            *(uint4*)&Bl[pr * BSU + cg * 4] = lu;
        }
        __syncthreads();
        // ---- MMA: two k16 chunks per K-tile ----
#pragma unroll
        for (int kk = 0; kk < 2; kk++) {
            int kp = kk * 8;
            uint32_t bh[4][2], bl[4][2];
#pragma unroll
            for (int nt = 0; nt < 4; nt++) {
                int cb = warpN * 32 + nt * 8 + gid;
                bh[nt][0] = Bh[(kp + tig) * BSU + cb];
                bh[nt][1] = Bh[(kp + tig + 4) * BSU + cb];
                bl[nt][0] = Bl[(kp + tig) * BSU + cb];
                bl[nt][1] = Bl[(kp + tig + 4) * BSU + cb];
            }
#pragma unroll
            for (int mt = 0; mt < 4; mt++) {
                int rb = warpM * 64 + mt * 16 + gid;
                uint32_t ah[4], al[4];
                ah[0] = Ah[rb * ASU + kp + tig];
                ah[1] = Ah[(rb + 8) * ASU + kp + tig];
                ah[2] = Ah[rb * ASU + kp + tig + 4];
                ah[3] = Ah[(rb + 8) * ASU + kp + tig + 4];
                al[0] = Al[rb * ASU + kp + tig];
                al[1] = Al[(rb + 8) * ASU + kp + tig];
                al[2] = Al[rb * ASU + kp + tig + 4];
                al[3] = Al[(rb + 8) * ASU + kp + tig + 4];
#pragma unroll
                for (int nt = 0; nt < 4; nt++) {
                    mma_bf16(c[mt][nt], ah, bh[nt]);
                    mma_bf16(c[mt][nt], al, bh[nt]);
                    mma_bf16(c[mt][nt], ah, bl[nt]);
                }
            }
        }
    }
    // ---- epilogue ----
#pragma unroll
    for (int mt = 0; mt < 4; mt++) {
#pragma unroll
        for (int half = 0; half < 2; half++) {
            int row = m0 + warpM * 64 + mt * 16 + gid + half * 8;
            float* Crow = C + (size_t)row * N + n0 + warpN * 32;
#pragma unroll
            for (int nt = 0; nt < 4; nt++) {
                int col = nt * 8 + tig * 2;
                float2 r;
                r.x = c[mt][nt][half * 2 + 0];
                r.y = c[mt][nt][half * 2 + 1];
                if (FLAGS & 1) {
                    float2 bb = *(const float2*)&bias[n0 + warpN * 32 + col];
                    r.x += bb.x; r.y += bb.y;
                }
                if (FLAGS & 2) {
                    float2 cc = *(const float2*)&Crow[col];
                    r.x += cc.x; r.y += cc.y;
                }
                *(float2*)&Crow[col] = r;
            }
        }
    }
}

// ---------------- flash attention (fp32, causal, GQA) ----------------
#define AT_STRIDE 68
#define SMEM_ATTN (4 * 64 * AT_STRIDE * 4)
__global__ void flash_attn_kernel(const float* __restrict__ q,
                                  const float* __restrict__ kk,
                                  const float* __restrict__ vv,
                                  float* __restrict__ o) {
    extern __shared__ float sm[];
    float* Qs = sm;
    float* Ks = sm + 64 * AT_STRIDE;
    float* Vt = sm + 2 * 64 * AT_STRIDE;
    float* Ps = sm + 3 * 64 * AT_STRIDE;
    const int T = KTOK;
    int qt = blockIdx.x, h = blockIdx.y, b = blockIdx.z;
    int kh = h >> 2;
    int tid = threadIdx.x, tx = tid & 15, ty = tid >> 4;
    const float scale = 0.125f;

    for (int i = tid; i < 1024; i += 256) {
        int row = i >> 4, c4 = (i & 15) << 2;
        float4 v = *(const float4*)&q[((size_t)(b * T + qt * 64 + row)) * DIM + h * HEADD + c4];
        float* dst = &Qs[row * AT_STRIDE + c4];
        dst[0] = v.x * scale; dst[1] = v.y * scale;
        dst[2] = v.z * scale; dst[3] = v.w * scale;
    }
    float acc[4][4];
    float m_i[4], l_i[4];
#pragma unroll
    for (int i = 0; i < 4; i++) {
        m_i[i] = -1e30f; l_i[i] = 0.f;
#pragma unroll
        for (int cc = 0; cc < 4; cc++) acc[i][cc] = 0.f;
    }

    for (int kt = 0; kt <= qt; kt++) {
        for (int i = tid; i < 1024; i += 256) {
            int row = i >> 4, c4 = (i & 15) << 2;
            size_t base = ((size_t)(b * T + kt * 64 + row)) * (KVHEAD * HEADD) + kh * HEADD + c4;
            float4 k4 = *(const float4*)&kk[base];
            *(float4*)&Ks[row * AT_STRIDE + c4] = k4;
            float4 v4 = *(const float4*)&vv[base];
            Vt[(c4 + 0) * AT_STRIDE + row] = v4.x;
            Vt[(c4 + 1) * AT_STRIDE + row] = v4.y;
            Vt[(c4 + 2) * AT_STRIDE + row] = v4.z;
            Vt[(c4 + 3) * AT_STRIDE + row] = v4.w;
        }
        __syncthreads();

        float s[4][4];
#pragma unroll
        for (int i = 0; i < 4; i++)
#pragma unroll
            for (int j = 0; j < 4; j++) s[i][j] = 0.f;
        for (int kd = 0; kd < 64; kd += 4) {
            float4 qa[4], kb[4];
#pragma unroll
            for (int i = 0; i < 4; i++) qa[i] = *(float4*)&Qs[(ty * 4 + i) * AT_STRIDE + kd];
#pragma unroll
            for (int j = 0; j < 4; j++) kb[j] = *(float4*)&Ks[(tx + 16 * j) * AT_STRIDE + kd];
#pragma unroll
            for (int i = 0; i < 4; i++)
#pragma unroll
                for (int j = 0; j < 4; j++)
                    s[i][j] += qa[i].x * kb[j].x + qa[i].y * kb[j].y +
                               qa[i].z * kb[j].z + qa[i].w * kb[j].w;
        }
        if (kt == qt) {
#pragma unroll
            for (int i = 0; i < 4; i++)
#pragma unroll
                for (int j = 0; j < 4; j++)
                    if (tx + 16 * j > ty * 4 + i) s[i][j] = -1e30f;
        }
#pragma unroll
        for (int i = 0; i < 4; i++) {
            float mx = fmaxf(fmaxf(s[i][0], s[i][1]), fmaxf(s[i][2], s[i][3]));
#pragma unroll
            for (int d = 1; d < 16; d <<= 1) mx = fmaxf(mx, __shfl_xor_sync(0xffffffffu, mx, d));
            float mnew = fmaxf(m_i[i], mx);
            float corr = __expf(m_i[i] - mnew);
            float psum = 0.f;
#pragma unroll
            for (int j = 0; j < 4; j++) {
                float p = __expf(s[i][j] - mnew);
                s[i][j] = p;
                psum += p;
            }
#pragma unroll
            for (int d = 1; d < 16; d <<= 1) psum += __shfl_xor_sync(0xffffffffu, psum, d);
            l_i[i] = l_i[i] * corr + psum;
            m_i[i] = mnew;
#pragma unroll
            for (int cc = 0; cc < 4; cc++) acc[i][cc] *= corr;
#pragma unroll
            for (int j = 0; j < 4; j++) Ps[(ty * 4 + i) * AT_STRIDE + tx + 16 * j] = s[i][j];
        }
        __syncthreads();
        for (int jr = 0; jr < 64; jr += 4) {
            float4 p4[4], v4[4];
#pragma unroll
            for (int i = 0; i < 4; i++) p4[i] = *(float4*)&Ps[(ty * 4 + i) * AT_STRIDE + jr];
#pragma unroll
            for (int cc = 0; cc < 4; cc++) v4[cc] = *(float4*)&Vt[(tx + 16 * cc) * AT_STRIDE + jr];
#pragma unroll
            for (int i = 0; i < 4; i++)
#pragma unroll
                for (int cc = 0; cc < 4; cc++)
                    acc[i][cc] += p4[i].x * v4[cc].x + p4[i].y * v4[cc].y +
                                  p4[i].z * v4[cc].z + p4[i].w * v4[cc].w;
        }
        __syncthreads();
    }
#pragma unroll
    for (int i = 0; i < 4; i++) {
        float inv = 1.f / l_i[i];
        size_t rbase = ((size_t)(b * T + qt * 64 + ty * 4 + i)) * DIM + h * HEADD;
#pragma unroll
        for (int cc = 0; cc < 4; cc++) o[rbase + tx + 16 * cc] = acc[i][cc] * inv;
    }
}

// ---------------- silu(gate)*up ----------------
__global__ void silu_mul_kernel(float* __restrict__ g, const float* __restrict__ u, int n4) {
    int i = blockIdx.x * blockDim.x + threadIdx.x;
    if (i >= n4) return;
    float4 x = ((float4*)g)[i];
    float4 y = ((const float4*)u)[i];
    x.x = x.x / (1.f + __expf(-x.x)) * y.x;
    x.y = x.y / (1.f + __expf(-x.y)) * y.y;
    x.z = x.z / (1.f + __expf(-x.z)) * y.z;
    x.w = x.w / (1.f + __expf(-x.w)) * y.w;
    ((float4*)g)[i] = x;
}

// ---------------- launch ----------------
extern "C" void kernel_launch(void* const* d_in, const int* in_sizes, int n_in,
                              void* d_out, int out_size) {
    const int*   ids      = (const int*)d_in[0];
    const float* emb      = (const float*)d_in[1];
    const float* router_k = (const float*)d_in[2];
    const float* router_q = (const float*)d_in[3];
    const float* ln1      = (const float*)d_in[4];
    const float* ln2      = (const float*)d_in[5];
    const float* wq       = (const float*)d_in[6];
    const float* bq       = (const float*)d_in[7];
    const float* wk       = (const float*)d_in[8];
    const float* bk       = (const float*)d_in[9];
    const float* wv       = (const float*)d_in[10];
    const float* bv       = (const float*)d_in[11];
    const float* wo       = (const float*)d_in[12];
    const float* wg       = (const float*)d_in[13];
    const float* wu       = (const float*)d_in[14];
    const float* wd       = (const float*)d_in[15];
    float* hidden = (float*)d_out;

    float *x, *h, *q, *k, *v, *o, *gate, *up, *pooled, *scores;
    int* tok;
    cudaGetSymbolAddress((void**)&x, g_x);
    cudaGetSymbolAddress((void**)&h, g_h);
    cudaGetSymbolAddress((void**)&q, g_q);
    cudaGetSymbolAddress((void**)&k, g_k);
    cudaGetSymbolAddress((void**)&v, g_v);
    cudaGetSymbolAddress((void**)&o, g_o);
    cudaGetSymbolAddress((void**)&gate, g_gate);
    cudaGetSymbolAddress((void**)&up, g_up);
    cudaGetSymbolAddress((void**)&pooled, g_pool);
    cudaGetSymbolAddress((void**)&scores, g_scores);
    cudaGetSymbolAddress((void**)&tok, g_tok);

    cudaFuncSetAttribute(flash_attn_kernel,
                         cudaFuncAttributeMaxDynamicSharedMemorySize, SMEM_ATTN);

    embed_kernel<<<BATCH * SEQ, 256>>>(ids, emb, hidden);

    for (int blk = 0; blk < NBLK; blk++) {
        pool_kernel<<<BATCH * NSEG, 256>>>(hidden, pooled);
        router_kernel<<<dim3(NSEG, BATCH), 128>>>(
            pooled, router_k + (size_t)blk * DIM * RANKR,
            router_q + (size_t)blk * NQRY * RANKR, scores);
        select_kernel<<<BATCH, 256>>>(scores, tok);
        gather_kernel<<<BT, 256>>>(hidden, tok, x);

        for (int j = 0; j < BPL; j++) {
            int li = blk * BPL + j;
            rmsnorm_kernel<<<BT, 256>>>(x, ln1 + (size_t)li * DIM, h);
            bf16x3_gemm_kernel<1><<<dim3(DIM / 128, BT / 128), 256>>>(
                h, wq + (size_t)li * DIM * DIM, bq + (size_t)li * DIM, q, BT, DIM, DIM);
            bf16x3_gemm_kernel<1><<<dim3((KVHEAD * HEADD) / 128, BT / 128), 256>>>(
                h, wk + (size_t)li * DIM * KVHEAD * HEADD, bk + (size_t)li * KVHEAD * HEADD,
                k, BT, KVHEAD * HEADD, DIM);
            bf16x3_gemm_kernel<1><<<dim3((KVHEAD * HEADD) / 128, BT / 128), 256>>>(
                h, wv + (size_t)li * DIM * KVHEAD * HEADD, bv + (size_t)li * KVHEAD * HEADD,
                v, BT, KVHEAD * HEADD, DIM);
            rope_kernel<<<BT, 256>>>(q, k, tok);
            flash_attn_kernel<<<dim3(KTOK / 64, NHEAD, BATCH), 256, SMEM_ATTN>>>(q, k, v, o);
            bf16x3_gemm_kernel<2><<<dim3(DIM / 128, BT / 128), 256>>>(
                o, wo + (size_t)li * DIM * DIM, nullptr, x, BT, DIM, DIM);
            rmsnorm_kernel<<<BT, 256>>>(x, ln2 + (size_t)li * DIM, h);
            bf16x3_gemm_kernel<0><<<dim3(FFD / 128, BT / 128), 256>>>(
                h, wg + (size_t)li * DIM * FFD, nullptr, gate, BT, FFD, DIM);
            bf16x3_gemm_kernel<0><<<dim3(FFD / 128, BT / 128), 256>>>(
                h, wu + (size_t)li * DIM * FFD, nullptr, up, BT, FFD, DIM);
            int n4 = BT * FFD / 4;
            silu_mul_kernel<<<(n4 + 255) / 256, 256>>>(gate, up, n4);
            bf16x3_gemm_kernel<2><<<dim3(DIM / 128, BT / 128), 256>>>(
                gate, wd + (size_t)li * FFD * DIM, nullptr, x, BT, DIM, FFD);
        }
        scatter_kernel<<<BT, 256>>>(x, tok, hidden);
    }
}

// round 10
// speedup vs baseline: 1.9814x; 1.1934x over previous
#include <cuda_runtime.h>
#include <cuda_bf16.h>
#include <math.h>
#include <stdint.h>

// ---------------- problem constants ----------------
#define BATCH 2
#define SEQ   4096
#define DIM   1024
#define NHEAD 16
#define KVHEAD 4
#define HEADD 64
#define FFD   2816
#define NSEG  256
#define SEGLEN 16
#define KSEG  76
#define KTOK  (KSEG*SEGLEN)      // 1216
#define BT    (BATCH*KTOK)       // 2432 = 19*128
#define NLAYER 12
#define NBLK  2
#define BPL   6
#define RANKR 16
#define NQRY  8

// ---------------- scratch (device globals; no allocs allowed) ----------------
__device__ float g_x   [BT*DIM];
__device__ float g_q   [BT*DIM];
__device__ float g_k   [BT*(KVHEAD*HEADD)];
__device__ float g_v   [BT*(KVHEAD*HEADD)];
__device__ float g_o   [BT*DIM];
__device__ float g_gate[BT*FFD];
__device__ float g_up  [BT*FFD];
__device__ float g_pool[BATCH*NSEG*DIM];
__device__ float g_scores[BATCH*NSEG];
__device__ int   g_tok [BATCH*KTOK];

// pre-packed bf16 hi/lo pair buffers (pair along K: u32 = {lo16=k, hi16=k+1})
__device__ uint32_t g_wqh[NLAYER*512*1024],  g_wql[NLAYER*512*1024];
__device__ uint32_t g_wkh[NLAYER*512*256],   g_wkl[NLAYER*512*256];
__device__ uint32_t g_wvh[NLAYER*512*256],   g_wvl[NLAYER*512*256];
__device__ uint32_t g_woh[NLAYER*512*1024],  g_wol[NLAYER*512*1024];
__device__ uint32_t g_wgh[NLAYER*512*2816],  g_wgl[NLAYER*512*2816];
__device__ uint32_t g_wuh[NLAYER*512*2816],  g_wul[NLAYER*512*2816];
__device__ uint32_t g_wdh[NLAYER*1408*1024], g_wdl[NLAYER*1408*1024];
// activation pair buffers
__device__ uint32_t g_hh[BT*DIM/2],  g_hl[BT*DIM/2];
__device__ uint32_t g_oh[BT*DIM/2],  g_ol[BT*DIM/2];
__device__ uint32_t g_gh[BT*FFD/2],  g_gl[BT*FFD/2];

// ---------------- split helper: fp32 pair -> bf16 hi/lo pair u32s ----------------
__device__ __forceinline__ void split_pair(float x0, float x1, uint32_t& hp, uint32_t& lp) {
    uint32_t h;
    asm("cvt.rn.bf16x2.f32 %0, %1, %2;" : "=r"(h) : "f"(x1), "f"(x0));
    float h0 = __uint_as_float(h << 16);
    float h1 = __uint_as_float(h & 0xFFFF0000u);
    float l0 = x0 - h0, l1 = x1 - h1;
    uint32_t l;
    asm("cvt.rn.bf16x2.f32 %0, %1, %2;" : "=r"(l) : "f"(l1), "f"(l0));
    hp = h; lp = l;
}

// ---------------- weight prepack: [R][N] f32 -> [R/2][N] u32 hi/lo ----------------
__global__ void prepack_kernel(const float* __restrict__ src,
                               uint32_t* __restrict__ dh, uint32_t* __restrict__ dl,
                               int n4row, int N) {
    int idx = blockIdx.x * 256 + threadIdx.x;
    int p = idx / n4row, c = (idx - p * n4row) * 4;
    const float* r0 = src + (size_t)(2 * p) * N + c;
    float4 a = *(const float4*)r0;
    float4 b = *(const float4*)(r0 + N);
    uint4 h, l;
    split_pair(a.x, b.x, h.x, l.x);
    split_pair(a.y, b.y, h.y, l.y);
    split_pair(a.z, b.z, h.z, l.z);
    split_pair(a.w, b.w, h.w, l.w);
    *(uint4*)(dh + (size_t)idx * 4) = h;
    *(uint4*)(dl + (size_t)idx * 4) = l;
}

// ---------------- activation pack: fp32 -> pair (row-contiguous K) ----------------
__global__ void pack_act_kernel(const float* __restrict__ src,
                                uint32_t* __restrict__ dh, uint32_t* __restrict__ dl) {
    int i = blockIdx.x * 256 + threadIdx.x;
    float4 v = ((const float4*)src)[i];
    uint32_t h0, l0, h1, l1;
    split_pair(v.x, v.y, h0, l0);
    split_pair(v.z, v.w, h1, l1);
    *(uint2*)&dh[(size_t)i * 2] = make_uint2(h0, h1);
    *(uint2*)&dl[(size_t)i * 2] = make_uint2(l0, l1);
}

// ---------------- embed gather ----------------
__global__ void embed_kernel(const int* __restrict__ ids,
                             const float* __restrict__ emb,
                             float* __restrict__ hidden) {
    int row = blockIdx.x;
    int id  = ids[row];
    const float4* src = (const float4*)(emb + (size_t)id * DIM);
    float4* dst = (float4*)(hidden + (size_t)row * DIM);
    dst[threadIdx.x] = src[threadIdx.x];
}

// ---------------- segment mean pool ----------------
__global__ void pool_kernel(const float* __restrict__ hidden,
                            float* __restrict__ pooled) {
    int b = blockIdx.x >> 8, n = blockIdx.x & 255;
    const float* base = hidden + ((size_t)b * SEQ + n * SEGLEN) * DIM + threadIdx.x * 4;
    float4 acc = make_float4(0.f, 0.f, 0.f, 0.f);
#pragma unroll
    for (int t = 0; t < SEGLEN; t++) {
        float4 v = *(const float4*)(base + (size_t)t * DIM);
        acc.x += v.x; acc.y += v.y; acc.z += v.z; acc.w += v.w;
    }
    const float s = 1.f / SEGLEN;
    acc.x *= s; acc.y *= s; acc.z *= s; acc.w *= s;
    *(float4*)(pooled + ((size_t)b * NSEG + n) * DIM + threadIdx.x * 4) = acc;
}

// ---------------- multi-query router scores ----------------
__global__ void router_kernel(const float* __restrict__ pooled,
                              const float* __restrict__ rk,
                              const float* __restrict__ rq,
                              float* __restrict__ scores) {
    int n = blockIdx.x, b = blockIdx.y;
    const float* p = pooled + ((size_t)b * NSEG + n) * DIM;
    __shared__ float part[128];
    int tid = threadIdx.x;
    int r = tid & 15, g = tid >> 4;
    float sum = 0.f;
    int d0 = g * 128;
    for (int d = d0; d < d0 + 128; d++) sum += p[d] * rk[d * RANKR + r];
    part[tid] = sum;
    __syncthreads();
    if (tid < RANKR) {
        float key = 0.f;
        for (int gg = 0; gg < 8; gg++) key += part[gg * 16 + tid];
        part[tid] = key;
    }
    __syncthreads();
    if (tid == 0) {
        float best = -1e30f;
        for (int qq = 0; qq < NQRY; qq++) {
            float dv = 0.f;
            for (int rr = 0; rr < RANKR; rr++) dv += rq[qq * RANKR + rr] * part[rr];
            best = fmaxf(best, dv);
        }
        scores[b * NSEG + n] = best;
    }
}

// ---------------- top-k select ----------------
__global__ void select_kernel(const float* __restrict__ scores,
                              int* __restrict__ tok) {
    int b = blockIdx.x;
    __shared__ float s[NSEG];
    __shared__ int pf[NSEG];
    int i = threadIdx.x;
    float mine = scores[b * NSEG + i];
    s[i] = mine;
    __syncthreads();
    int rank = 0;
    for (int j = 0; j < NSEG; j++) {
        float o = s[j];
        rank += (o > mine) || (o == mine && j < i);
    }
    int sel = (rank < KSEG) ? 1 : 0;
    pf[i] = sel;
    __syncthreads();
    for (int off = 1; off < NSEG; off <<= 1) {
        int add = (i >= off) ? pf[i - off] : 0;
        __syncthreads();
        pf[i] += add;
        __syncthreads();
    }
    if (sel) {
        int p = pf[i] - 1;
        int* dst = tok + b * KTOK + p * SEGLEN;
        int base = i * SEGLEN;
#pragma unroll
        for (int t = 0; t < SEGLEN; t++) dst[t] = base + t;
    }
}

// ---------------- gather / scatter ----------------
__global__ void gather_kernel(const float* __restrict__ hidden,
                              const int* __restrict__ tok,
                              float* __restrict__ x) {
    int row = blockIdx.x;
    int b = row / KTOK;
    int tk = tok[row];
    const float4* src = (const float4*)(hidden + ((size_t)b * SEQ + tk) * DIM);
    float4* dst = (float4*)(x + (size_t)row * DIM);
    dst[threadIdx.x] = src[threadIdx.x];
}
__global__ void scatter_kernel(const float* __restrict__ x,
                               const int* __restrict__ tok,
                               float* __restrict__ hidden) {
    int row = blockIdx.x;
    int b = row / KTOK;
    int tk = tok[row];
    const float4* src = (const float4*)(x + (size_t)row * DIM);
    float4* dst = (float4*)(hidden + ((size_t)b * SEQ + tk) * DIM);
    dst[threadIdx.x] = src[threadIdx.x];
}

// ---------------- RMSNorm (writes bf16 hi/lo pair buffers) ----------------
__global__ void rmsnorm_kernel(const float* __restrict__ x,
                               const float* __restrict__ w,
                               uint32_t* __restrict__ oh,
                               uint32_t* __restrict__ ol) {
    int row = blockIdx.x;
    int t = threadIdx.x;
    const float4* xr = (const float4*)(x + (size_t)row * DIM);
    float4 v = xr[t];
    float ss = v.x * v.x + v.y * v.y + v.z * v.z + v.w * v.w;
#pragma unroll
    for (int d = 16; d >= 1; d >>= 1) ss += __shfl_xor_sync(0xffffffffu, ss, d);
    __shared__ float ws[8];
    __shared__ float tot;
    if ((t & 31) == 0) ws[t >> 5] = ss;
    __syncthreads();
    if (t == 0) {
        float a = 0.f;
        for (int wgi = 0; wgi < 8; wgi++) a += ws[wgi];
        tot = a;
    }
    __syncthreads();
    float inv = rsqrtf(tot * (1.f / DIM) + 1e-6f);
    float4 wv = ((const float4*)w)[t];
    float o0 = v.x * inv * wv.x, o1 = v.y * inv * wv.y;
    float o2 = v.z * inv * wv.z, o3 = v.w * inv * wv.w;
    uint32_t h0, l0, h1, l1;
    split_pair(o0, o1, h0, l0);
    split_pair(o2, o3, h1, l1);
    size_t base = (size_t)row * (DIM / 2) + t * 2;
    *(uint2*)&oh[base] = make_uint2(h0, h1);
    *(uint2*)&ol[base] = make_uint2(l0, l1);
}

// ---------------- RoPE ----------------
__global__ void rope_kernel(float* __restrict__ q, float* __restrict__ k,
                            const int* __restrict__ tok) {
    int row = blockIdx.x;
    float pos = (float)tok[row];
    int t = threadIdx.x;
    for (int pidx = t; pidx < NHEAD * 32; pidx += 256) {
        int hh = pidx >> 5, i = pidx & 31;
        float inv = __powf(10000.f, -(float)(2 * i) / (float)HEADD);
        float ang = pos * inv;
        float sn, cs;
        sincosf(ang, &sn, &cs);
        float* qp = q + (size_t)row * DIM + hh * HEADD;
        float x1 = qp[i], x2 = qp[i + 32];
        qp[i]      = x1 * cs - x2 * sn;
        qp[i + 32] = x2 * cs + x1 * sn;
    }
    if (t < KVHEAD * 32) {
        int hh = t >> 5, i = t & 31;
        float inv = __powf(10000.f, -(float)(2 * i) / (float)HEADD);
        float ang = pos * inv;
        float sn, cs;
        sincosf(ang, &sn, &cs);
        float* kp = k + (size_t)row * (KVHEAD * HEADD) + hh * HEADD;
        float x1 = kp[i], x2 = kp[i + 32];
        kp[i]      = x1 * cs - x2 * sn;
        kp[i + 32] = x2 * cs + x1 * sn;
    }
}

// ---------------- pair-format split-bf16 (3xMMA) GEMM ----------------
// C[M,N] = A[M,K] @ W[K,N] (+bias)(+residual); A,W pre-split into bf16 hi/lo
// pairs along K (u32 = two adjacent K elems). No converts in the hot loop.
// 128x128 CTA tile, K-tile 32 (16 pairs), 256 threads = 2(M)x4(N) warps.
#define ASU 20     // A smem stride (u32): banks gid*20+tig distinct over 8x4 lanes
#define BSU 136    // B smem stride (u32): banks distinct over 4x8 lanes

__device__ __forceinline__ void mma_bf16(float c[4], const uint32_t a[4], const uint32_t b[2]) {
    asm volatile(
        "mma.sync.aligned.m16n8k16.row.col.f32.bf16.bf16.f32 "
        "{%0,%1,%2,%3}, {%4,%5,%6,%7}, {%8,%9}, {%0,%1,%2,%3};\n"
        : "+f"(c[0]), "+f"(c[1]), "+f"(c[2]), "+f"(c[3])
        : "r"(a[0]), "r"(a[1]), "r"(a[2]), "r"(a[3]), "r"(b[0]), "r"(b[1]));
}

template <int FLAGS>   // bit0: add bias, bit1: add existing C (residual)
__global__ void __launch_bounds__(256)
pgemm_kernel(const uint32_t* __restrict__ Ahp, const uint32_t* __restrict__ Alp,
             const uint32_t* __restrict__ Whp, const uint32_t* __restrict__ Wlp,
             const float* __restrict__ bias,
             float* __restrict__ C,
             int M, int N, int K2) {        // K2 = K/2 (pairs)
    __shared__ uint32_t sAh[128 * ASU], sAl[128 * ASU];
    __shared__ uint32_t sBh[16 * BSU],  sBl[16 * BSU];
    int tid = threadIdx.x, lane = tid & 31, warp = tid >> 5;
    int warpM = warp & 1, warpN = warp >> 1;
    int m0 = blockIdx.y * 128, n0 = blockIdx.x * 128;
    int gid = lane >> 2, tig = lane & 3;

    float c[4][4][4];
#pragma unroll
    for (int i = 0; i < 4; i++)
#pragma unroll
        for (int j = 0; j < 4; j++)
#pragma unroll
            for (int f = 0; f < 4; f++) c[i][j][f] = 0.f;

    for (int p0 = 0; p0 < K2; p0 += 16) {
        uint4 aH[2], aL[2], bH[2], bL[2];
#pragma unroll
        for (int i = 0; i < 2; i++) {
            int f = tid + 256 * i;
            int arow = f >> 2, apc = (f & 3) * 4;     // 128 rows x 4 uint4
            size_t aoff = (size_t)(m0 + arow) * K2 + p0 + apc;
            aH[i] = *(const uint4*)&Ahp[aoff];
            aL[i] = *(const uint4*)&Alp[aoff];
            int pr = f >> 5, cg = (f & 31) * 4;       // 16 pair-rows x 32 uint4
            size_t boff = (size_t)(p0 + pr) * N + n0 + cg;
            bH[i] = *(const uint4*)&Whp[boff];
            bL[i] = *(const uint4*)&Wlp[boff];
        }
        __syncthreads();
#pragma unroll
        for (int i = 0; i < 2; i++) {
            int f = tid + 256 * i;
            int arow = f >> 2, apc = (f & 3) * 4;
            *(uint4*)&sAh[arow * ASU + apc] = aH[i];
            *(uint4*)&sAl[arow * ASU + apc] = aL[i];
            int pr = f >> 5, cg = (f & 31) * 4;
            *(uint4*)&sBh[pr * BSU + cg] = bH[i];
            *(uint4*)&sBl[pr * BSU + cg] = bL[i];
        }
        __syncthreads();
#pragma unroll
        for (int kk = 0; kk < 2; kk++) {
            int kp = kk * 8;
            uint32_t bh[4][2], bl[4][2];
#pragma unroll
            for (int nt = 0; nt < 4; nt++) {
                int cb = warpN * 32 + nt * 8 + gid;
                bh[nt][0] = sBh[(kp + tig) * BSU + cb];
                bh[nt][1] = sBh[(kp + tig + 4) * BSU + cb];
                bl[nt][0] = sBl[(kp + tig) * BSU + cb];
                bl[nt][1] = sBl[(kp + tig + 4) * BSU + cb];
            }
#pragma unroll
            for (int mt = 0; mt < 4; mt++) {
                int rb = warpM * 64 + mt * 16 + gid;
                uint32_t ah[4], al[4];
                ah[0] = sAh[rb * ASU + kp + tig];
                ah[1] = sAh[(rb + 8) * ASU + kp + tig];
                ah[2] = sAh[rb * ASU + kp + tig + 4];
                ah[3] = sAh[(rb + 8) * ASU + kp + tig + 4];
                al[0] = sAl[rb * ASU + kp + tig];
                al[1] = sAl[(rb + 8) * ASU + kp + tig];
                al[2] = sAl[rb * ASU + kp + tig + 4];
                al[3] = sAl[(rb + 8) * ASU + kp + tig + 4];
#pragma unroll
                for (int nt = 0; nt < 4; nt++) {
                    mma_bf16(c[mt][nt], ah, bh[nt]);
                    mma_bf16(c[mt][nt], al, bh[nt]);
                    mma_bf16(c[mt][nt], ah, bl[nt]);
                }
            }
        }
    }
    // ---- epilogue ----
#pragma unroll
    for (int mt = 0; mt < 4; mt++) {
#pragma unroll
        for (int half = 0; half < 2; half++) {
            int row = m0 + warpM * 64 + mt * 16 + gid + half * 8;
            float* Crow = C + (size_t)row * N + n0 + warpN * 32;
#pragma unroll
            for (int nt = 0; nt < 4; nt++) {
                int col = nt * 8 + tig * 2;
                float2 r;
                r.x = c[mt][nt][half * 2 + 0];
                r.y = c[mt][nt][half * 2 + 1];
                if (FLAGS & 1) {
                    float2 bb = *(const float2*)&bias[n0 + warpN * 32 + col];
                    r.x += bb.x; r.y += bb.y;
                }
                if (FLAGS & 2) {
                    float2 cc = *(const float2*)&Crow[col];
                    r.x += cc.x; r.y += cc.y;
                }
                *(float2*)&Crow[col] = r;
            }
        }
    }
}

// ---------------- flash attention (fp32, causal, GQA) ----------------
#define AT_STRIDE 68
#define SMEM_ATTN (4 * 64 * AT_STRIDE * 4)
__global__ void flash_attn_kernel(const float* __restrict__ q,
                                  const float* __restrict__ kk,
                                  const float* __restrict__ vv,
                                  float* __restrict__ o) {
    extern __shared__ float sm[];
    float* Qs = sm;
    float* Ks = sm + 64 * AT_STRIDE;
    float* Vt = sm + 2 * 64 * AT_STRIDE;
    float* Ps = sm + 3 * 64 * AT_STRIDE;
    const int T = KTOK;
    int qt = blockIdx.x, h = blockIdx.y, b = blockIdx.z;
    int kh = h >> 2;
    int tid = threadIdx.x, tx = tid & 15, ty = tid >> 4;
    const float scale = 0.125f;

    for (int i = tid; i < 1024; i += 256) {
        int row = i >> 4, c4 = (i & 15) << 2;
        float4 v = *(const float4*)&q[((size_t)(b * T + qt * 64 + row)) * DIM + h * HEADD + c4];
        float* dst = &Qs[row * AT_STRIDE + c4];
        dst[0] = v.x * scale; dst[1] = v.y * scale;
        dst[2] = v.z * scale; dst[3] = v.w * scale;
    }
    float acc[4][4];
    float m_i[4], l_i[4];
#pragma unroll
    for (int i = 0; i < 4; i++) {
        m_i[i] = -1e30f; l_i[i] = 0.f;
#pragma unroll
        for (int cc = 0; cc < 4; cc++) acc[i][cc] = 0.f;
    }

    for (int kt = 0; kt <= qt; kt++) {
        for (int i = tid; i < 1024; i += 256) {
            int row = i >> 4, c4 = (i & 15) << 2;
            size_t base = ((size_t)(b * T + kt * 64 + row)) * (KVHEAD * HEADD) + kh * HEADD + c4;
            float4 k4 = *(const float4*)&kk[base];
            *(float4*)&Ks[row * AT_STRIDE + c4] = k4;
            float4 v4 = *(const float4*)&vv[base];
            Vt[(c4 + 0) * AT_STRIDE + row] = v4.x;
            Vt[(c4 + 1) * AT_STRIDE + row] = v4.y;
            Vt[(c4 + 2) * AT_STRIDE + row] = v4.z;
            Vt[(c4 + 3) * AT_STRIDE + row] = v4.w;
        }
        __syncthreads();

        float s[4][4];
#pragma unroll
        for (int i = 0; i < 4; i++)
#pragma unroll
            for (int j = 0; j < 4; j++) s[i][j] = 0.f;
        for (int kd = 0; kd < 64; kd += 4) {
            float4 qa[4], kb[4];
#pragma unroll
            for (int i = 0; i < 4; i++) qa[i] = *(float4*)&Qs[(ty * 4 + i) * AT_STRIDE + kd];
#pragma unroll
            for (int j = 0; j < 4; j++) kb[j] = *(float4*)&Ks[(tx + 16 * j) * AT_STRIDE + kd];
#pragma unroll
            for (int i = 0; i < 4; i++)
#pragma unroll
                for (int j = 0; j < 4; j++)
                    s[i][j] += qa[i].x * kb[j].x + qa[i].y * kb[j].y +
                               qa[i].z * kb[j].z + qa[i].w * kb[j].w;
        }
        if (kt == qt) {
#pragma unroll
            for (int i = 0; i < 4; i++)
#pragma unroll
                for (int j = 0; j < 4; j++)
                    if (tx + 16 * j > ty * 4 + i) s[i][j] = -1e30f;
        }
#pragma unroll
        for (int i = 0; i < 4; i++) {
            float mx = fmaxf(fmaxf(s[i][0], s[i][1]), fmaxf(s[i][2], s[i][3]));
#pragma unroll
            for (int d = 1; d < 16; d <<= 1) mx = fmaxf(mx, __shfl_xor_sync(0xffffffffu, mx, d));
            float mnew = fmaxf(m_i[i], mx);
            float corr = __expf(m_i[i] - mnew);
            float psum = 0.f;
#pragma unroll
            for (int j = 0; j < 4; j++) {
                float p = __expf(s[i][j] - mnew);
                s[i][j] = p;
                psum += p;
            }
#pragma unroll
            for (int d = 1; d < 16; d <<= 1) psum += __shfl_xor_sync(0xffffffffu, psum, d);
            l_i[i] = l_i[i] * corr + psum;
            m_i[i] = mnew;
#pragma unroll
            for (int cc = 0; cc < 4; cc++) acc[i][cc] *= corr;
#pragma unroll
            for (int j = 0; j < 4; j++) Ps[(ty * 4 + i) * AT_STRIDE + tx + 16 * j] = s[i][j];
        }
        __syncthreads();
        for (int jr = 0; jr < 64; jr += 4) {
            float4 p4[4], v4[4];
#pragma unroll
            for (int i = 0; i < 4; i++) p4[i] = *(float4*)&Ps[(ty * 4 + i) * AT_STRIDE + jr];
#pragma unroll
            for (int cc = 0; cc < 4; cc++) v4[cc] = *(float4*)&Vt[(tx + 16 * cc) * AT_STRIDE + jr];
#pragma unroll
            for (int i = 0; i < 4; i++)
#pragma unroll
                for (int cc = 0; cc < 4; cc++)
                    acc[i][cc] += p4[i].x * v4[cc].x + p4[i].y * v4[cc].y +
                                  p4[i].z * v4[cc].z + p4[i].w * v4[cc].w;
        }
        __syncthreads();
    }
#pragma unroll
    for (int i = 0; i < 4; i++) {
        float inv = 1.f / l_i[i];
        size_t rbase = ((size_t)(b * T + qt * 64 + ty * 4 + i)) * DIM + h * HEADD;
#pragma unroll
        for (int cc = 0; cc < 4; cc++) o[rbase + tx + 16 * cc] = acc[i][cc] * inv;
    }
}

// ---------------- silu(gate)*up -> pair buffers ----------------
__global__ void silu_mul_kernel(const float* __restrict__ g, const float* __restrict__ u,
                                uint32_t* __restrict__ dh, uint32_t* __restrict__ dl) {
    int i = blockIdx.x * 256 + threadIdx.x;
    float4 x = ((const float4*)g)[i];
    float4 y = ((const float4*)u)[i];
    float o0 = x.x / (1.f + __expf(-x.x)) * y.x;
    float o1 = x.y / (1.f + __expf(-x.y)) * y.y;
    float o2 = x.z / (1.f + __expf(-x.z)) * y.z;
    float o3 = x.w / (1.f + __expf(-x.w)) * y.w;
    uint32_t h0, l0, h1, l1;
    split_pair(o0, o1, h0, l0);
    split_pair(o2, o3, h1, l1);
    *(uint2*)&dh[(size_t)i * 2] = make_uint2(h0, h1);
    *(uint2*)&dl[(size_t)i * 2] = make_uint2(l0, l1);
}

// ---------------- launch ----------------
extern "C" void kernel_launch(void* const* d_in, const int* in_sizes, int n_in,
                              void* d_out, int out_size) {
    const int*   ids      = (const int*)d_in[0];
    const float* emb      = (const float*)d_in[1];
    const float* router_k = (const float*)d_in[2];
    const float* router_q = (const float*)d_in[3];
    const float* ln1      = (const float*)d_in[4];
    const float* ln2      = (const float*)d_in[5];
    const float* wq       = (const float*)d_in[6];
    const float* bq       = (const float*)d_in[7];
    const float* wk       = (const float*)d_in[8];
    const float* bk       = (const float*)d_in[9];
    const float* wv       = (const float*)d_in[10];
    const float* bv       = (const float*)d_in[11];
    const float* wo       = (const float*)d_in[12];
    const float* wg       = (const float*)d_in[13];
    const float* wu       = (const float*)d_in[14];
    const float* wd       = (const float*)d_in[15];
    float* hidden = (float*)d_out;

    float *x, *q, *k, *v, *o, *gate, *up, *pooled, *scores;
    int* tok;
    uint32_t *wqh, *wql, *wkh, *wkl, *wvh, *wvl, *woh, *wol;
    uint32_t *wgh, *wgl, *wuh, *wul, *wdh, *wdl;
    uint32_t *hh, *hl, *oh, *ol, *gh, *gl;
    cudaGetSymbolAddress((void**)&x, g_x);
    cudaGetSymbolAddress((void**)&q, g_q);
    cudaGetSymbolAddress((void**)&k, g_k);
    cudaGetSymbolAddress((void**)&v, g_v);
    cudaGetSymbolAddress((void**)&o, g_o);
    cudaGetSymbolAddress((void**)&gate, g_gate);
    cudaGetSymbolAddress((void**)&up, g_up);
    cudaGetSymbolAddress((void**)&pooled, g_pool);
    cudaGetSymbolAddress((void**)&scores, g_scores);
    cudaGetSymbolAddress((void**)&tok, g_tok);
    cudaGetSymbolAddress((void**)&wqh, g_wqh); cudaGetSymbolAddress((void**)&wql, g_wql);
    cudaGetSymbolAddress((void**)&wkh, g_wkh); cudaGetSymbolAddress((void**)&wkl, g_wkl);
    cudaGetSymbolAddress((void**)&wvh, g_wvh); cudaGetSymbolAddress((void**)&wvl, g_wvl);
    cudaGetSymbolAddress((void**)&woh, g_woh); cudaGetSymbolAddress((void**)&wol, g_wol);
    cudaGetSymbolAddress((void**)&wgh, g_wgh); cudaGetSymbolAddress((void**)&wgl, g_wgl);
    cudaGetSymbolAddress((void**)&wuh, g_wuh); cudaGetSymbolAddress((void**)&wul, g_wul);
    cudaGetSymbolAddress((void**)&wdh, g_wdh); cudaGetSymbolAddress((void**)&wdl, g_wdl);
    cudaGetSymbolAddress((void**)&hh, g_hh);   cudaGetSymbolAddress((void**)&hl, g_hl);
    cudaGetSymbolAddress((void**)&oh, g_oh);   cudaGetSymbolAddress((void**)&ol, g_ol);
    cudaGetSymbolAddress((void**)&gh, g_gh);   cudaGetSymbolAddress((void**)&gl, g_gl);

    cudaFuncSetAttribute(flash_attn_kernel,
                         cudaFuncAttributeMaxDynamicSharedMemorySize, SMEM_ATTN);

    // ---- weight prepack (once per launch; graph replays rerun it) ----
    // rows = L*K (even), pair-rows = L*K/2; total uint4 = pair-rows * N/4
    prepack_kernel<<<NLAYER * 512 * 1024 / 1024, 256>>>(wq, wqh, wql, 1024 / 4, 1024);
    prepack_kernel<<<NLAYER * 512 * 256 / 1024,  256>>>(wk, wkh, wkl, 256 / 4, 256);
    prepack_kernel<<<NLAYER * 512 * 256 / 1024,  256>>>(wv, wvh, wvl, 256 / 4, 256);
    prepack_kernel<<<NLAYER * 512 * 1024 / 1024, 256>>>(wo, woh, wol, 1024 / 4, 1024);
    prepack_kernel<<<NLAYER * 512 * 2816 / 1024, 256>>>(wg, wgh, wgl, 2816 / 4, 2816);
    prepack_kernel<<<NLAYER * 512 * 2816 / 1024, 256>>>(wu, wuh, wul, 2816 / 4, 2816);
    prepack_kernel<<<NLAYER * 1408 * 1024 / 1024, 256>>>(wd, wdh, wdl, 1024 / 4, 1024);

    embed_kernel<<<BATCH * SEQ, 256>>>(ids, emb, hidden);

    for (int blk = 0; blk < NBLK; blk++) {
        pool_kernel<<<BATCH * NSEG, 256>>>(hidden, pooled);
        router_kernel<<<dim3(NSEG, BATCH), 128>>>(
            pooled, router_k + (size_t)blk * DIM * RANKR,
            router_q + (size_t)blk * NQRY * RANKR, scores);
        select_kernel<<<BATCH, 256>>>(scores, tok);
        gather_kernel<<<BT, 256>>>(hidden, tok, x);

        for (int j = 0; j < BPL; j++) {
            int li = blk * BPL + j;
            size_t oq = (size_t)li * 512 * 1024;   // wq/wo pack offset (u32)
            size_t okv = (size_t)li * 512 * 256;   // wk/wv
            size_t ogu = (size_t)li * 512 * 2816;  // wg/wu
            size_t od  = (size_t)li * 1408 * 1024; // wd

            rmsnorm_kernel<<<BT, 256>>>(x, ln1 + (size_t)li * DIM, hh, hl);
            pgemm_kernel<1><<<dim3(DIM / 128, BT / 128), 256>>>(
                hh, hl, wqh + oq, wql + oq, bq + (size_t)li * DIM, q, BT, DIM, 512);
            pgemm_kernel<1><<<dim3(2, BT / 128), 256>>>(
                hh, hl, wkh + okv, wkl + okv, bk + (size_t)li * 256, k, BT, 256, 512);
            pgemm_kernel<1><<<dim3(2, BT / 128), 256>>>(
                hh, hl, wvh + okv, wvl + okv, bv + (size_t)li * 256, v, BT, 256, 512);
            rope_kernel<<<BT, 256>>>(q, k, tok);
            flash_attn_kernel<<<dim3(KTOK / 64, NHEAD, BATCH), 256, SMEM_ATTN>>>(q, k, v, o);
            pack_act_kernel<<<BT * DIM / 1024, 256>>>(o, oh, ol);
            pgemm_kernel<2><<<dim3(DIM / 128, BT / 128), 256>>>(
                oh, ol, woh + oq, wol + oq, nullptr, x, BT, DIM, 512);
            rmsnorm_kernel<<<BT, 256>>>(x, ln2 + (size_t)li * DIM, hh, hl);
            pgemm_kernel<0><<<dim3(FFD / 128, BT / 128), 256>>>(
                hh, hl, wgh + ogu, wgl + ogu, nullptr, gate, BT, FFD, 512);
            pgemm_kernel<0><<<dim3(FFD / 128, BT / 128), 256>>>(
                hh, hl, wuh + ogu, wul + ogu, nullptr, up, BT, FFD, 512);
            silu_mul_kernel<<<BT * FFD / 1024, 256>>>(gate, up, gh, gl);
            pgemm_kernel<2><<<dim3(DIM / 128, BT / 128), 256>>>(
                gh, gl, wdh + od, wdl + od, nullptr, x, BT, DIM, 1408);
        }
        scatter_kernel<<<BT, 256>>>(x, tok, hidden);
    }
}

// round 11
// speedup vs baseline: 2.5725x; 1.2983x over previous
#include <cuda_runtime.h>
#include <cuda_bf16.h>
#include <math.h>
#include <stdint.h>

// ---------------- problem constants ----------------
#define BATCH 2
#define SEQ   4096
#define DIM   1024
#define NHEAD 16
#define KVHEAD 4
#define HEADD 64
#define FFD   2816
#define NSEG  256
#define SEGLEN 16
#define KSEG  76
#define KTOK  (KSEG*SEGLEN)      // 1216
#define BT    (BATCH*KTOK)       // 2432 = 19*128
#define NLAYER 12
#define NBLK  2
#define BPL   6
#define RANKR 16
#define NQRY  8
#define NQKV  1536               // 1024 q + 256 k + 256 v
#define NGU   5632               // 2816 gate + 2816 up

// ---------------- scratch (device globals; no allocs allowed) ----------------
__device__ float g_x   [BT*DIM];
__device__ float g_qkv [BT*NQKV];
__device__ float g_o   [BT*DIM];
__device__ float g_gu  [BT*NGU];
__device__ float g_pool[BATCH*NSEG*DIM];
__device__ float g_scores[BATCH*NSEG];
__device__ int   g_tok [BATCH*KTOK];
__device__ float g_bqkv[NLAYER*NQKV];

// pre-packed bf16 hi/lo pair weights (pair along K: u32 = {lo16=k, hi16=k+1})
__device__ uint32_t g_wqkvh[NLAYER*512*NQKV], g_wqkvl[NLAYER*512*NQKV];
__device__ uint32_t g_woh  [NLAYER*512*1024], g_wol  [NLAYER*512*1024];
__device__ uint32_t g_wguh [NLAYER*512*NGU],  g_wgul [NLAYER*512*NGU];
__device__ uint32_t g_wdh  [NLAYER*1408*1024],g_wdl  [NLAYER*1408*1024];
// activation pair buffers
__device__ uint32_t g_hh[BT*DIM/2],  g_hl[BT*DIM/2];
__device__ uint32_t g_oh[BT*DIM/2],  g_ol[BT*DIM/2];
__device__ uint32_t g_gh[BT*FFD/2],  g_gl[BT*FFD/2];

// ---------------- split helper: fp32 pair -> bf16 hi/lo pair u32s ----------------
__device__ __forceinline__ void split_pair(float x0, float x1, uint32_t& hp, uint32_t& lp) {
    uint32_t h;
    asm("cvt.rn.bf16x2.f32 %0, %1, %2;" : "=r"(h) : "f"(x1), "f"(x0));
    float h0 = __uint_as_float(h << 16);
    float h1 = __uint_as_float(h & 0xFFFF0000u);
    float l0 = x0 - h0, l1 = x1 - h1;
    uint32_t l;
    asm("cvt.rn.bf16x2.f32 %0, %1, %2;" : "=r"(l) : "f"(l1), "f"(l0));
    hp = h; lp = l;
}

// ---------------- weight prepacks ----------------
// generic: src [R][N] f32 (R even) -> dst [R/2][N] u32 hi/lo (same N)
__global__ void prepack_kernel(const float* __restrict__ src,
                               uint32_t* __restrict__ dh, uint32_t* __restrict__ dl,
                               int n4row, int N) {
    int idx = blockIdx.x * 256 + threadIdx.x;
    int p = idx / n4row, c = (idx - p * n4row) * 4;
    const float* r0 = src + (size_t)(2 * p) * N + c;
    float4 a = *(const float4*)r0;
    float4 b = *(const float4*)(r0 + N);
    uint4 h, l;
    split_pair(a.x, b.x, h.x, l.x);
    split_pair(a.y, b.y, h.y, l.y);
    split_pair(a.z, b.z, h.z, l.z);
    split_pair(a.w, b.w, h.w, l.w);
    *(uint4*)(dh + (size_t)idx * 4) = h;
    *(uint4*)(dl + (size_t)idx * 4) = l;
}

// fused QKV: dst [L][512][1536] from wq [L][1024][1024], wk/wv [L][1024][256]
__global__ void prepack_qkv_kernel(const float* __restrict__ wq,
                                   const float* __restrict__ wk,
                                   const float* __restrict__ wv,
                                   uint32_t* __restrict__ dh, uint32_t* __restrict__ dl) {
    int idx = blockIdx.x * 256 + threadIdx.x;       // uint4 index over L*512*384
    int l = idx / (512 * 384);
    int rem = idx - l * (512 * 384);
    int p = rem / 384, col = (rem - p * 384) * 4;
    const float *s0;
    int srcN;
    if (col < 1024)      { s0 = wq + ((size_t)(l * 1024 + 2 * p)) * 1024 + col;          srcN = 1024; }
    else if (col < 1280) { s0 = wk + ((size_t)(l * 1024 + 2 * p)) * 256 + (col - 1024);  srcN = 256; }
    else                 { s0 = wv + ((size_t)(l * 1024 + 2 * p)) * 256 + (col - 1280);  srcN = 256; }
    float4 a = *(const float4*)s0;
    float4 b = *(const float4*)(s0 + srcN);
    uint4 h, l4;
    split_pair(a.x, b.x, h.x, l4.x);
    split_pair(a.y, b.y, h.y, l4.y);
    split_pair(a.z, b.z, h.z, l4.z);
    split_pair(a.w, b.w, h.w, l4.w);
    *(uint4*)(dh + (size_t)idx * 4) = h;
    *(uint4*)(dl + (size_t)idx * 4) = l4;
}

// fused gate+up: dst [L][512][5632] from wg/wu [L][1024][2816]
__global__ void prepack_gu_kernel(const float* __restrict__ wg,
                                  const float* __restrict__ wu,
                                  uint32_t* __restrict__ dh, uint32_t* __restrict__ dl) {
    int idx = blockIdx.x * 256 + threadIdx.x;       // uint4 index over L*512*1408
    int l = idx / (512 * 1408);
    int rem = idx - l * (512 * 1408);
    int p = rem / 1408, col = (rem - p * 1408) * 4;
    const float* s0 = (col < 2816)
        ? wg + ((size_t)(l * 1024 + 2 * p)) * 2816 + col
        : wu + ((size_t)(l * 1024 + 2 * p)) * 2816 + (col - 2816);
    float4 a = *(const float4*)s0;
    float4 b = *(const float4*)(s0 + 2816);
    uint4 h, l4;
    split_pair(a.x, b.x, h.x, l4.x);
    split_pair(a.y, b.y, h.y, l4.y);
    split_pair(a.z, b.z, h.z, l4.z);
    split_pair(a.w, b.w, h.w, l4.w);
    *(uint4*)(dh + (size_t)idx * 4) = h;
    *(uint4*)(dl + (size_t)idx * 4) = l4;
}

__global__ void fuse_bias_kernel(const float* __restrict__ bq,
                                 const float* __restrict__ bk,
                                 const float* __restrict__ bv,
                                 float* __restrict__ dst) {
    int i = blockIdx.x * 256 + threadIdx.x;         // L*1536
    int l = i / NQKV, j = i - l * NQKV;
    float v = (j < 1024) ? bq[l * 1024 + j]
            : (j < 1280) ? bk[l * 256 + j - 1024]
                         : bv[l * 256 + j - 1280];
    dst[i] = v;
}

// ---------------- activation pack: fp32 -> pair (row-contiguous K) ----------------
__global__ void pack_act_kernel(const float* __restrict__ src,
                                uint32_t* __restrict__ dh, uint32_t* __restrict__ dl) {
    int i = blockIdx.x * 256 + threadIdx.x;
    float4 v = ((const float4*)src)[i];
    uint32_t h0, l0, h1, l1;
    split_pair(v.x, v.y, h0, l0);
    split_pair(v.z, v.w, h1, l1);
    *(uint2*)&dh[(size_t)i * 2] = make_uint2(h0, h1);
    *(uint2*)&dl[(size_t)i * 2] = make_uint2(l0, l1);
}

// ---------------- embed gather ----------------
__global__ void embed_kernel(const int* __restrict__ ids,
                             const float* __restrict__ emb,
                             float* __restrict__ hidden) {
    int row = blockIdx.x;
    int id  = ids[row];
    const float4* src = (const float4*)(emb + (size_t)id * DIM);
    float4* dst = (float4*)(hidden + (size_t)row * DIM);
    dst[threadIdx.x] = src[threadIdx.x];
}

// ---------------- segment mean pool ----------------
__global__ void pool_kernel(const float* __restrict__ hidden,
                            float* __restrict__ pooled) {
    int b = blockIdx.x >> 8, n = blockIdx.x & 255;
    const float* base = hidden + ((size_t)b * SEQ + n * SEGLEN) * DIM + threadIdx.x * 4;
    float4 acc = make_float4(0.f, 0.f, 0.f, 0.f);
#pragma unroll
    for (int t = 0; t < SEGLEN; t++) {
        float4 v = *(const float4*)(base + (size_t)t * DIM);
        acc.x += v.x; acc.y += v.y; acc.z += v.z; acc.w += v.w;
    }
    const float s = 1.f / SEGLEN;
    acc.x *= s; acc.y *= s; acc.z *= s; acc.w *= s;
    *(float4*)(pooled + ((size_t)b * NSEG + n) * DIM + threadIdx.x * 4) = acc;
}

// ---------------- multi-query router scores ----------------
__global__ void router_kernel(const float* __restrict__ pooled,
                              const float* __restrict__ rk,
                              const float* __restrict__ rq,
                              float* __restrict__ scores) {
    int n = blockIdx.x, b = blockIdx.y;
    const float* p = pooled + ((size_t)b * NSEG + n) * DIM;
    __shared__ float part[128];
    int tid = threadIdx.x;
    int r = tid & 15, g = tid >> 4;
    float sum = 0.f;
    int d0 = g * 128;
    for (int d = d0; d < d0 + 128; d++) sum += p[d] * rk[d * RANKR + r];
    part[tid] = sum;
    __syncthreads();
    if (tid < RANKR) {
        float key = 0.f;
        for (int gg = 0; gg < 8; gg++) key += part[gg * 16 + tid];
        part[tid] = key;
    }
    __syncthreads();
    if (tid == 0) {
        float best = -1e30f;
        for (int qq = 0; qq < NQRY; qq++) {
            float dv = 0.f;
            for (int rr = 0; rr < RANKR; rr++) dv += rq[qq * RANKR + rr] * part[rr];
            best = fmaxf(best, dv);
        }
        scores[b * NSEG + n] = best;
    }
}

// ---------------- top-k select ----------------
__global__ void select_kernel(const float* __restrict__ scores,
                              int* __restrict__ tok) {
    int b = blockIdx.x;
    __shared__ float s[NSEG];
    __shared__ int pf[NSEG];
    int i = threadIdx.x;
    float mine = scores[b * NSEG + i];
    s[i] = mine;
    __syncthreads();
    int rank = 0;
    for (int j = 0; j < NSEG; j++) {
        float o = s[j];
        rank += (o > mine) || (o == mine && j < i);
    }
    int sel = (rank < KSEG) ? 1 : 0;
    pf[i] = sel;
    __syncthreads();
    for (int off = 1; off < NSEG; off <<= 1) {
        int add = (i >= off) ? pf[i - off] : 0;
        __syncthreads();
        pf[i] += add;
        __syncthreads();
    }
    if (sel) {
        int p = pf[i] - 1;
        int* dst = tok + b * KTOK + p * SEGLEN;
        int base = i * SEGLEN;
#pragma unroll
        for (int t = 0; t < SEGLEN; t++) dst[t] = base + t;
    }
}

// ---------------- scatter ----------------
__global__ void scatter_kernel(const float* __restrict__ x,
                               const int* __restrict__ tok,
                               float* __restrict__ hidden) {
    int row = blockIdx.x;
    int b = row / KTOK;
    int tk = tok[row];
    const float4* src = (const float4*)(x + (size_t)row * DIM);
    float4* dst = (float4*)(hidden + ((size_t)b * SEQ + tk) * DIM);
    dst[threadIdx.x] = src[threadIdx.x];
}

// ---------------- RMSNorm core (shared by plain and fused-gather variants) ----
__device__ __forceinline__ void rms_body(float4 v, const float* w, int row, int t,
                                         uint32_t* oh, uint32_t* ol) {
    float ss = v.x * v.x + v.y * v.y + v.z * v.z + v.w * v.w;
#pragma unroll
    for (int d = 16; d >= 1; d >>= 1) ss += __shfl_xor_sync(0xffffffffu, ss, d);
    __shared__ float ws[8];
    __shared__ float tot;
    if ((t & 31) == 0) ws[t >> 5] = ss;
    __syncthreads();
    if (t == 0) {
        float a = 0.f;
        for (int wgi = 0; wgi < 8; wgi++) a += ws[wgi];
        tot = a;
    }
    __syncthreads();
    float inv = rsqrtf(tot * (1.f / DIM) + 1e-6f);
    float4 wv = ((const float4*)w)[t];
    float o0 = v.x * inv * wv.x, o1 = v.y * inv * wv.y;
    float o2 = v.z * inv * wv.z, o3 = v.w * inv * wv.w;
    uint32_t h0, l0, h1, l1;
    split_pair(o0, o1, h0, l0);
    split_pair(o2, o3, h1, l1);
    size_t base = (size_t)row * (DIM / 2) + t * 2;
    *(uint2*)&oh[base] = make_uint2(h0, h1);
    *(uint2*)&ol[base] = make_uint2(l0, l1);
}

__global__ void rmsnorm_kernel(const float* __restrict__ x,
                               const float* __restrict__ w,
                               uint32_t* __restrict__ oh,
                               uint32_t* __restrict__ ol) {
    int row = blockIdx.x, t = threadIdx.x;
    float4 v = ((const float4*)(x + (size_t)row * DIM))[t];
    rms_body(v, w, row, t, oh, ol);
}

// gather + rmsnorm fused (first layer of a block)
__global__ void gather_norm_kernel(const float* __restrict__ hidden,
                                   const int* __restrict__ tok,
                                   const float* __restrict__ w,
                                   float* __restrict__ x,
                                   uint32_t* __restrict__ oh,
                                   uint32_t* __restrict__ ol) {
    int row = blockIdx.x, t = threadIdx.x;
    int b = row / KTOK;
    int tk = tok[row];
    float4 v = ((const float4*)(hidden + ((size_t)b * SEQ + tk) * DIM))[t];
    ((float4*)(x + (size_t)row * DIM))[t] = v;
    rms_body(v, w, row, t, oh, ol);
}

// ---------------- RoPE (on fused qkv buffer, stride 1536) ----------------
__global__ void rope_kernel(float* __restrict__ qkv, const int* __restrict__ tok) {
    int row = blockIdx.x;
    float pos = (float)tok[row];
    int t = threadIdx.x;
    float* base = qkv + (size_t)row * NQKV;
    for (int pidx = t; pidx < NHEAD * 32; pidx += 256) {
        int hh = pidx >> 5, i = pidx & 31;
        float inv = __powf(10000.f, -(float)(2 * i) / (float)HEADD);
        float ang = pos * inv;
        float sn, cs;
        sincosf(ang, &sn, &cs);
        float* qp = base + hh * HEADD;
        float x1 = qp[i], x2 = qp[i + 32];
        qp[i]      = x1 * cs - x2 * sn;
        qp[i + 32] = x2 * cs + x1 * sn;
    }
    if (t < KVHEAD * 32) {
        int hh = t >> 5, i = t & 31;
        float inv = __powf(10000.f, -(float)(2 * i) / (float)HEADD);
        float ang = pos * inv;
        float sn, cs;
        sincosf(ang, &sn, &cs);
        float* kp = base + 1024 + hh * HEADD;
        float x1 = kp[i], x2 = kp[i + 32];
        kp[i]      = x1 * cs - x2 * sn;
        kp[i + 32] = x2 * cs + x1 * sn;
    }
}

// ---------------- bf16 MMA primitive ----------------
__device__ __forceinline__ void mma_bf16(float c[4], const uint32_t a[4], const uint32_t b[2]) {
    asm volatile(
        "mma.sync.aligned.m16n8k16.row.col.f32.bf16.bf16.f32 "
        "{%0,%1,%2,%3}, {%4,%5,%6,%7}, {%8,%9}, {%0,%1,%2,%3};\n"
        : "+f"(c[0]), "+f"(c[1]), "+f"(c[2]), "+f"(c[3])
        : "r"(a[0]), "r"(a[1]), "r"(a[2]), "r"(a[3]), "r"(b[0]), "r"(b[1]));
}

// ---------------- pair-format split-bf16 (3xMMA) GEMM ----------------
#define ASU 20
#define BSU 136
template <int FLAGS>   // bit0: add bias, bit1: add existing C (residual)
__global__ void __launch_bounds__(256)
pgemm_kernel(const uint32_t* __restrict__ Ahp, const uint32_t* __restrict__ Alp,
             const uint32_t* __restrict__ Whp, const uint32_t* __restrict__ Wlp,
             const float* __restrict__ bias,
             float* __restrict__ C,
             int M, int N, int K2) {        // K2 = K/2 (pairs)
    __shared__ uint32_t sAh[128 * ASU], sAl[128 * ASU];
    __shared__ uint32_t sBh[16 * BSU],  sBl[16 * BSU];
    int tid = threadIdx.x, lane = tid & 31, warp = tid >> 5;
    int warpM = warp & 1, warpN = warp >> 1;
    int m0 = blockIdx.y * 128, n0 = blockIdx.x * 128;
    int gid = lane >> 2, tig = lane & 3;

    float c[4][4][4];
#pragma unroll
    for (int i = 0; i < 4; i++)
#pragma unroll
        for (int j = 0; j < 4; j++)
#pragma unroll
            for (int f = 0; f < 4; f++) c[i][j][f] = 0.f;

    for (int p0 = 0; p0 < K2; p0 += 16) {
        uint4 aH[2], aL[2], bH[2], bL[2];
#pragma unroll
        for (int i = 0; i < 2; i++) {
            int f = tid + 256 * i;
            int arow = f >> 2, apc = (f & 3) * 4;
            size_t aoff = (size_t)(m0 + arow) * K2 + p0 + apc;
            aH[i] = *(const uint4*)&Ahp[aoff];
            aL[i] = *(const uint4*)&Alp[aoff];
            int pr = f >> 5, cg = (f & 31) * 4;
            size_t boff = (size_t)(p0 + pr) * N + n0 + cg;
            bH[i] = *(const uint4*)&Whp[boff];
            bL[i] = *(const uint4*)&Wlp[boff];
        }
        __syncthreads();
#pragma unroll
        for (int i = 0; i < 2; i++) {
            int f = tid + 256 * i;
            int arow = f >> 2, apc = (f & 3) * 4;
            *(uint4*)&sAh[arow * ASU + apc] = aH[i];
            *(uint4*)&sAl[arow * ASU + apc] = aL[i];
            int pr = f >> 5, cg = (f & 31) * 4;
            *(uint4*)&sBh[pr * BSU + cg] = bH[i];
            *(uint4*)&sBl[pr * BSU + cg] = bL[i];
        }
        __syncthreads();
#pragma unroll
        for (int kk = 0; kk < 2; kk++) {
            int kp = kk * 8;
            uint32_t bh[4][2], bl[4][2];
#pragma unroll
            for (int nt = 0; nt < 4; nt++) {
                int cb = warpN * 32 + nt * 8 + gid;
                bh[nt][0] = sBh[(kp + tig) * BSU + cb];
                bh[nt][1] = sBh[(kp + tig + 4) * BSU + cb];
                bl[nt][0] = sBl[(kp + tig) * BSU + cb];
                bl[nt][1] = sBl[(kp + tig + 4) * BSU + cb];
            }
#pragma unroll
            for (int mt = 0; mt < 4; mt++) {
                int rb = warpM * 64 + mt * 16 + gid;
                uint32_t ah[4], al[4];
                ah[0] = sAh[rb * ASU + kp + tig];
                ah[1] = sAh[(rb + 8) * ASU + kp + tig];
                ah[2] = sAh[rb * ASU + kp + tig + 4];
                ah[3] = sAh[(rb + 8) * ASU + kp + tig + 4];
                al[0] = sAl[rb * ASU + kp + tig];
                al[1] = sAl[(rb + 8) * ASU + kp + tig];
                al[2] = sAl[rb * ASU + kp + tig + 4];
                al[3] = sAl[(rb + 8) * ASU + kp + tig + 4];
#pragma unroll
                for (int nt = 0; nt < 4; nt++) {
                    mma_bf16(c[mt][nt], ah, bh[nt]);
                    mma_bf16(c[mt][nt], al, bh[nt]);
                    mma_bf16(c[mt][nt], ah, bl[nt]);
                }
            }
        }
    }
#pragma unroll
    for (int mt = 0; mt < 4; mt++) {
#pragma unroll
        for (int half = 0; half < 2; half++) {
            int row = m0 + warpM * 64 + mt * 16 + gid + half * 8;
            float* Crow = C + (size_t)row * N + n0 + warpN * 32;
#pragma unroll
            for (int nt = 0; nt < 4; nt++) {
                int col = nt * 8 + tig * 2;
                float2 r;
                r.x = c[mt][nt][half * 2 + 0];
                r.y = c[mt][nt][half * 2 + 1];
                if (FLAGS & 1) {
                    float2 bb = *(const float2*)&bias[n0 + warpN * 32 + col];
                    r.x += bb.x; r.y += bb.y;
                }
                if (FLAGS & 2) {
                    float2 cc = *(const float2*)&Crow[col];
                    r.x += cc.x; r.y += cc.y;
                }
                *(float2*)&Crow[col] = r;
            }
        }
    }
}

// ---------------- tensor-core flash attention (split-bf16, causal, GQA) ----------
// grid (KTOK/64, NHEAD, BATCH), 128 threads = 4 warps (16 q-rows each).
// S = Qh*Kh + Ql*Kh + Qh*Kl ; O += Ph*Vh + Pl*Vh + Ph*Vl  (all m16n8k16)
#define ATSU 36
__global__ void __launch_bounds__(128)
attn_mma_kernel(const float* __restrict__ qkv, float* __restrict__ o) {
    __shared__ uint32_t sm0[64 * ATSU], sm1[64 * ATSU];   // Q (prologue) then K hi/lo
    __shared__ uint32_t sm2[64 * ATSU], sm3[64 * ATSU];   // V^T hi/lo [d][tokpair]
    const int T = KTOK;
    int qt = blockIdx.x, h = blockIdx.y, b = blockIdx.z;
    int kh = h >> 2;
    int tid = threadIdx.x, lane = tid & 31, warp = tid >> 5;
    int gid = lane >> 2, tig = lane & 3;

    // ---- Q tile (scaled) -> sm0/sm1 pairs along d ----
    for (int i = tid; i < 1024; i += 128) {
        int row = i >> 4, c4 = (i & 15) << 2;
        const float* src = &qkv[((size_t)(b * T + qt * 64 + row)) * NQKV + h * HEADD + c4];
        float4 v = *(const float4*)src;
        v.x *= 0.125f; v.y *= 0.125f; v.z *= 0.125f; v.w *= 0.125f;
        uint32_t h0, l0, h1, l1;
        split_pair(v.x, v.y, h0, l0);
        split_pair(v.z, v.w, h1, l1);
        int p = c4 >> 1;
        sm0[row * ATSU + p] = h0; sm0[row * ATSU + p + 1] = h1;
        sm1[row * ATSU + p] = l0; sm1[row * ATSU + p + 1] = l1;
    }
    __syncthreads();
    // hoist Q fragments (loop-invariant)
    uint32_t qh[4][4], ql[4][4];
    {
        int r0 = warp * 16 + gid, r1 = r0 + 8;
#pragma unroll
        for (int kc = 0; kc < 4; kc++) {
            int p = kc * 8 + tig;
            qh[kc][0] = sm0[r0 * ATSU + p];
            qh[kc][1] = sm0[r1 * ATSU + p];
            qh[kc][2] = sm0[r0 * ATSU + p + 4];
            qh[kc][3] = sm0[r1 * ATSU + p + 4];
            ql[kc][0] = sm1[r0 * ATSU + p];
            ql[kc][1] = sm1[r1 * ATSU + p];
            ql[kc][2] = sm1[r0 * ATSU + p + 4];
            ql[kc][3] = sm1[r1 * ATSU + p + 4];
        }
    }

    float accO[8][4];
#pragma unroll
    for (int nt = 0; nt < 8; nt++)
#pragma unroll
        for (int f = 0; f < 4; f++) accO[nt][f] = 0.f;
    float m0r = -1e30f, m1r = -1e30f, l0r = 0.f, l1r = 0.f;

    for (int kt = 0; kt <= qt; kt++) {
        __syncthreads();
        // K tile -> sm0/sm1 (pairs along d)
        for (int i = tid; i < 1024; i += 128) {
            int row = i >> 4, c4 = (i & 15) << 2;
            const float* src = &qkv[((size_t)(b * T + kt * 64 + row)) * NQKV + 1024 + kh * HEADD + c4];
            float4 v = *(const float4*)src;
            uint32_t h0, l0, h1, l1;
            split_pair(v.x, v.y, h0, l0);
            split_pair(v.z, v.w, h1, l1);
            int p = c4 >> 1;
            sm0[row * ATSU + p] = h0; sm0[row * ATSU + p + 1] = h1;
            sm1[row * ATSU + p] = l0; sm1[row * ATSU + p + 1] = l1;
        }
        // V tile transposed -> sm2/sm3 [d][tokpair]
        for (int i = tid; i < 512; i += 128) {
            int pt = i & 31, d4 = (i >> 5) << 2;
            const float* s0 = &qkv[((size_t)(b * T + kt * 64 + 2 * pt)) * NQKV + 1280 + kh * HEADD + d4];
            float4 a = *(const float4*)s0;
            float4 c = *(const float4*)(s0 + NQKV);
            uint32_t hh_, ll_;
            split_pair(a.x, c.x, hh_, ll_); sm2[(d4 + 0) * ATSU + pt] = hh_; sm3[(d4 + 0) * ATSU + pt] = ll_;
            split_pair(a.y, c.y, hh_, ll_); sm2[(d4 + 1) * ATSU + pt] = hh_; sm3[(d4 + 1) * ATSU + pt] = ll_;
            split_pair(a.z, c.z, hh_, ll_); sm2[(d4 + 2) * ATSU + pt] = hh_; sm3[(d4 + 2) * ATSU + pt] = ll_;
            split_pair(a.w, c.w, hh_, ll_); sm2[(d4 + 3) * ATSU + pt] = hh_; sm3[(d4 + 3) * ATSU + pt] = ll_;
        }
        __syncthreads();

        // ---- S = Q K^T ----
        float s[8][4];
#pragma unroll
        for (int nt = 0; nt < 8; nt++)
#pragma unroll
            for (int f = 0; f < 4; f++) s[nt][f] = 0.f;
#pragma unroll
        for (int kc = 0; kc < 4; kc++) {
#pragma unroll
            for (int nt = 0; nt < 8; nt++) {
                int tok = nt * 8 + gid;
                uint32_t bh[2], bl[2];
                bh[0] = sm0[tok * ATSU + kc * 8 + tig];
                bh[1] = sm0[tok * ATSU + kc * 8 + tig + 4];
                bl[0] = sm1[tok * ATSU + kc * 8 + tig];
                bl[1] = sm1[tok * ATSU + kc * 8 + tig + 4];
                mma_bf16(s[nt], qh[kc], bh);
                mma_bf16(s[nt], ql[kc], bh);
                mma_bf16(s[nt], qh[kc], bl);
            }
        }
        // ---- causal mask on diagonal tile ----
        if (kt == qt) {
            int r0 = warp * 16 + gid, r1 = r0 + 8;
#pragma unroll
            for (int nt = 0; nt < 8; nt++) {
                int c0 = nt * 8 + 2 * tig, c1 = c0 + 1;
                if (c0 > r0) s[nt][0] = -1e30f;
                if (c1 > r0) s[nt][1] = -1e30f;
                if (c0 > r1) s[nt][2] = -1e30f;
                if (c1 > r1) s[nt][3] = -1e30f;
            }
        }
        // ---- online softmax (rows r0 = warp*16+gid, r1 = +8) ----
        float mx0 = -1e30f, mx1 = -1e30f;
#pragma unroll
        for (int nt = 0; nt < 8; nt++) {
            mx0 = fmaxf(mx0, fmaxf(s[nt][0], s[nt][1]));
            mx1 = fmaxf(mx1, fmaxf(s[nt][2], s[nt][3]));
        }
        mx0 = fmaxf(mx0, __shfl_xor_sync(0xffffffffu, mx0, 1));
        mx0 = fmaxf(mx0, __shfl_xor_sync(0xffffffffu, mx0, 2));
        mx1 = fmaxf(mx1, __shfl_xor_sync(0xffffffffu, mx1, 1));
        mx1 = fmaxf(mx1, __shfl_xor_sync(0xffffffffu, mx1, 2));
        float mn0 = fmaxf(m0r, mx0), mn1 = fmaxf(m1r, mx1);
        float cor0 = __expf(m0r - mn0), cor1 = __expf(m1r - mn1);
        float ps0 = 0.f, ps1 = 0.f;
#pragma unroll
        for (int nt = 0; nt < 8; nt++) {
            s[nt][0] = __expf(s[nt][0] - mn0);
            s[nt][1] = __expf(s[nt][1] - mn0);
            s[nt][2] = __expf(s[nt][2] - mn1);
            s[nt][3] = __expf(s[nt][3] - mn1);
            ps0 += s[nt][0] + s[nt][1];
            ps1 += s[nt][2] + s[nt][3];
        }
        ps0 += __shfl_xor_sync(0xffffffffu, ps0, 1);
        ps0 += __shfl_xor_sync(0xffffffffu, ps0, 2);
        ps1 += __shfl_xor_sync(0xffffffffu, ps1, 1);
        ps1 += __shfl_xor_sync(0xffffffffu, ps1, 2);
        l0r = l0r * cor0 + ps0;  m0r = mn0;
        l1r = l1r * cor1 + ps1;  m1r = mn1;
#pragma unroll
        for (int nt = 0; nt < 8; nt++) {
            accO[nt][0] *= cor0; accO[nt][1] *= cor0;
            accO[nt][2] *= cor1; accO[nt][3] *= cor1;
        }
        // ---- O += P V (P fragments built in registers from S fragments) ----
#pragma unroll
        for (int kc = 0; kc < 4; kc++) {
            uint32_t ph[4], pl[4];
            split_pair(s[2 * kc][0],     s[2 * kc][1],     ph[0], pl[0]);
            split_pair(s[2 * kc][2],     s[2 * kc][3],     ph[1], pl[1]);
            split_pair(s[2 * kc + 1][0], s[2 * kc + 1][1], ph[2], pl[2]);
            split_pair(s[2 * kc + 1][2], s[2 * kc + 1][3], ph[3], pl[3]);
#pragma unroll
            for (int nt = 0; nt < 8; nt++) {
                int d = nt * 8 + gid;
                uint32_t vh[2], vl[2];
                vh[0] = sm2[d * ATSU + kc * 8 + tig];
                vh[1] = sm2[d * ATSU + kc * 8 + tig + 4];
                vl[0] = sm3[d * ATSU + kc * 8 + tig];
                vl[1] = sm3[d * ATSU + kc * 8 + tig + 4];
                mma_bf16(accO[nt], ph, vh);
                mma_bf16(accO[nt], pl, vh);
                mma_bf16(accO[nt], ph, vl);
            }
        }
    }
    // ---- epilogue ----
    float i0 = 1.f / l0r, i1 = 1.f / l1r;
    int r0 = qt * 64 + warp * 16 + gid;
#pragma unroll
    for (int nt = 0; nt < 8; nt++) {
        int d = h * HEADD + nt * 8 + 2 * tig;
        float2 w0 = make_float2(accO[nt][0] * i0, accO[nt][1] * i0);
        *(float2*)&o[((size_t)(b * T + r0)) * DIM + d] = w0;
        float2 w1 = make_float2(accO[nt][2] * i1, accO[nt][3] * i1);
        *(float2*)&o[((size_t)(b * T + r0 + 8)) * DIM + d] = w1;
    }
}

// ---------------- silu(gate)*up from fused gu -> pair buffers ----------------
__global__ void silu_mul_kernel(const float* __restrict__ gu,
                                uint32_t* __restrict__ dh, uint32_t* __restrict__ dl) {
    int idx = blockIdx.x * 256 + threadIdx.x;     // over BT * (FFD/4)
    int row = idx / (FFD / 4), c4 = (idx - row * (FFD / 4)) * 4;
    const float* base = gu + (size_t)row * NGU;
    float4 x = *(const float4*)(base + c4);
    float4 y = *(const float4*)(base + FFD + c4);
    float o0 = x.x / (1.f + __expf(-x.x)) * y.x;
    float o1 = x.y / (1.f + __expf(-x.y)) * y.y;
    float o2 = x.z / (1.f + __expf(-x.z)) * y.z;
    float o3 = x.w / (1.f + __expf(-x.w)) * y.w;
    uint32_t h0, l0, h1, l1;
    split_pair(o0, o1, h0, l0);
    split_pair(o2, o3, h1, l1);
    size_t base2 = (size_t)row * (FFD / 2) + (c4 >> 1);
    *(uint2*)&dh[base2] = make_uint2(h0, h1);
    *(uint2*)&dl[base2] = make_uint2(l0, l1);
}

// ---------------- launch ----------------
extern "C" void kernel_launch(void* const* d_in, const int* in_sizes, int n_in,
                              void* d_out, int out_size) {
    const int*   ids      = (const int*)d_in[0];
    const float* emb      = (const float*)d_in[1];
    const float* router_k = (const float*)d_in[2];
    const float* router_q = (const float*)d_in[3];
    const float* ln1      = (const float*)d_in[4];
    const float* ln2      = (const float*)d_in[5];
    const float* wq       = (const float*)d_in[6];
    const float* bq       = (const float*)d_in[7];
    const float* wk       = (const float*)d_in[8];
    const float* bk       = (const float*)d_in[9];
    const float* wv       = (const float*)d_in[10];
    const float* bv       = (const float*)d_in[11];
    const float* wo       = (const float*)d_in[12];
    const float* wg       = (const float*)d_in[13];
    const float* wu       = (const float*)d_in[14];
    const float* wd       = (const float*)d_in[15];
    float* hidden = (float*)d_out;

    float *x, *qkv, *o, *gu, *pooled, *scores, *bqkv;
    int* tok;
    uint32_t *wqkvh, *wqkvl, *woh, *wol, *wguh, *wgul, *wdh, *wdl;
    uint32_t *hh, *hl, *oh, *ol, *gh, *gl;
    cudaGetSymbolAddress((void**)&x, g_x);
    cudaGetSymbolAddress((void**)&qkv, g_qkv);
    cudaGetSymbolAddress((void**)&o, g_o);
    cudaGetSymbolAddress((void**)&gu, g_gu);
    cudaGetSymbolAddress((void**)&pooled, g_pool);
    cudaGetSymbolAddress((void**)&scores, g_scores);
    cudaGetSymbolAddress((void**)&tok, g_tok);
    cudaGetSymbolAddress((void**)&bqkv, g_bqkv);
    cudaGetSymbolAddress((void**)&wqkvh, g_wqkvh); cudaGetSymbolAddress((void**)&wqkvl, g_wqkvl);
    cudaGetSymbolAddress((void**)&woh, g_woh);     cudaGetSymbolAddress((void**)&wol, g_wol);
    cudaGetSymbolAddress((void**)&wguh, g_wguh);   cudaGetSymbolAddress((void**)&wgul, g_wgul);
    cudaGetSymbolAddress((void**)&wdh, g_wdh);     cudaGetSymbolAddress((void**)&wdl, g_wdl);
    cudaGetSymbolAddress((void**)&hh, g_hh);       cudaGetSymbolAddress((void**)&hl, g_hl);
    cudaGetSymbolAddress((void**)&oh, g_oh);       cudaGetSymbolAddress((void**)&ol, g_ol);
    cudaGetSymbolAddress((void**)&gh, g_gh);       cudaGetSymbolAddress((void**)&gl, g_gl);

    embed_kernel<<<BATCH * SEQ, 256>>>(ids, emb, hidden);

    // ---- weight prepacks (before first GEMM use) ----
    prepack_gu_kernel<<<NLAYER * 512 * 1408 / 256, 256>>>(wg, wu, wguh, wgul);
    prepack_qkv_kernel<<<NLAYER * 512 * 384 / 256, 256>>>(wq, wk, wv, wqkvh, wqkvl);
    prepack_kernel<<<NLAYER * 512 * 1024 / 1024, 256>>>(wo, woh, wol, 256, 1024);
    prepack_kernel<<<NLAYER * 1408 * 1024 / 1024, 256>>>(wd, wdh, wdl, 256, 1024);
    fuse_bias_kernel<<<NLAYER * NQKV / 256, 256>>>(bq, bk, bv, bqkv);

    for (int blk = 0; blk < NBLK; blk++) {
        int li0 = blk * BPL;
        pool_kernel<<<BATCH * NSEG, 256>>>(hidden, pooled);
        router_kernel<<<dim3(NSEG, BATCH), 128>>>(
            pooled, router_k + (size_t)blk * DIM * RANKR,
            router_q + (size_t)blk * NQRY * RANKR, scores);
        select_kernel<<<BATCH, 256>>>(scores, tok);
        gather_norm_kernel<<<BT, 256>>>(hidden, tok, ln1 + (size_t)li0 * DIM, x, hh, hl);

        for (int j = 0; j < BPL; j++) {
            int li = li0 + j;
            size_t oqkv = (size_t)li * 512 * NQKV;
            size_t oo   = (size_t)li * 512 * 1024;
            size_t ogu  = (size_t)li * 512 * NGU;
            size_t od   = (size_t)li * 1408 * 1024;

            if (j > 0)
                rmsnorm_kernel<<<BT, 256>>>(x, ln1 + (size_t)li * DIM, hh, hl);
            pgemm_kernel<1><<<dim3(NQKV / 128, BT / 128), 256>>>(
                hh, hl, wqkvh + oqkv, wqkvl + oqkv, bqkv + (size_t)li * NQKV,
                qkv, BT, NQKV, 512);
            rope_kernel<<<BT, 256>>>(qkv, tok);
            attn_mma_kernel<<<dim3(KTOK / 64, NHEAD, BATCH), 128>>>(qkv, o);
            pack_act_kernel<<<BT * DIM / 1024, 256>>>(o, oh, ol);
            pgemm_kernel<2><<<dim3(DIM / 128, BT / 128), 256>>>(
                oh, ol, woh + oo, wol + oo, nullptr, x, BT, DIM, 512);
            rmsnorm_kernel<<<BT, 256>>>(x, ln2 + (size_t)li * DIM, hh, hl);
            pgemm_kernel<0><<<dim3(NGU / 128, BT / 128), 256>>>(
                hh, hl, wguh + ogu, wgul + ogu, nullptr, gu, BT, NGU, 512);
            silu_mul_kernel<<<BT * (FFD / 4) / 256, 256>>>(gu, gh, gl);
            pgemm_kernel<2><<<dim3(DIM / 128, BT / 128), 256>>>(
                gh, gl, wdh + od, wdl + od, nullptr, x, BT, DIM, 1408);
        }
        scatter_kernel<<<BT, 256>>>(x, tok, hidden);
    }
}

// round 13
// speedup vs baseline: 3.2423x; 1.2604x over previous
#include <cuda_runtime.h>
#include <cuda_bf16.h>
#include <math.h>
#include <stdint.h>

// ---------------- problem constants ----------------
#define BATCH 2
#define SEQ   4096
#define DIM   1024
#define NHEAD 16
#define KVHEAD 4
#define HEADD 64
#define FFD   2816
#define NSEG  256
#define SEGLEN 16
#define KSEG  76
#define KTOK  (KSEG*SEGLEN)      // 1216
#define BT    (BATCH*KTOK)       // 2432 = 19*128
#define NLAYER 12
#define NBLK  2
#define BPL   6
#define RANKR 16
#define NQRY  8
#define NQKV  1536
#define NGU   5632

// ---------------- scratch (device globals; no allocs allowed) ----------------
__device__ float g_x   [BT*DIM];
__device__ float g_qkv [BT*NQKV];
__device__ float g_o   [BT*DIM];
__device__ float g_gu  [BT*NGU];
__device__ float g_pool[BATCH*NSEG*DIM];
__device__ float g_scores[BATCH*NSEG];
__device__ int   g_tok [BATCH*KTOK];
__device__ float g_bqkv[NLAYER*NQKV];

// pre-packed bf16 hi/lo pair weights: [L][K/2][N] u32 (u32 = bf16 pair along K)
__device__ uint32_t g_wqkvh[NLAYER*512*NQKV], g_wqkvl[NLAYER*512*NQKV];
__device__ uint32_t g_woh  [NLAYER*512*1024], g_wol  [NLAYER*512*1024];
__device__ uint32_t g_wguh [NLAYER*512*NGU],  g_wgul [NLAYER*512*NGU];
__device__ uint32_t g_wdh  [NLAYER*1408*1024],g_wdl  [NLAYER*1408*1024];
// activation pair buffers [M][K/2]
__device__ uint32_t g_hh[BT*DIM/2],  g_hl[BT*DIM/2];
__device__ uint32_t g_oh[BT*DIM/2],  g_ol[BT*DIM/2];
__device__ uint32_t g_gh[BT*FFD/2],  g_gl[BT*FFD/2];

// ---------------- split helper ----------------
__device__ __forceinline__ void split_pair(float x0, float x1, uint32_t& hp, uint32_t& lp) {
    uint32_t h;
    asm("cvt.rn.bf16x2.f32 %0, %1, %2;" : "=r"(h) : "f"(x1), "f"(x0));
    float h0 = __uint_as_float(h << 16);
    float h1 = __uint_as_float(h & 0xFFFF0000u);
    float l0 = x0 - h0, l1 = x1 - h1;
    uint32_t l;
    asm("cvt.rn.bf16x2.f32 %0, %1, %2;" : "=r"(l) : "f"(l1), "f"(l0));
    hp = h; lp = l;
}
__device__ __forceinline__ uint32_t smem_u32(const void* p) {
    uint32_t a;
    asm("{ .reg .u64 t; cvta.to.shared.u64 t, %1; cvt.u32.u64 %0, t; }" : "=r"(a) : "l"(p));
    return a;
}
__device__ __forceinline__ void cpasync16(uint32_t dst, const void* src) {
    asm volatile("cp.async.cg.shared.global [%0], [%1], 16;" :: "r"(dst), "l"(src));
}
#define CP_COMMIT() asm volatile("cp.async.commit_group;" ::: "memory")
#define CP_WAIT1()  asm volatile("cp.async.wait_group 1;" ::: "memory")
#define CP_WAIT0()  asm volatile("cp.async.wait_group 0;" ::: "memory")

// ---------------- weight prepacks ----------------
__global__ void prepack_kernel(const float* __restrict__ src,
                               uint32_t* __restrict__ dh, uint32_t* __restrict__ dl,
                               int n4row, int N) {
    int idx = blockIdx.x * 256 + threadIdx.x;
    int p = idx / n4row, c = (idx - p * n4row) * 4;
    const float* r0 = src + (size_t)(2 * p) * N + c;
    float4 a = *(const float4*)r0;
    float4 b = *(const float4*)(r0 + N);
    uint4 h, l;
    split_pair(a.x, b.x, h.x, l.x);
    split_pair(a.y, b.y, h.y, l.y);
    split_pair(a.z, b.z, h.z, l.z);
    split_pair(a.w, b.w, h.w, l.w);
    *(uint4*)(dh + (size_t)idx * 4) = h;
    *(uint4*)(dl + (size_t)idx * 4) = l;
}

__global__ void prepack_qkv_kernel(const float* __restrict__ wq,
                                   const float* __restrict__ wk,
                                   const float* __restrict__ wv,
                                   uint32_t* __restrict__ dh, uint32_t* __restrict__ dl) {
    int idx = blockIdx.x * 256 + threadIdx.x;       // uint4 index over L*512*384
    int l = idx / (512 * 384);
    int rem = idx - l * (512 * 384);
    int p = rem / 384, col = (rem - p * 384) * 4;
    const float *s0;
    int srcN;
    if (col < 1024)      { s0 = wq + ((size_t)(l * 1024 + 2 * p)) * 1024 + col;          srcN = 1024; }
    else if (col < 1280) { s0 = wk + ((size_t)(l * 1024 + 2 * p)) * 256 + (col - 1024);  srcN = 256; }
    else                 { s0 = wv + ((size_t)(l * 1024 + 2 * p)) * 256 + (col - 1280);  srcN = 256; }
    float4 a = *(const float4*)s0;
    float4 b = *(const float4*)(s0 + srcN);
    uint4 h, l4;
    split_pair(a.x, b.x, h.x, l4.x);
    split_pair(a.y, b.y, h.y, l4.y);
    split_pair(a.z, b.z, h.z, l4.z);
    split_pair(a.w, b.w, h.w, l4.w);
    *(uint4*)(dh + (size_t)idx * 4) = h;
    *(uint4*)(dl + (size_t)idx * 4) = l4;
}

__global__ void prepack_gu_kernel(const float* __restrict__ wg,
                                  const float* __restrict__ wu,
                                  uint32_t* __restrict__ dh, uint32_t* __restrict__ dl) {
    int idx = blockIdx.x * 256 + threadIdx.x;       // uint4 index over L*512*1408
    int l = idx / (512 * 1408);
    int rem = idx - l * (512 * 1408);
    int p = rem / 1408, col = (rem - p * 1408) * 4;
    const float* s0 = (col < 2816)
        ? wg + ((size_t)(l * 1024 + 2 * p)) * 2816 + col
        : wu + ((size_t)(l * 1024 + 2 * p)) * 2816 + (col - 2816);
    float4 a = *(const float4*)s0;
    float4 b = *(const float4*)(s0 + 2816);
    uint4 h, l4;
    split_pair(a.x, b.x, h.x, l4.x);
    split_pair(a.y, b.y, h.y, l4.y);
    split_pair(a.z, b.z, h.z, l4.z);
    split_pair(a.w, b.w, h.w, l4.w);
    *(uint4*)(dh + (size_t)idx * 4) = h;
    *(uint4*)(dl + (size_t)idx * 4) = l4;
}

__global__ void fuse_bias_kernel(const float* __restrict__ bq,
                                 const float* __restrict__ bk,
                                 const float* __restrict__ bv,
                                 float* __restrict__ dst) {
    int i = blockIdx.x * 256 + threadIdx.x;
    int l = i / NQKV, j = i - l * NQKV;
    float v = (j < 1024) ? bq[l * 1024 + j]
            : (j < 1280) ? bk[l * 256 + j - 1024]
                         : bv[l * 256 + j - 1280];
    dst[i] = v;
}

// ---------------- activation pack ----------------
__global__ void pack_act_kernel(const float* __restrict__ src,
                                uint32_t* __restrict__ dh, uint32_t* __restrict__ dl) {
    int i = blockIdx.x * 256 + threadIdx.x;
    float4 v = ((const float4*)src)[i];
    uint32_t h0, l0, h1, l1;
    split_pair(v.x, v.y, h0, l0);
    split_pair(v.z, v.w, h1, l1);
    *(uint2*)&dh[(size_t)i * 2] = make_uint2(h0, h1);
    *(uint2*)&dl[(size_t)i * 2] = make_uint2(l0, l1);
}

// ---------------- embed / pool / router / select / scatter ----------------
__global__ void embed_kernel(const int* __restrict__ ids,
                             const float* __restrict__ emb,
                             float* __restrict__ hidden) {
    int row = blockIdx.x;
    int id  = ids[row];
    const float4* src = (const float4*)(emb + (size_t)id * DIM);
    float4* dst = (float4*)(hidden + (size_t)row * DIM);
    dst[threadIdx.x] = src[threadIdx.x];
}

__global__ void pool_kernel(const float* __restrict__ hidden,
                            float* __restrict__ pooled) {
    int b = blockIdx.x >> 8, n = blockIdx.x & 255;
    const float* base = hidden + ((size_t)b * SEQ + n * SEGLEN) * DIM + threadIdx.x * 4;
    float4 acc = make_float4(0.f, 0.f, 0.f, 0.f);
#pragma unroll
    for (int t = 0; t < SEGLEN; t++) {
        float4 v = *(const float4*)(base + (size_t)t * DIM);
        acc.x += v.x; acc.y += v.y; acc.z += v.z; acc.w += v.w;
    }
    const float s = 1.f / SEGLEN;
    acc.x *= s; acc.y *= s; acc.z *= s; acc.w *= s;
    *(float4*)(pooled + ((size_t)b * NSEG + n) * DIM + threadIdx.x * 4) = acc;
}

__global__ void router_kernel(const float* __restrict__ pooled,
                              const float* __restrict__ rk,
                              const float* __restrict__ rq,
                              float* __restrict__ scores) {
    int n = blockIdx.x, b = blockIdx.y;
    const float* p = pooled + ((size_t)b * NSEG + n) * DIM;
    __shared__ float part[128];
    int tid = threadIdx.x;
    int r = tid & 15, g = tid >> 4;
    float sum = 0.f;
    int d0 = g * 128;
    for (int d = d0; d < d0 + 128; d++) sum += p[d] * rk[d * RANKR + r];
    part[tid] = sum;
    __syncthreads();
    if (tid < RANKR) {
        float key = 0.f;
        for (int gg = 0; gg < 8; gg++) key += part[gg * 16 + tid];
        part[tid] = key;
    }
    __syncthreads();
    if (tid == 0) {
        float best = -1e30f;
        for (int qq = 0; qq < NQRY; qq++) {
            float dv = 0.f;
            for (int rr = 0; rr < RANKR; rr++) dv += rq[qq * RANKR + rr] * part[rr];
            best = fmaxf(best, dv);
        }
        scores[b * NSEG + n] = best;
    }
}

__global__ void select_kernel(const float* __restrict__ scores,
                              int* __restrict__ tok) {
    int b = blockIdx.x;
    __shared__ float s[NSEG];
    __shared__ int pf[NSEG];
    int i = threadIdx.x;
    float mine = scores[b * NSEG + i];
    s[i] = mine;
    __syncthreads();
    int rank = 0;
    for (int j = 0; j < NSEG; j++) {
        float o = s[j];
        rank += (o > mine) || (o == mine && j < i);
    }
    int sel = (rank < KSEG) ? 1 : 0;
    pf[i] = sel;
    __syncthreads();
    for (int off = 1; off < NSEG; off <<= 1) {
        int add = (i >= off) ? pf[i - off] : 0;
        __syncthreads();
        pf[i] += add;
        __syncthreads();
    }
    if (sel) {
        int p = pf[i] - 1;
        int* dst = tok + b * KTOK + p * SEGLEN;
        int base = i * SEGLEN;
#pragma unroll
        for (int t = 0; t < SEGLEN; t++) dst[t] = base + t;
    }
}

__global__ void scatter_kernel(const float* __restrict__ x,
                               const int* __restrict__ tok,
                               float* __restrict__ hidden) {
    int row = blockIdx.x;
    int b = row / KTOK;
    int tk = tok[row];
    const float4* src = (const float4*)(x + (size_t)row * DIM);
    float4* dst = (float4*)(hidden + ((size_t)b * SEQ + tk) * DIM);
    dst[threadIdx.x] = src[threadIdx.x];
}

// ---------------- RMSNorm ----------------
__device__ __forceinline__ void rms_body(float4 v, const float* w, int row, int t,
                                         uint32_t* oh, uint32_t* ol) {
    float ss = v.x * v.x + v.y * v.y + v.z * v.z + v.w * v.w;
#pragma unroll
    for (int d = 16; d >= 1; d >>= 1) ss += __shfl_xor_sync(0xffffffffu, ss, d);
    __shared__ float ws[8];
    __shared__ float tot;
    if ((t & 31) == 0) ws[t >> 5] = ss;
    __syncthreads();
    if (t == 0) {
        float a = 0.f;
        for (int wgi = 0; wgi < 8; wgi++) a += ws[wgi];
        tot = a;
    }
    __syncthreads();
    float inv = rsqrtf(tot * (1.f / DIM) + 1e-6f);
    float4 wv = ((const float4*)w)[t];
    float o0 = v.x * inv * wv.x, o1 = v.y * inv * wv.y;
    float o2 = v.z * inv * wv.z, o3 = v.w * inv * wv.w;
    uint32_t h0, l0, h1, l1;
    split_pair(o0, o1, h0, l0);
    split_pair(o2, o3, h1, l1);
    size_t base = (size_t)row * (DIM / 2) + t * 2;
    *(uint2*)&oh[base] = make_uint2(h0, h1);
    *(uint2*)&ol[base] = make_uint2(l0, l1);
}

__global__ void rmsnorm_kernel(const float* __restrict__ x,
                               const float* __restrict__ w,
                               uint32_t* __restrict__ oh,
                               uint32_t* __restrict__ ol) {
    int row = blockIdx.x, t = threadIdx.x;
    float4 v = ((const float4*)(x + (size_t)row * DIM))[t];
    rms_body(v, w, row, t, oh, ol);
}

__global__ void gather_norm_kernel(const float* __restrict__ hidden,
                                   const int* __restrict__ tok,
                                   const float* __restrict__ w,
                                   float* __restrict__ x,
                                   uint32_t* __restrict__ oh,
                                   uint32_t* __restrict__ ol) {
    int row = blockIdx.x, t = threadIdx.x;
    int b = row / KTOK;
    int tk = tok[row];
    float4 v = ((const float4*)(hidden + ((size_t)b * SEQ + tk) * DIM))[t];
    ((float4*)(x + (size_t)row * DIM))[t] = v;
    rms_body(v, w, row, t, oh, ol);
}

// ---------------- RoPE ----------------
__global__ void rope_kernel(float* __restrict__ qkv, const int* __restrict__ tok) {
    int row = blockIdx.x;
    float pos = (float)tok[row];
    int t = threadIdx.x;
    float* base = qkv + (size_t)row * NQKV;
    for (int pidx = t; pidx < NHEAD * 32; pidx += 256) {
        int hh = pidx >> 5, i = pidx & 31;
        float inv = __powf(10000.f, -(float)(2 * i) / (float)HEADD);
        float ang = pos * inv;
        float sn, cs;
        sincosf(ang, &sn, &cs);
        float* qp = base + hh * HEADD;
        float x1 = qp[i], x2 = qp[i + 32];
        qp[i]      = x1 * cs - x2 * sn;
        qp[i + 32] = x2 * cs + x1 * sn;
    }
    if (t < KVHEAD * 32) {
        int hh = t >> 5, i = t & 31;
        float inv = __powf(10000.f, -(float)(2 * i) / (float)HEADD);
        float ang = pos * inv;
        float sn, cs;
        sincosf(ang, &sn, &cs);
        float* kp = base + 1024 + hh * HEADD;
        float x1 = kp[i], x2 = kp[i + 32];
        kp[i]      = x1 * cs - x2 * sn;
        kp[i + 32] = x2 * cs + x1 * sn;
    }
}

// ---------------- bf16 MMA primitive ----------------
__device__ __forceinline__ void mma_bf16(float c[4], const uint32_t a[4], const uint32_t b[2]) {
    asm volatile(
        "mma.sync.aligned.m16n8k16.row.col.f32.bf16.bf16.f32 "
        "{%0,%1,%2,%3}, {%4,%5,%6,%7}, {%8,%9}, {%0,%1,%2,%3};\n"
        : "+f"(c[0]), "+f"(c[1]), "+f"(c[2]), "+f"(c[3])
        : "r"(a[0]), "r"(a[1]), "r"(a[2]), "r"(a[3]), "r"(b[0]), "r"(b[1]));
}

// ---------------- pair-format split-bf16 (3xMMA) GEMM, cp.async 2-stage ---------
// C[M,N] = A[M,K] @ W[K,N] (+bias)(+residual); A act planes [M][K/2],
// W weight planes [K/2][N]. 128x128 CTA tile, K-tile 32 elems (16 pairs),
// double-buffered cp.async pipeline overlapping fills with MMA.
#define ASU 20
#define BSU 136
#define A_STG (128 * ASU)                 // 2560 u32
#define B_STG (16 * BSU)                  // 2176 u32
#define STG_U32 (2 * A_STG + 2 * B_STG)   // 9472 u32 = 37888 B
#define SM_PGEMM (2 * STG_U32 * 4)        // 75776 B

template <int FLAGS>   // bit0: add bias, bit1: add existing C (residual)
__global__ void __launch_bounds__(256, 2)
pgemm_kernel(const uint32_t* __restrict__ Ahp, const uint32_t* __restrict__ Alp,
             const uint32_t* __restrict__ Whp, const uint32_t* __restrict__ Wlp,
             const float* __restrict__ bias,
             float* __restrict__ C,
             int M, int N, int K2) {        // K2 = K/2 (pairs)
    extern __shared__ uint32_t sgm[];
    uint32_t sb = smem_u32(sgm);
    int tid = threadIdx.x, lane = tid & 31, warp = tid >> 5;
    int warpM = warp & 1, warpN = warp >> 1;
    int m0 = blockIdx.y * 128, n0 = blockIdx.x * 128;
    int gid = lane >> 2, tig = lane & 3;
    int NT = K2 / 16;

    // per-thread fill coordinates (2 uint4 chunks per plane)
    int arow0 = tid >> 2, apc0 = (tid & 3) * 4;
    int arow1 = (tid + 256) >> 2, apc1 = ((tid + 256) & 3) * 4;
    int pr0 = tid >> 5, cg0 = (tid & 31) * 4;
    int pr1 = (tid + 256) >> 5, cg1 = ((tid + 256) & 31) * 4;

    float c[4][4][4];
#pragma unroll
    for (int i = 0; i < 4; i++)
#pragma unroll
        for (int j = 0; j < 4; j++)
#pragma unroll
            for (int f = 0; f < 4; f++) c[i][j][f] = 0.f;

#define ISSUE_TILE(kt, buf) do {                                               \
        uint32_t st = sb + (buf) * (STG_U32 * 4);                              \
        int p0 = (kt) * 16;                                                    \
        size_t a0 = (size_t)(m0 + arow0) * K2 + p0 + apc0;                     \
        uint32_t sa0 = st + (arow0 * ASU + apc0) * 4;                          \
        cpasync16(sa0, &Ahp[a0]);                                              \
        cpasync16(sa0 + A_STG * 4, &Alp[a0]);                                  \
        size_t a1 = (size_t)(m0 + arow1) * K2 + p0 + apc1;                     \
        uint32_t sa1 = st + (arow1 * ASU + apc1) * 4;                          \
        cpasync16(sa1, &Ahp[a1]);                                              \
        cpasync16(sa1 + A_STG * 4, &Alp[a1]);                                  \
        size_t b0 = (size_t)(p0 + pr0) * N + n0 + cg0;                         \
        uint32_t sb0 = st + (2 * A_STG + pr0 * BSU + cg0) * 4;                 \
        cpasync16(sb0, &Whp[b0]);                                              \
        cpasync16(sb0 + B_STG * 4, &Wlp[b0]);                                  \
        size_t b1 = (size_t)(p0 + pr1) * N + n0 + cg1;                         \
        uint32_t sb1 = st + (2 * A_STG + pr1 * BSU + cg1) * 4;                 \
        cpasync16(sb1, &Whp[b1]);                                              \
        cpasync16(sb1 + B_STG * 4, &Wlp[b1]);                                  \
        CP_COMMIT();                                                           \
    } while (0)

    ISSUE_TILE(0, 0);
    if (NT > 1) ISSUE_TILE(1, 1);

    for (int kt = 0; kt < NT; kt++) {
        int buf = kt & 1;
        if (kt + 1 < NT) CP_WAIT1(); else CP_WAIT0();
        __syncthreads();
        uint32_t* sAh = sgm + buf * STG_U32;
        uint32_t* sAl = sAh + A_STG;
        uint32_t* sBh = sAl + A_STG;
        uint32_t* sBl = sBh + B_STG;
#pragma unroll
        for (int kk = 0; kk < 2; kk++) {
            int kp = kk * 8;
            uint32_t bh[4][2], bl[4][2];
#pragma unroll
            for (int nt = 0; nt < 4; nt++) {
                int cb = warpN * 32 + nt * 8 + gid;
                bh[nt][0] = sBh[(kp + tig) * BSU + cb];
                bh[nt][1] = sBh[(kp + tig + 4) * BSU + cb];
                bl[nt][0] = sBl[(kp + tig) * BSU + cb];
                bl[nt][1] = sBl[(kp + tig + 4) * BSU + cb];
            }
#pragma unroll
            for (int mt = 0; mt < 4; mt++) {
                int rb = warpM * 64 + mt * 16 + gid;
                uint32_t ah[4], al[4];
                ah[0] = sAh[rb * ASU + kp + tig];
                ah[1] = sAh[(rb + 8) * ASU + kp + tig];
                ah[2] = sAh[rb * ASU + kp + tig + 4];
                ah[3] = sAh[(rb + 8) * ASU + kp + tig + 4];
                al[0] = sAl[rb * ASU + kp + tig];
                al[1] = sAl[(rb + 8) * ASU + kp + tig];
                al[2] = sAl[rb * ASU + kp + tig + 4];
                al[3] = sAl[(rb + 8) * ASU + kp + tig + 4];
#pragma unroll
                for (int nt = 0; nt < 4; nt++) {
                    mma_bf16(c[mt][nt], ah, bh[nt]);
                    mma_bf16(c[mt][nt], al, bh[nt]);
                    mma_bf16(c[mt][nt], ah, bl[nt]);
                }
            }
        }
        __syncthreads();
        if (kt + 2 < NT) ISSUE_TILE(kt + 2, buf);
    }
#undef ISSUE_TILE
    // ---- epilogue ----
#pragma unroll
    for (int mt = 0; mt < 4; mt++) {
#pragma unroll
        for (int half = 0; half < 2; half++) {
            int row = m0 + warpM * 64 + mt * 16 + gid + half * 8;
            float* Crow = C + (size_t)row * N + n0 + warpN * 32;
#pragma unroll
            for (int nt = 0; nt < 4; nt++) {
                int col = nt * 8 + tig * 2;
                float2 r;
                r.x = c[mt][nt][half * 2 + 0];
                r.y = c[mt][nt][half * 2 + 1];
                if (FLAGS & 1) {
                    float2 bb = *(const float2*)&bias[n0 + warpN * 32 + col];
                    r.x += bb.x; r.y += bb.y;
                }
                if (FLAGS & 2) {
                    float2 cc = *(const float2*)&Crow[col];
                    r.x += cc.x; r.y += cc.y;
                }
                *(float2*)&Crow[col] = r;
            }
        }
    }
}

// ---------------- tensor-core flash attention (split-bf16, causal, GQA) ----------
#define ATSU 36
__global__ void __launch_bounds__(128)
attn_mma_kernel(const float* __restrict__ qkv, float* __restrict__ o) {
    __shared__ uint32_t sm0[64 * ATSU], sm1[64 * ATSU];
    __shared__ uint32_t sm2[64 * ATSU], sm3[64 * ATSU];
    const int T = KTOK;
    int qt = blockIdx.x, h = blockIdx.y, b = blockIdx.z;
    int kh = h >> 2;
    int tid = threadIdx.x, lane = tid & 31, warp = tid >> 5;
    int gid = lane >> 2, tig = lane & 3;

    for (int i = tid; i < 1024; i += 128) {
        int row = i >> 4, c4 = (i & 15) << 2;
        const float* src = &qkv[((size_t)(b * T + qt * 64 + row)) * NQKV + h * HEADD + c4];
        float4 v = *(const float4*)src;
        v.x *= 0.125f; v.y *= 0.125f; v.z *= 0.125f; v.w *= 0.125f;
        uint32_t h0, l0, h1, l1;
        split_pair(v.x, v.y, h0, l0);
        split_pair(v.z, v.w, h1, l1);
        int p = c4 >> 1;
        sm0[row * ATSU + p] = h0; sm0[row * ATSU + p + 1] = h1;
        sm1[row * ATSU + p] = l0; sm1[row * ATSU + p + 1] = l1;
    }
    __syncthreads();
    uint32_t qh[4][4], ql[4][4];
    {
        int r0 = warp * 16 + gid, r1 = r0 + 8;
#pragma unroll
        for (int kc = 0; kc < 4; kc++) {
            int p = kc * 8 + tig;
            qh[kc][0] = sm0[r0 * ATSU + p];
            qh[kc][1] = sm0[r1 * ATSU + p];
            qh[kc][2] = sm0[r0 * ATSU + p + 4];
            qh[kc][3] = sm0[r1 * ATSU + p + 4];
            ql[kc][0] = sm1[r0 * ATSU + p];
            ql[kc][1] = sm1[r1 * ATSU + p];
            ql[kc][2] = sm1[r0 * ATSU + p + 4];
            ql[kc][3] = sm1[r1 * ATSU + p + 4];
        }
    }

    float accO[8][4];
#pragma unroll
    for (int nt = 0; nt < 8; nt++)
#pragma unroll
        for (int f = 0; f < 4; f++) accO[nt][f] = 0.f;
    float m0r = -1e30f, m1r = -1e30f, l0r = 0.f, l1r = 0.f;

    for (int kt = 0; kt <= qt; kt++) {
        __syncthreads();
        for (int i = tid; i < 1024; i += 128) {
            int row = i >> 4, c4 = (i & 15) << 2;
            const float* src = &qkv[((size_t)(b * T + kt * 64 + row)) * NQKV + 1024 + kh * HEADD + c4];
            float4 v = *(const float4*)src;
            uint32_t h0, l0, h1, l1;
            split_pair(v.x, v.y, h0, l0);
            split_pair(v.z, v.w, h1, l1);
            int p = c4 >> 1;
            sm0[row * ATSU + p] = h0; sm0[row * ATSU + p + 1] = h1;
            sm1[row * ATSU + p] = l0; sm1[row * ATSU + p + 1] = l1;
        }
        for (int i = tid; i < 512; i += 128) {
            int pt = i & 31, d4 = (i >> 5) << 2;
            const float* s0 = &qkv[((size_t)(b * T + kt * 64 + 2 * pt)) * NQKV + 1280 + kh * HEADD + d4];
            float4 a = *(const float4*)s0;
            float4 c = *(const float4*)(s0 + NQKV);
            uint32_t hh_, ll_;
            split_pair(a.x, c.x, hh_, ll_); sm2[(d4 + 0) * ATSU + pt] = hh_; sm3[(d4 + 0) * ATSU + pt] = ll_;
            split_pair(a.y, c.y, hh_, ll_); sm2[(d4 + 1) * ATSU + pt] = hh_; sm3[(d4 + 1) * ATSU + pt] = ll_;
            split_pair(a.z, c.z, hh_, ll_); sm2[(d4 + 2) * ATSU + pt] = hh_; sm3[(d4 + 2) * ATSU + pt] = ll_;
            split_pair(a.w, c.w, hh_, ll_); sm2[(d4 + 3) * ATSU + pt] = hh_; sm3[(d4 + 3) * ATSU + pt] = ll_;
        }
        __syncthreads();

        float s[8][4];
#pragma unroll
        for (int nt = 0; nt < 8; nt++)
#pragma unroll
            for (int f = 0; f < 4; f++) s[nt][f] = 0.f;
#pragma unroll
        for (int kc = 0; kc < 4; kc++) {
#pragma unroll
            for (int nt = 0; nt < 8; nt++) {
                int tok = nt * 8 + gid;
                uint32_t bh[2], bl[2];
                bh[0] = sm0[tok * ATSU + kc * 8 + tig];
                bh[1] = sm0[tok * ATSU + kc * 8 + tig + 4];
                bl[0] = sm1[tok * ATSU + kc * 8 + tig];
                bl[1] = sm1[tok * ATSU + kc * 8 + tig + 4];
                mma_bf16(s[nt], qh[kc], bh);
                mma_bf16(s[nt], ql[kc], bh);
                mma_bf16(s[nt], qh[kc], bl);
            }
        }
        if (kt == qt) {
            int r0 = warp * 16 + gid, r1 = r0 + 8;
#pragma unroll
            for (int nt = 0; nt < 8; nt++) {
                int c0 = nt * 8 + 2 * tig, c1 = c0 + 1;
                if (c0 > r0) s[nt][0] = -1e30f;
                if (c1 > r0) s[nt][1] = -1e30f;
                if (c0 > r1) s[nt][2] = -1e30f;
                if (c1 > r1) s[nt][3] = -1e30f;
            }
        }
        float mx0 = -1e30f, mx1 = -1e30f;
#pragma unroll
        for (int nt = 0; nt < 8; nt++) {
            mx0 = fmaxf(mx0, fmaxf(s[nt][0], s[nt][1]));
            mx1 = fmaxf(mx1, fmaxf(s[nt][2], s[nt][3]));
        }
        mx0 = fmaxf(mx0, __shfl_xor_sync(0xffffffffu, mx0, 1));
        mx0 = fmaxf(mx0, __shfl_xor_sync(0xffffffffu, mx0, 2));
        mx1 = fmaxf(mx1, __shfl_xor_sync(0xffffffffu, mx1, 1));
        mx1 = fmaxf(mx1, __shfl_xor_sync(0xffffffffu, mx1, 2));
        float mn0 = fmaxf(m0r, mx0), mn1 = fmaxf(m1r, mx1);
        float cor0 = __expf(m0r - mn0), cor1 = __expf(m1r - mn1);
        float ps0 = 0.f, ps1 = 0.f;
#pragma unroll
        for (int nt = 0; nt < 8; nt++) {
            s[nt][0] = __expf(s[nt][0] - mn0);
            s[nt][1] = __expf(s[nt][1] - mn0);
            s[nt][2] = __expf(s[nt][2] - mn1);
            s[nt][3] = __expf(s[nt][3] - mn1);
            ps0 += s[nt][0] + s[nt][1];
            ps1 += s[nt][2] + s[nt][3];
        }
        ps0 += __shfl_xor_sync(0xffffffffu, ps0, 1);
        ps0 += __shfl_xor_sync(0xffffffffu, ps0, 2);
        ps1 += __shfl_xor_sync(0xffffffffu, ps1, 1);
        ps1 += __shfl_xor_sync(0xffffffffu, ps1, 2);
        l0r = l0r * cor0 + ps0;  m0r = mn0;
        l1r = l1r * cor1 + ps1;  m1r = mn1;
#pragma unroll
        for (int nt = 0; nt < 8; nt++) {
            accO[nt][0] *= cor0; accO[nt][1] *= cor0;
            accO[nt][2] *= cor1; accO[nt][3] *= cor1;
        }
#pragma unroll
        for (int kc = 0; kc < 4; kc++) {
            uint32_t ph[4], pl[4];
            split_pair(s[2 * kc][0],     s[2 * kc][1],     ph[0], pl[0]);
            split_pair(s[2 * kc][2],     s[2 * kc][3],     ph[1], pl[1]);
            split_pair(s[2 * kc + 1][0], s[2 * kc + 1][1], ph[2], pl[2]);
            split_pair(s[2 * kc + 1][2], s[2 * kc + 1][3], ph[3], pl[3]);
#pragma unroll
            for (int nt = 0; nt < 8; nt++) {
                int d = nt * 8 + gid;
                uint32_t vh[2], vl[2];
                vh[0] = sm2[d * ATSU + kc * 8 + tig];
                vh[1] = sm2[d * ATSU + kc * 8 + tig + 4];
                vl[0] = sm3[d * ATSU + kc * 8 + tig];
                vl[1] = sm3[d * ATSU + kc * 8 + tig + 4];
                mma_bf16(accO[nt], ph, vh);
                mma_bf16(accO[nt], pl, vh);
                mma_bf16(accO[nt], ph, vl);
            }
        }
    }
    float i0 = 1.f / l0r, i1 = 1.f / l1r;
    int r0 = qt * 64 + warp * 16 + gid;
#pragma unroll
    for (int nt = 0; nt < 8; nt++) {
        int d = h * HEADD + nt * 8 + 2 * tig;
        float2 w0 = make_float2(accO[nt][0] * i0, accO[nt][1] * i0);
        *(float2*)&o[((size_t)(b * T + r0)) * DIM + d] = w0;
        float2 w1 = make_float2(accO[nt][2] * i1, accO[nt][3] * i1);
        *(float2*)&o[((size_t)(b * T + r0 + 8)) * DIM + d] = w1;
    }
}

// ---------------- silu(gate)*up from fused gu -> pair buffers ----------------
__global__ void silu_mul_kernel(const float* __restrict__ gu,
                                uint32_t* __restrict__ dh, uint32_t* __restrict__ dl) {
    int idx = blockIdx.x * 256 + threadIdx.x;
    int row = idx / (FFD / 4), c4 = (idx - row * (FFD / 4)) * 4;
    const float* base = gu + (size_t)row * NGU;
    float4 x = *(const float4*)(base + c4);
    float4 y = *(const float4*)(base + FFD + c4);
    float o0 = x.x / (1.f + __expf(-x.x)) * y.x;
    float o1 = x.y / (1.f + __expf(-x.y)) * y.y;
    float o2 = x.z / (1.f + __expf(-x.z)) * y.z;
    float o3 = x.w / (1.f + __expf(-x.w)) * y.w;
    uint32_t h0, l0, h1, l1;
    split_pair(o0, o1, h0, l0);
    split_pair(o2, o3, h1, l1);
    size_t base2 = (size_t)row * (FFD / 2) + (c4 >> 1);
    *(uint2*)&dh[base2] = make_uint2(h0, h1);
    *(uint2*)&dl[base2] = make_uint2(l0, l1);
}

// ---------------- launch ----------------
extern "C" void kernel_launch(void* const* d_in, const int* in_sizes, int n_in,
                              void* d_out, int out_size) {
    const int*   ids      = (const int*)d_in[0];
    const float* emb      = (const float*)d_in[1];
    const float* router_k = (const float*)d_in[2];
    const float* router_q = (const float*)d_in[3];
    const float* ln1      = (const float*)d_in[4];
    const float* ln2      = (const float*)d_in[5];
    const float* wq       = (const float*)d_in[6];
    const float* bq       = (const float*)d_in[7];
    const float* wk       = (const float*)d_in[8];
    const float* bk       = (const float*)d_in[9];
    const float* wv       = (const float*)d_in[10];
    const float* bv       = (const float*)d_in[11];
    const float* wo       = (const float*)d_in[12];
    const float* wg       = (const float*)d_in[13];
    const float* wu       = (const float*)d_in[14];
    const float* wd       = (const float*)d_in[15];
    float* hidden = (float*)d_out;

    float *x, *qkv, *o, *gu, *pooled, *scores, *bqkv;
    int* tok;
    uint32_t *wqkvh, *wqkvl, *woh, *wol, *wguh, *wgul, *wdh, *wdl;
    uint32_t *hh, *hl, *oh, *ol, *gh, *gl;
    cudaGetSymbolAddress((void**)&x, g_x);
    cudaGetSymbolAddress((void**)&qkv, g_qkv);
    cudaGetSymbolAddress((void**)&o, g_o);
    cudaGetSymbolAddress((void**)&gu, g_gu);
    cudaGetSymbolAddress((void**)&pooled, g_pool);
    cudaGetSymbolAddress((void**)&scores, g_scores);
    cudaGetSymbolAddress((void**)&tok, g_tok);
    cudaGetSymbolAddress((void**)&bqkv, g_bqkv);
    cudaGetSymbolAddress((void**)&wqkvh, g_wqkvh); cudaGetSymbolAddress((void**)&wqkvl, g_wqkvl);
    cudaGetSymbolAddress((void**)&woh, g_woh);     cudaGetSymbolAddress((void**)&wol, g_wol);
    cudaGetSymbolAddress((void**)&wguh, g_wguh);   cudaGetSymbolAddress((void**)&wgul, g_wgul);
    cudaGetSymbolAddress((void**)&wdh, g_wdh);     cudaGetSymbolAddress((void**)&wdl, g_wdl);
    cudaGetSymbolAddress((void**)&hh, g_hh);       cudaGetSymbolAddress((void**)&hl, g_hl);
    cudaGetSymbolAddress((void**)&oh, g_oh);       cudaGetSymbolAddress((void**)&ol, g_ol);
    cudaGetSymbolAddress((void**)&gh, g_gh);       cudaGetSymbolAddress((void**)&gl, g_gl);

    cudaFuncSetAttribute(pgemm_kernel<0>, cudaFuncAttributeMaxDynamicSharedMemorySize, SM_PGEMM);
    cudaFuncSetAttribute(pgemm_kernel<1>, cudaFuncAttributeMaxDynamicSharedMemorySize, SM_PGEMM);
    cudaFuncSetAttribute(pgemm_kernel<2>, cudaFuncAttributeMaxDynamicSharedMemorySize, SM_PGEMM);

    embed_kernel<<<BATCH * SEQ, 256>>>(ids, emb, hidden);

    // ---- weight prepacks ----
    prepack_gu_kernel<<<NLAYER * 512 * 1408 / 256, 256>>>(wg, wu, wguh, wgul);
    prepack_qkv_kernel<<<NLAYER * 512 * 384 / 256, 256>>>(wq, wk, wv, wqkvh, wqkvl);
    prepack_kernel<<<NLAYER * 512 * 1024 / 1024, 256>>>(wo, woh, wol, 256, 1024);
    prepack_kernel<<<NLAYER * 1408 * 1024 / 1024, 256>>>(wd, wdh, wdl, 256, 1024);
    fuse_bias_kernel<<<NLAYER * NQKV / 256, 256>>>(bq, bk, bv, bqkv);

    for (int blk = 0; blk < NBLK; blk++) {
        int li0 = blk * BPL;
        pool_kernel<<<BATCH * NSEG, 256>>>(hidden, pooled);
        router_kernel<<<dim3(NSEG, BATCH), 128>>>(
            pooled, router_k + (size_t)blk * DIM * RANKR,
            router_q + (size_t)blk * NQRY * RANKR, scores);
        select_kernel<<<BATCH, 256>>>(scores, tok);
        gather_norm_kernel<<<BT, 256>>>(hidden, tok, ln1 + (size_t)li0 * DIM, x, hh, hl);

        for (int j = 0; j < BPL; j++) {
            int li = li0 + j;
            size_t oqkv = (size_t)li * 512 * NQKV;
            size_t oo   = (size_t)li * 512 * 1024;
            size_t ogu  = (size_t)li * 512 * NGU;
            size_t od   = (size_t)li * 1408 * 1024;

            if (j > 0)
                rmsnorm_kernel<<<BT, 256>>>(x, ln1 + (size_t)li * DIM, hh, hl);
            pgemm_kernel<1><<<dim3(NQKV / 128, BT / 128), 256, SM_PGEMM>>>(
                hh, hl, wqkvh + oqkv, wqkvl + oqkv, bqkv + (size_t)li * NQKV,
                qkv, BT, NQKV, 512);
            rope_kernel<<<BT, 256>>>(qkv, tok);
            attn_mma_kernel<<<dim3(KTOK / 64, NHEAD, BATCH), 128>>>(qkv, o);
            pack_act_kernel<<<BT * DIM / 1024, 256>>>(o, oh, ol);
            pgemm_kernel<2><<<dim3(8, BT / 128), 256, SM_PGEMM>>>(
                oh, ol, woh + oo, wol + oo, nullptr, x, BT, 1024, 512);
            rmsnorm_kernel<<<BT, 256>>>(x, ln2 + (size_t)li * DIM, hh, hl);
            pgemm_kernel<0><<<dim3(NGU / 128, BT / 128), 256, SM_PGEMM>>>(
                hh, hl, wguh + ogu, wgul + ogu, nullptr, gu, BT, NGU, 512);
            silu_mul_kernel<<<BT * (FFD / 4) / 256, 256>>>(gu, gh, gl);
            pgemm_kernel<2><<<dim3(8, BT / 128), 256, SM_PGEMM>>>(
                gh, gl, wdh + od, wdl + od, nullptr, x, BT, 1024, 1408);
        }
        scatter_kernel<<<BT, 256>>>(x, tok, hidden);
    }
}

// round 14
// speedup vs baseline: 3.2875x; 1.0139x over previous
#include <cuda_runtime.h>
#include <cuda_bf16.h>
#include <math.h>
#include <stdint.h>

// ---------------- problem constants ----------------
#define BATCH 2
#define SEQ   4096
#define DIM   1024
#define NHEAD 16
#define KVHEAD 4
#define HEADD 64
#define FFD   2816
#define NSEG  256
#define SEGLEN 16
#define KSEG  76
#define KTOK  (KSEG*SEGLEN)      // 1216
#define BT    (BATCH*KTOK)       // 2432 = 19*128
#define NLAYER 12
#define NBLK  2
#define BPL   6
#define RANKR 16
#define NQRY  8
#define NQKV  1536
#define NGU   5632
#define TPH   (KTOK/2)           // 608 token pairs per batch

// ---------------- scratch (device globals; no allocs allowed) ----------------
__device__ float g_x   [BT*DIM];
__device__ float g_qkv [BT*NQKV];
__device__ float g_pool[BATCH*NSEG*DIM];
__device__ float g_scores[BATCH*NSEG];
__device__ int   g_tok [BATCH*KTOK];
__device__ float g_bqkv[NLAYER*NQKV];

// pre-packed bf16 hi/lo pair weights: [L][K/2][N] u32 (u32 = bf16 pair along K)
__device__ uint32_t g_wqkvh[NLAYER*512*NQKV], g_wqkvl[NLAYER*512*NQKV];
__device__ uint32_t g_woh  [NLAYER*512*1024], g_wol  [NLAYER*512*1024];
__device__ uint32_t g_wguh [NLAYER*512*NGU],  g_wgul [NLAYER*512*NGU];   // gate/up col-interleaved (groups of 4)
__device__ uint32_t g_wdh  [NLAYER*1408*1024],g_wdl  [NLAYER*1408*1024];
// activation pair buffers [M][K/2]
__device__ uint32_t g_hh[BT*DIM/2],  g_hl[BT*DIM/2];
__device__ uint32_t g_oh[BT*DIM/2],  g_ol[BT*DIM/2];
__device__ uint32_t g_gh[BT*FFD/2],  g_gl[BT*FFD/2];
// attention pre-split planes
__device__ uint32_t g_qhp[BT*512],  g_qlp[BT*512];     // roped+scaled Q pairs
__device__ uint32_t g_khp[BT*128],  g_klp[BT*128];     // roped K pairs
__device__ uint32_t g_vth[BATCH*KVHEAD*HEADD*TPH], g_vtl[BATCH*KVHEAD*HEADD*TPH]; // V^T [d][tokpair]

// ---------------- split helper ----------------
__device__ __forceinline__ void split_pair(float x0, float x1, uint32_t& hp, uint32_t& lp) {
    uint32_t h;
    asm("cvt.rn.bf16x2.f32 %0, %1, %2;" : "=r"(h) : "f"(x1), "f"(x0));
    float h0 = __uint_as_float(h << 16);
    float h1 = __uint_as_float(h & 0xFFFF0000u);
    float l0 = x0 - h0, l1 = x1 - h1;
    uint32_t l;
    asm("cvt.rn.bf16x2.f32 %0, %1, %2;" : "=r"(l) : "f"(l1), "f"(l0));
    hp = h; lp = l;
}
__device__ __forceinline__ uint32_t smem_u32(const void* p) {
    uint32_t a;
    asm("{ .reg .u64 t; cvta.to.shared.u64 t, %1; cvt.u32.u64 %0, t; }" : "=r"(a) : "l"(p));
    return a;
}
__device__ __forceinline__ void cpasync16(uint32_t dst, const void* src) {
    asm volatile("cp.async.cg.shared.global [%0], [%1], 16;" :: "r"(dst), "l"(src));
}
#define CP_COMMIT() asm volatile("cp.async.commit_group;" ::: "memory")
#define CP_WAIT1()  asm volatile("cp.async.wait_group 1;" ::: "memory")
#define CP_WAIT0()  asm volatile("cp.async.wait_group 0;" ::: "memory")

// ---------------- weight prepacks ----------------
__global__ void prepack_kernel(const float* __restrict__ src,
                               uint32_t* __restrict__ dh, uint32_t* __restrict__ dl,
                               int n4row, int N) {
    int idx = blockIdx.x * 256 + threadIdx.x;
    int p = idx / n4row, c = (idx - p * n4row) * 4;
    const float* r0 = src + (size_t)(2 * p) * N + c;
    float4 a = *(const float4*)r0;
    float4 b = *(const float4*)(r0 + N);
    uint4 h, l;
    split_pair(a.x, b.x, h.x, l.x);
    split_pair(a.y, b.y, h.y, l.y);
    split_pair(a.z, b.z, h.z, l.z);
    split_pair(a.w, b.w, h.w, l.w);
    *(uint4*)(dh + (size_t)idx * 4) = h;
    *(uint4*)(dl + (size_t)idx * 4) = l;
}

__global__ void prepack_qkv_kernel(const float* __restrict__ wq,
                                   const float* __restrict__ wk,
                                   const float* __restrict__ wv,
                                   uint32_t* __restrict__ dh, uint32_t* __restrict__ dl) {
    int idx = blockIdx.x * 256 + threadIdx.x;       // uint4 index over L*512*384
    int l = idx / (512 * 384);
    int rem = idx - l * (512 * 384);
    int p = rem / 384, col = (rem - p * 384) * 4;
    const float *s0;
    int srcN;
    if (col < 1024)      { s0 = wq + ((size_t)(l * 1024 + 2 * p)) * 1024 + col;          srcN = 1024; }
    else if (col < 1280) { s0 = wk + ((size_t)(l * 1024 + 2 * p)) * 256 + (col - 1024);  srcN = 256; }
    else                 { s0 = wv + ((size_t)(l * 1024 + 2 * p)) * 256 + (col - 1280);  srcN = 256; }
    float4 a = *(const float4*)s0;
    float4 b = *(const float4*)(s0 + srcN);
    uint4 h, l4;
    split_pair(a.x, b.x, h.x, l4.x);
    split_pair(a.y, b.y, h.y, l4.y);
    split_pair(a.z, b.z, h.z, l4.z);
    split_pair(a.w, b.w, h.w, l4.w);
    *(uint4*)(dh + (size_t)idx * 4) = h;
    *(uint4*)(dl + (size_t)idx * 4) = l4;
}

// gate/up interleaved: dst col group q (4 cols) = {gate 2q, gate 2q+1, up 2q, up 2q+1}
__global__ void prepack_gu_kernel(const float* __restrict__ wg,
                                  const float* __restrict__ wu,
                                  uint32_t* __restrict__ dh, uint32_t* __restrict__ dl) {
    int idx = blockIdx.x * 256 + threadIdx.x;       // uint4 index over L*512*1408
    int l = idx / (512 * 1408);
    int rem = idx - l * (512 * 1408);
    int p = rem / 1408, q = rem - p * 1408;         // group index; cols 4q..4q+3
    size_t row0 = (size_t)(l * 1024 + 2 * p);
    const float* g0 = wg + row0 * 2816 + 2 * q;
    const float* u0 = wu + row0 * 2816 + 2 * q;
    float2 ga = *(const float2*)g0;
    float2 gb = *(const float2*)(g0 + 2816);
    float2 ua = *(const float2*)u0;
    float2 ub = *(const float2*)(u0 + 2816);
    uint4 h, l4;
    split_pair(ga.x, gb.x, h.x, l4.x);
    split_pair(ga.y, gb.y, h.y, l4.y);
    split_pair(ua.x, ub.x, h.z, l4.z);
    split_pair(ua.y, ub.y, h.w, l4.w);
    *(uint4*)(dh + (size_t)idx * 4) = h;
    *(uint4*)(dl + (size_t)idx * 4) = l4;
}

__global__ void fuse_bias_kernel(const float* __restrict__ bq,
                                 const float* __restrict__ bk,
                                 const float* __restrict__ bv,
                                 float* __restrict__ dst) {
    int i = blockIdx.x * 256 + threadIdx.x;
    int l = i / NQKV, j = i - l * NQKV;
    float v = (j < 1024) ? bq[l * 1024 + j]
            : (j < 1280) ? bk[l * 256 + j - 1024]
                         : bv[l * 256 + j - 1280];
    dst[i] = v;
}

// ---------------- embed / pool / router / select / scatter ----------------
__global__ void embed_kernel(const int* __restrict__ ids,
                             const float* __restrict__ emb,
                             float* __restrict__ hidden) {
    int row = blockIdx.x;
    int id  = ids[row];
    const float4* src = (const float4*)(emb + (size_t)id * DIM);
    float4* dst = (float4*)(hidden + (size_t)row * DIM);
    dst[threadIdx.x] = src[threadIdx.x];
}

__global__ void pool_kernel(const float* __restrict__ hidden,
                            float* __restrict__ pooled) {
    int b = blockIdx.x >> 8, n = blockIdx.x & 255;
    const float* base = hidden + ((size_t)b * SEQ + n * SEGLEN) * DIM + threadIdx.x * 4;
    float4 acc = make_float4(0.f, 0.f, 0.f, 0.f);
#pragma unroll
    for (int t = 0; t < SEGLEN; t++) {
        float4 v = *(const float4*)(base + (size_t)t * DIM);
        acc.x += v.x; acc.y += v.y; acc.z += v.z; acc.w += v.w;
    }
    const float s = 1.f / SEGLEN;
    acc.x *= s; acc.y *= s; acc.z *= s; acc.w *= s;
    *(float4*)(pooled + ((size_t)b * NSEG + n) * DIM + threadIdx.x * 4) = acc;
}

__global__ void router_kernel(const float* __restrict__ pooled,
                              const float* __restrict__ rk,
                              const float* __restrict__ rq,
                              float* __restrict__ scores) {
    int n = blockIdx.x, b = blockIdx.y;
    const float* p = pooled + ((size_t)b * NSEG + n) * DIM;
    __shared__ float part[128];
    int tid = threadIdx.x;
    int r = tid & 15, g = tid >> 4;
    float sum = 0.f;
    int d0 = g * 128;
    for (int d = d0; d < d0 + 128; d++) sum += p[d] * rk[d * RANKR + r];
    part[tid] = sum;
    __syncthreads();
    if (tid < RANKR) {
        float key = 0.f;
        for (int gg = 0; gg < 8; gg++) key += part[gg * 16 + tid];
        part[tid] = key;
    }
    __syncthreads();
    if (tid == 0) {
        float best = -1e30f;
        for (int qq = 0; qq < NQRY; qq++) {
            float dv = 0.f;
            for (int rr = 0; rr < RANKR; rr++) dv += rq[qq * RANKR + rr] * part[rr];
            best = fmaxf(best, dv);
        }
        scores[b * NSEG + n] = best;
    }
}

__global__ void select_kernel(const float* __restrict__ scores,
                              int* __restrict__ tok) {
    int b = blockIdx.x;
    __shared__ float s[NSEG];
    __shared__ int pf[NSEG];
    int i = threadIdx.x;
    float mine = scores[b * NSEG + i];
    s[i] = mine;
    __syncthreads();
    int rank = 0;
    for (int j = 0; j < NSEG; j++) {
        float o = s[j];
        rank += (o > mine) || (o == mine && j < i);
    }
    int sel = (rank < KSEG) ? 1 : 0;
    pf[i] = sel;
    __syncthreads();
    for (int off = 1; off < NSEG; off <<= 1) {
        int add = (i >= off) ? pf[i - off] : 0;
        __syncthreads();
        pf[i] += add;
        __syncthreads();
    }
    if (sel) {
        int p = pf[i] - 1;
        int* dst = tok + b * KTOK + p * SEGLEN;
        int base = i * SEGLEN;
#pragma unroll
        for (int t = 0; t < SEGLEN; t++) dst[t] = base + t;
    }
}

__global__ void scatter_kernel(const float* __restrict__ x,
                               const int* __restrict__ tok,
                               float* __restrict__ hidden) {
    int row = blockIdx.x;
    int b = row / KTOK;
    int tk = tok[row];
    const float4* src = (const float4*)(x + (size_t)row * DIM);
    float4* dst = (float4*)(hidden + ((size_t)b * SEQ + tk) * DIM);
    dst[threadIdx.x] = src[threadIdx.x];
}

// ---------------- RMSNorm ----------------
__device__ __forceinline__ void rms_body(float4 v, const float* w, int row, int t,
                                         uint32_t* oh, uint32_t* ol) {
    float ss = v.x * v.x + v.y * v.y + v.z * v.z + v.w * v.w;
#pragma unroll
    for (int d = 16; d >= 1; d >>= 1) ss += __shfl_xor_sync(0xffffffffu, ss, d);
    __shared__ float ws[8];
    __shared__ float tot;
    if ((t & 31) == 0) ws[t >> 5] = ss;
    __syncthreads();
    if (t == 0) {
        float a = 0.f;
        for (int wgi = 0; wgi < 8; wgi++) a += ws[wgi];
        tot = a;
    }
    __syncthreads();
    float inv = rsqrtf(tot * (1.f / DIM) + 1e-6f);
    float4 wv = ((const float4*)w)[t];
    float o0 = v.x * inv * wv.x, o1 = v.y * inv * wv.y;
    float o2 = v.z * inv * wv.z, o3 = v.w * inv * wv.w;
    uint32_t h0, l0, h1, l1;
    split_pair(o0, o1, h0, l0);
    split_pair(o2, o3, h1, l1);
    size_t base = (size_t)row * (DIM / 2) + t * 2;
    *(uint2*)&oh[base] = make_uint2(h0, h1);
    *(uint2*)&ol[base] = make_uint2(l0, l1);
}

__global__ void rmsnorm_kernel(const float* __restrict__ x,
                               const float* __restrict__ w,
                               uint32_t* __restrict__ oh,
                               uint32_t* __restrict__ ol) {
    int row = blockIdx.x, t = threadIdx.x;
    float4 v = ((const float4*)(x + (size_t)row * DIM))[t];
    rms_body(v, w, row, t, oh, ol);
}

__global__ void gather_norm_kernel(const float* __restrict__ hidden,
                                   const int* __restrict__ tok,
                                   const float* __restrict__ w,
                                   float* __restrict__ x,
                                   uint32_t* __restrict__ oh,
                                   uint32_t* __restrict__ ol) {
    int row = blockIdx.x, t = threadIdx.x;
    int b = row / KTOK;
    int tk = tok[row];
    float4 v = ((const float4*)(hidden + ((size_t)b * SEQ + tk) * DIM))[t];
    ((float4*)(x + (size_t)row * DIM))[t] = v;
    rms_body(v, w, row, t, oh, ol);
}

// ---------------- prep_attn: RoPE + pre-split Q/K/V into pair planes ----------------
// grid BT/2 blocks (one token pair), 128 threads
__global__ void __launch_bounds__(128)
prep_attn_kernel(const float* __restrict__ qkv, const int* __restrict__ tok,
                 uint32_t* __restrict__ qh, uint32_t* __restrict__ ql,
                 uint32_t* __restrict__ khp, uint32_t* __restrict__ klp,
                 uint32_t* __restrict__ vth, uint32_t* __restrict__ vtl) {
    __shared__ float q[2][1024], kk[2][256], vv[2][256];
    int p = blockIdx.x;
    int b = p / TPH;
    int lp = p - b * TPH;
    int r0 = b * KTOK + lp * 2;
    int tid = threadIdx.x;
    // load 2 rows of qkv
    for (int i = tid; i < 768; i += 128) {
        int row = i / 384, c = (i % 384) * 4;
        float4 v = *(const float4*)&qkv[(size_t)(r0 + row) * NQKV + c];
        if (c < 1024)      *(float4*)&q[row][c] = v;
        else if (c < 1280) *(float4*)&kk[row][c - 1024] = v;
        else               *(float4*)&vv[row][c - 1280] = v;
    }
    __syncthreads();
    float pos0 = (float)tok[r0], pos1 = (float)tok[r0 + 1];
    // rope q (1024 tasks) + k (256 tasks)
    for (int t = tid; t < 1280; t += 128) {
        if (t < 1024) {
            int row = t >> 9, rr = t & 511, hh = rr >> 5, i = rr & 31;
            float inv = __powf(10000.f, -(float)(2 * i) / 64.f);
            float ang = (row ? pos1 : pos0) * inv;
            float sn, cs; sincosf(ang, &sn, &cs);
            float* qp = &q[row][hh * 64];
            float x1 = qp[i], x2 = qp[i + 32];
            qp[i]      = x1 * cs - x2 * sn;
            qp[i + 32] = x2 * cs + x1 * sn;
        } else {
            int t2 = t - 1024;
            int row = t2 >> 7, rr = t2 & 127, hh = rr >> 5, i = rr & 31;
            float inv = __powf(10000.f, -(float)(2 * i) / 64.f);
            float ang = (row ? pos1 : pos0) * inv;
            float sn, cs; sincosf(ang, &sn, &cs);
            float* kp = &kk[row][hh * 64];
            float x1 = kp[i], x2 = kp[i + 32];
            kp[i]      = x1 * cs - x2 * sn;
            kp[i + 32] = x2 * cs + x1 * sn;
        }
    }
    __syncthreads();
    // q split + scale
    for (int t = tid; t < 1024; t += 128) {
        int row = t >> 9, j = t & 511;
        uint32_t h, l;
        split_pair(q[row][2 * j] * 0.125f, q[row][2 * j + 1] * 0.125f, h, l);
        size_t o = (size_t)(r0 + row) * 512 + j;
        qh[o] = h; ql[o] = l;
    }
    // k split
    for (int t = tid; t < 256; t += 128) {
        int row = t >> 7, j = t & 127;
        uint32_t h, l;
        split_pair(kk[row][2 * j], kk[row][2 * j + 1], h, l);
        size_t o = (size_t)(r0 + row) * 128 + j;
        khp[o] = h; klp[o] = l;
    }
    // v transposed token pairs
    for (int t = tid; t < 256; t += 128) {
        int kvh = t >> 6, d = t & 63;
        uint32_t h, l;
        split_pair(vv[0][kvh * 64 + d], vv[1][kvh * 64 + d], h, l);
        size_t o = (size_t)((b * KVHEAD + kvh) * HEADD + d) * TPH + lp;
        vth[o] = h; vtl[o] = l;
    }
}

// ---------------- bf16 MMA primitive ----------------
__device__ __forceinline__ void mma_bf16(float c[4], const uint32_t a[4], const uint32_t b[2]) {
    asm volatile(
        "mma.sync.aligned.m16n8k16.row.col.f32.bf16.bf16.f32 "
        "{%0,%1,%2,%3}, {%4,%5,%6,%7}, {%8,%9}, {%0,%1,%2,%3};\n"
        : "+f"(c[0]), "+f"(c[1]), "+f"(c[2]), "+f"(c[3])
        : "r"(a[0]), "r"(a[1]), "r"(a[2]), "r"(a[3]), "r"(b[0]), "r"(b[1]));
}

// ---------------- pair-format split-bf16 (3xMMA) GEMM, cp.async 2-stage ---------
#define ASU 20
#define BSU 136
#define A_STG (128 * ASU)
#define B_STG (16 * BSU)
#define STG_U32 (2 * A_STG + 2 * B_STG)
#define SM_PGEMM (2 * STG_U32 * 4)

// FLAGS: 0 plain, 1 +bias, 2 +residual, 4 silu-pair epilogue (gate/up interleaved)
template <int FLAGS>
__global__ void __launch_bounds__(256, 2)
pgemm_kernel(const uint32_t* __restrict__ Ahp, const uint32_t* __restrict__ Alp,
             const uint32_t* __restrict__ Whp, const uint32_t* __restrict__ Wlp,
             const float* __restrict__ bias,
             float* __restrict__ C,
             uint32_t* __restrict__ Dh, uint32_t* __restrict__ Dl,
             int M, int N, int K2) {
    extern __shared__ uint32_t sgm[];
    uint32_t sb = smem_u32(sgm);
    int tid = threadIdx.x, lane = tid & 31, warp = tid >> 5;
    int warpM = warp & 1, warpN = warp >> 1;
    int m0 = blockIdx.y * 128, n0 = blockIdx.x * 128;
    int gid = lane >> 2, tig = lane & 3;
    int NT = K2 / 16;

    int arow0 = tid >> 2, apc0 = (tid & 3) * 4;
    int arow1 = (tid + 256) >> 2, apc1 = ((tid + 256) & 3) * 4;
    int pr0 = tid >> 5, cg0 = (tid & 31) * 4;
    int pr1 = (tid + 256) >> 5, cg1 = ((tid + 256) & 31) * 4;

    float c[4][4][4];
#pragma unroll
    for (int i = 0; i < 4; i++)
#pragma unroll
        for (int j = 0; j < 4; j++)
#pragma unroll
            for (int f = 0; f < 4; f++) c[i][j][f] = 0.f;

#define ISSUE_TILE(kt, buf) do {                                               \
        uint32_t st = sb + (buf) * (STG_U32 * 4);                              \
        int p0 = (kt) * 16;                                                    \
        size_t a0 = (size_t)(m0 + arow0) * K2 + p0 + apc0;                     \
        uint32_t sa0 = st + (arow0 * ASU + apc0) * 4;                          \
        cpasync16(sa0, &Ahp[a0]);                                              \
        cpasync16(sa0 + A_STG * 4, &Alp[a0]);                                  \
        size_t a1 = (size_t)(m0 + arow1) * K2 + p0 + apc1;                     \
        uint32_t sa1 = st + (arow1 * ASU + apc1) * 4;                          \
        cpasync16(sa1, &Ahp[a1]);                                              \
        cpasync16(sa1 + A_STG * 4, &Alp[a1]);                                  \
        size_t b0 = (size_t)(p0 + pr0) * N + n0 + cg0;                         \
        uint32_t sb0 = st + (2 * A_STG + pr0 * BSU + cg0) * 4;                 \
        cpasync16(sb0, &Whp[b0]);                                              \
        cpasync16(sb0 + B_STG * 4, &Wlp[b0]);                                  \
        size_t b1 = (size_t)(p0 + pr1) * N + n0 + cg1;                         \
        uint32_t sb1 = st + (2 * A_STG + pr1 * BSU + cg1) * 4;                 \
        cpasync16(sb1, &Whp[b1]);                                              \
        cpasync16(sb1 + B_STG * 4, &Wlp[b1]);                                  \
        CP_COMMIT();                                                           \
    } while (0)

    ISSUE_TILE(0, 0);
    if (NT > 1) ISSUE_TILE(1, 1);

    for (int kt = 0; kt < NT; kt++) {
        int buf = kt & 1;
        if (kt + 1 < NT) CP_WAIT1(); else CP_WAIT0();
        __syncthreads();
        uint32_t* sAh = sgm + buf * STG_U32;
        uint32_t* sAl = sAh + A_STG;
        uint32_t* sBh = sAl + A_STG;
        uint32_t* sBl = sBh + B_STG;
#pragma unroll
        for (int kk = 0; kk < 2; kk++) {
            int kp = kk * 8;
            uint32_t bh[4][2], bl[4][2];
#pragma unroll
            for (int nt = 0; nt < 4; nt++) {
                int cb = warpN * 32 + nt * 8 + gid;
                bh[nt][0] = sBh[(kp + tig) * BSU + cb];
                bh[nt][1] = sBh[(kp + tig + 4) * BSU + cb];
                bl[nt][0] = sBl[(kp + tig) * BSU + cb];
                bl[nt][1] = sBl[(kp + tig + 4) * BSU + cb];
            }
#pragma unroll
            for (int mt = 0; mt < 4; mt++) {
                int rb = warpM * 64 + mt * 16 + gid;
                uint32_t ah[4], al[4];
                ah[0] = sAh[rb * ASU + kp + tig];
                ah[1] = sAh[(rb + 8) * ASU + kp + tig];
                ah[2] = sAh[rb * ASU + kp + tig + 4];
                ah[3] = sAh[(rb + 8) * ASU + kp + tig + 4];
                al[0] = sAl[rb * ASU + kp + tig];
                al[1] = sAl[(rb + 8) * ASU + kp + tig];
                al[2] = sAl[rb * ASU + kp + tig + 4];
                al[3] = sAl[(rb + 8) * ASU + kp + tig + 4];
#pragma unroll
                for (int nt = 0; nt < 4; nt++) {
                    mma_bf16(c[mt][nt], ah, bh[nt]);
                    mma_bf16(c[mt][nt], al, bh[nt]);
                    mma_bf16(c[mt][nt], ah, bl[nt]);
                }
            }
        }
        __syncthreads();
        if (kt + 2 < NT) ISSUE_TILE(kt + 2, buf);
    }
#undef ISSUE_TILE
    // ---- epilogue ----
    if (FLAGS == 4) {
        // gate/up interleaved: cols 4q..4q+1 = gate pair, 4q+2..4q+3 = up pair.
        // even tig holds gate pair, odd tig holds up pair of the same group.
#pragma unroll
        for (int mt = 0; mt < 4; mt++) {
#pragma unroll
            for (int half = 0; half < 2; half++) {
                int row = m0 + warpM * 64 + mt * 16 + gid + half * 8;
#pragma unroll
                for (int nt = 0; nt < 4; nt++) {
                    float v0 = c[mt][nt][half * 2 + 0];
                    float v1 = c[mt][nt][half * 2 + 1];
                    float p0 = __shfl_xor_sync(0xffffffffu, v0, 1);
                    float p1 = __shfl_xor_sync(0xffffffffu, v1, 1);
                    if ((tig & 1) == 0) {
                        float o0 = v0 / (1.f + __expf(-v0)) * p0;
                        float o1 = v1 / (1.f + __expf(-v1)) * p1;
                        int c0 = n0 + warpN * 32 + nt * 8 + 2 * tig;
                        int q = c0 >> 2;
                        uint32_t hv, lv;
                        split_pair(o0, o1, hv, lv);
                        size_t o = (size_t)row * (FFD / 2) + q;
                        Dh[o] = hv; Dl[o] = lv;
                    }
                }
            }
        }
    } else {
#pragma unroll
        for (int mt = 0; mt < 4; mt++) {
#pragma unroll
            for (int half = 0; half < 2; half++) {
                int row = m0 + warpM * 64 + mt * 16 + gid + half * 8;
                float* Crow = C + (size_t)row * N + n0 + warpN * 32;
#pragma unroll
                for (int nt = 0; nt < 4; nt++) {
                    int col = nt * 8 + tig * 2;
                    float2 r;
                    r.x = c[mt][nt][half * 2 + 0];
                    r.y = c[mt][nt][half * 2 + 1];
                    if (FLAGS & 1) {
                        float2 bb = *(const float2*)&bias[n0 + warpN * 32 + col];
                        r.x += bb.x; r.y += bb.y;
                    }
                    if (FLAGS & 2) {
                        float2 cc = *(const float2*)&Crow[col];
                        r.x += cc.x; r.y += cc.y;
                    }
                    *(float2*)&Crow[col] = r;
                }
            }
        }
    }
}

// ---------------- tensor-core flash attention (pre-split planes) ----------------
#define ATSU 36
__global__ void __launch_bounds__(128)
attn_mma_kernel(const uint32_t* __restrict__ qhp, const uint32_t* __restrict__ qlp,
                const uint32_t* __restrict__ khp, const uint32_t* __restrict__ klp,
                const uint32_t* __restrict__ vth, const uint32_t* __restrict__ vtl,
                uint32_t* __restrict__ oh, uint32_t* __restrict__ ol) {
    __shared__ uint32_t sm0[64 * ATSU], sm1[64 * ATSU];   // Q (prologue) then K hi/lo
    __shared__ uint32_t sm2[64 * ATSU], sm3[64 * ATSU];   // V^T hi/lo
    int qt = blockIdx.x, h = blockIdx.y, b = blockIdx.z;
    int kh = h >> 2;
    int tid = threadIdx.x, lane = tid & 31, warp = tid >> 5;
    int gid = lane >> 2, tig = lane & 3;

    // Q fill (copies)
    for (int i = tid; i < 1024; i += 128) {
        int plane = i >> 9, rem = i & 511, row = rem >> 3, ch = (rem & 7) * 4;
        const uint32_t* src = plane ? qlp : qhp;
        uint4 v = *(const uint4*)&src[(size_t)(b * KTOK + qt * 64 + row) * 512 + h * 32 + ch];
        uint32_t* dst = plane ? sm1 : sm0;
        *(uint4*)&dst[row * ATSU + ch] = v;
    }
    __syncthreads();
    uint32_t qh[4][4], ql[4][4];
    {
        int r0 = warp * 16 + gid, r1 = r0 + 8;
#pragma unroll
        for (int kc = 0; kc < 4; kc++) {
            int p = kc * 8 + tig;
            qh[kc][0] = sm0[r0 * ATSU + p];
            qh[kc][1] = sm0[r1 * ATSU + p];
            qh[kc][2] = sm0[r0 * ATSU + p + 4];
            qh[kc][3] = sm0[r1 * ATSU + p + 4];
            ql[kc][0] = sm1[r0 * ATSU + p];
            ql[kc][1] = sm1[r1 * ATSU + p];
            ql[kc][2] = sm1[r0 * ATSU + p + 4];
            ql[kc][3] = sm1[r1 * ATSU + p + 4];
        }
    }

    float accO[8][4];
#pragma unroll
    for (int nt = 0; nt < 8; nt++)
#pragma unroll
        for (int f = 0; f < 4; f++) accO[nt][f] = 0.f;
    float m0r = -1e30f, m1r = -1e30f, l0r = 0.f, l1r = 0.f;

    for (int kt = 0; kt <= qt; kt++) {
        __syncthreads();
        // K fill (copies)
        for (int i = tid; i < 1024; i += 128) {
            int plane = i >> 9, rem = i & 511, row = rem >> 3, ch = (rem & 7) * 4;
            const uint32_t* src = plane ? klp : khp;
            uint4 v = *(const uint4*)&src[(size_t)(b * KTOK + kt * 64 + row) * 128 + kh * 32 + ch];
            uint32_t* dst = plane ? sm1 : sm0;
            *(uint4*)&dst[row * ATSU + ch] = v;
        }
        // V fill (copies from transposed planes)
        for (int i = tid; i < 1024; i += 128) {
            int plane = i >> 9, rem = i & 511, d = rem >> 3, ch = (rem & 7) * 4;
            const uint32_t* src = plane ? vtl : vth;
            uint4 v = *(const uint4*)&src[(size_t)((b * KVHEAD + kh) * HEADD + d) * TPH + kt * 32 + ch];
            uint32_t* dst = plane ? sm3 : sm2;
            *(uint4*)&dst[d * ATSU + ch] = v;
        }
        __syncthreads();

        float s[8][4];
#pragma unroll
        for (int nt = 0; nt < 8; nt++)
#pragma unroll
            for (int f = 0; f < 4; f++) s[nt][f] = 0.f;
#pragma unroll
        for (int kc = 0; kc < 4; kc++) {
#pragma unroll
            for (int nt = 0; nt < 8; nt++) {
                int tok = nt * 8 + gid;
                uint32_t bh[2], bl[2];
                bh[0] = sm0[tok * ATSU + kc * 8 + tig];
                bh[1] = sm0[tok * ATSU + kc * 8 + tig + 4];
                bl[0] = sm1[tok * ATSU + kc * 8 + tig];
                bl[1] = sm1[tok * ATSU + kc * 8 + tig + 4];
                mma_bf16(s[nt], qh[kc], bh);
                mma_bf16(s[nt], ql[kc], bh);
                mma_bf16(s[nt], qh[kc], bl);
            }
        }
        if (kt == qt) {
            int r0 = warp * 16 + gid, r1 = r0 + 8;
#pragma unroll
            for (int nt = 0; nt < 8; nt++) {
                int c0 = nt * 8 + 2 * tig, c1 = c0 + 1;
                if (c0 > r0) s[nt][0] = -1e30f;
                if (c1 > r0) s[nt][1] = -1e30f;
                if (c0 > r1) s[nt][2] = -1e30f;
                if (c1 > r1) s[nt][3] = -1e30f;
            }
        }
        float mx0 = -1e30f, mx1 = -1e30f;
#pragma unroll
        for (int nt = 0; nt < 8; nt++) {
            mx0 = fmaxf(mx0, fmaxf(s[nt][0], s[nt][1]));
            mx1 = fmaxf(mx1, fmaxf(s[nt][2], s[nt][3]));
        }
        mx0 = fmaxf(mx0, __shfl_xor_sync(0xffffffffu, mx0, 1));
        mx0 = fmaxf(mx0, __shfl_xor_sync(0xffffffffu, mx0, 2));
        mx1 = fmaxf(mx1, __shfl_xor_sync(0xffffffffu, mx1, 1));
        mx1 = fmaxf(mx1, __shfl_xor_sync(0xffffffffu, mx1, 2));
        float mn0 = fmaxf(m0r, mx0), mn1 = fmaxf(m1r, mx1);
        float cor0 = __expf(m0r - mn0), cor1 = __expf(m1r - mn1);
        float ps0 = 0.f, ps1 = 0.f;
#pragma unroll
        for (int nt = 0; nt < 8; nt++) {
            s[nt][0] = __expf(s[nt][0] - mn0);
            s[nt][1] = __expf(s[nt][1] - mn0);
            s[nt][2] = __expf(s[nt][2] - mn1);
            s[nt][3] = __expf(s[nt][3] - mn1);
            ps0 += s[nt][0] + s[nt][1];
            ps1 += s[nt][2] + s[nt][3];
        }
        ps0 += __shfl_xor_sync(0xffffffffu, ps0, 1);
        ps0 += __shfl_xor_sync(0xffffffffu, ps0, 2);
        ps1 += __shfl_xor_sync(0xffffffffu, ps1, 1);
        ps1 += __shfl_xor_sync(0xffffffffu, ps1, 2);
        l0r = l0r * cor0 + ps0;  m0r = mn0;
        l1r = l1r * cor1 + ps1;  m1r = mn1;
#pragma unroll
        for (int nt = 0; nt < 8; nt++) {
            accO[nt][0] *= cor0; accO[nt][1] *= cor0;
            accO[nt][2] *= cor1; accO[nt][3] *= cor1;
        }
#pragma unroll
        for (int kc = 0; kc < 4; kc++) {
            uint32_t ph[4], pl[4];
            split_pair(s[2 * kc][0],     s[2 * kc][1],     ph[0], pl[0]);
            split_pair(s[2 * kc][2],     s[2 * kc][3],     ph[1], pl[1]);
            split_pair(s[2 * kc + 1][0], s[2 * kc + 1][1], ph[2], pl[2]);
            split_pair(s[2 * kc + 1][2], s[2 * kc + 1][3], ph[3], pl[3]);
#pragma unroll
            for (int nt = 0; nt < 8; nt++) {
                int d = nt * 8 + gid;
                uint32_t vh[2], vl[2];
                vh[0] = sm2[d * ATSU + kc * 8 + tig];
                vh[1] = sm2[d * ATSU + kc * 8 + tig + 4];
                vl[0] = sm3[d * ATSU + kc * 8 + tig];
                vl[1] = sm3[d * ATSU + kc * 8 + tig + 4];
                mma_bf16(accO[nt], ph, vh);
                mma_bf16(accO[nt], pl, vh);
                mma_bf16(accO[nt], ph, vl);
            }
        }
    }
    // epilogue: write pair planes directly
    float i0 = 1.f / l0r, i1 = 1.f / l1r;
    int row0 = b * KTOK + qt * 64 + warp * 16 + gid;
#pragma unroll
    for (int nt = 0; nt < 8; nt++) {
        int dp = (h * HEADD + nt * 8 + 2 * tig) >> 1;
        uint32_t hv, lv;
        split_pair(accO[nt][0] * i0, accO[nt][1] * i0, hv, lv);
        oh[(size_t)row0 * 512 + dp] = hv;
        ol[(size_t)row0 * 512 + dp] = lv;
        split_pair(accO[nt][2] * i1, accO[nt][3] * i1, hv, lv);
        oh[(size_t)(row0 + 8) * 512 + dp] = hv;
        ol[(size_t)(row0 + 8) * 512 + dp] = lv;
    }
}

// ---------------- launch ----------------
extern "C" void kernel_launch(void* const* d_in, const int* in_sizes, int n_in,
                              void* d_out, int out_size) {
    const int*   ids      = (const int*)d_in[0];
    const float* emb      = (const float*)d_in[1];
    const float* router_k = (const float*)d_in[2];
    const float* router_q = (const float*)d_in[3];
    const float* ln1      = (const float*)d_in[4];
    const float* ln2      = (const float*)d_in[5];
    const float* wq       = (const float*)d_in[6];
    const float* bq       = (const float*)d_in[7];
    const float* wk       = (const float*)d_in[8];
    const float* bk       = (const float*)d_in[9];
    const float* wv       = (const float*)d_in[10];
    const float* bv       = (const float*)d_in[11];
    const float* wo       = (const float*)d_in[12];
    const float* wg       = (const float*)d_in[13];
    const float* wu       = (const float*)d_in[14];
    const float* wd       = (const float*)d_in[15];
    float* hidden = (float*)d_out;

    float *x, *qkv, *pooled, *scores, *bqkv;
    int* tok;
    uint32_t *wqkvh, *wqkvl, *woh, *wol, *wguh, *wgul, *wdh, *wdl;
    uint32_t *hh, *hl, *oh, *ol, *gh, *gl;
    uint32_t *qhp, *qlp, *khp, *klp, *vth, *vtl;
    cudaGetSymbolAddress((void**)&x, g_x);
    cudaGetSymbolAddress((void**)&qkv, g_qkv);
    cudaGetSymbolAddress((void**)&pooled, g_pool);
    cudaGetSymbolAddress((void**)&scores, g_scores);
    cudaGetSymbolAddress((void**)&tok, g_tok);
    cudaGetSymbolAddress((void**)&bqkv, g_bqkv);
    cudaGetSymbolAddress((void**)&wqkvh, g_wqkvh); cudaGetSymbolAddress((void**)&wqkvl, g_wqkvl);
    cudaGetSymbolAddress((void**)&woh, g_woh);     cudaGetSymbolAddress((void**)&wol, g_wol);
    cudaGetSymbolAddress((void**)&wguh, g_wguh);   cudaGetSymbolAddress((void**)&wgul, g_wgul);
    cudaGetSymbolAddress((void**)&wdh, g_wdh);     cudaGetSymbolAddress((void**)&wdl, g_wdl);
    cudaGetSymbolAddress((void**)&hh, g_hh);       cudaGetSymbolAddress((void**)&hl, g_hl);
    cudaGetSymbolAddress((void**)&oh, g_oh);       cudaGetSymbolAddress((void**)&ol, g_ol);
    cudaGetSymbolAddress((void**)&gh, g_gh);       cudaGetSymbolAddress((void**)&gl, g_gl);
    cudaGetSymbolAddress((void**)&qhp, g_qhp);     cudaGetSymbolAddress((void**)&qlp, g_qlp);
    cudaGetSymbolAddress((void**)&khp, g_khp);     cudaGetSymbolAddress((void**)&klp, g_klp);
    cudaGetSymbolAddress((void**)&vth, g_vth);     cudaGetSymbolAddress((void**)&vtl, g_vtl);

    cudaFuncSetAttribute(pgemm_kernel<0>, cudaFuncAttributeMaxDynamicSharedMemorySize, SM_PGEMM);
    cudaFuncSetAttribute(pgemm_kernel<1>, cudaFuncAttributeMaxDynamicSharedMemorySize, SM_PGEMM);
    cudaFuncSetAttribute(pgemm_kernel<2>, cudaFuncAttributeMaxDynamicSharedMemorySize, SM_PGEMM);
    cudaFuncSetAttribute(pgemm_kernel<4>, cudaFuncAttributeMaxDynamicSharedMemorySize, SM_PGEMM);

    embed_kernel<<<BATCH * SEQ, 256>>>(ids, emb, hidden);

    // ---- weight prepacks ----
    prepack_gu_kernel<<<NLAYER * 512 * 1408 / 256, 256>>>(wg, wu, wguh, wgul);
    prepack_qkv_kernel<<<NLAYER * 512 * 384 / 256, 256>>>(wq, wk, wv, wqkvh, wqkvl);
    prepack_kernel<<<NLAYER * 512 * 1024 / 1024, 256>>>(wo, woh, wol, 256, 1024);
    prepack_kernel<<<NLAYER * 1408 * 1024 / 1024, 256>>>(wd, wdh, wdl, 256, 1024);
    fuse_bias_kernel<<<NLAYER * NQKV / 256, 256>>>(bq, bk, bv, bqkv);

    for (int blk = 0; blk < NBLK; blk++) {
        int li0 = blk * BPL;
        pool_kernel<<<BATCH * NSEG, 256>>>(hidden, pooled);
        router_kernel<<<dim3(NSEG, BATCH), 128>>>(
            pooled, router_k + (size_t)blk * DIM * RANKR,
            router_q + (size_t)blk * NQRY * RANKR, scores);
        select_kernel<<<BATCH, 256>>>(scores, tok);
        gather_norm_kernel<<<BT, 256>>>(hidden, tok, ln1 + (size_t)li0 * DIM, x, hh, hl);

        for (int j = 0; j < BPL; j++) {
            int li = li0 + j;
            size_t oqkv = (size_t)li * 512 * NQKV;
            size_t oo   = (size_t)li * 512 * 1024;
            size_t ogu  = (size_t)li * 512 * NGU;
            size_t od   = (size_t)li * 1408 * 1024;

            if (j > 0)
                rmsnorm_kernel<<<BT, 256>>>(x, ln1 + (size_t)li * DIM, hh, hl);
            pgemm_kernel<1><<<dim3(NQKV / 128, BT / 128), 256, SM_PGEMM>>>(
                hh, hl, wqkvh + oqkv, wqkvl + oqkv, bqkv + (size_t)li * NQKV,
                qkv, nullptr, nullptr, BT, NQKV, 512);
            prep_attn_kernel<<<BT / 2, 128>>>(qkv, tok, qhp, qlp, khp, klp, vth, vtl);
            attn_mma_kernel<<<dim3(KTOK / 64, NHEAD, BATCH), 128>>>(
                qhp, qlp, khp, klp, vth, vtl, oh, ol);
            pgemm_kernel<2><<<dim3(8, BT / 128), 256, SM_PGEMM>>>(
                oh, ol, woh + oo, wol + oo, nullptr, x, nullptr, nullptr, BT, 1024, 512);
            rmsnorm_kernel<<<BT, 256>>>(x, ln2 + (size_t)li * DIM, hh, hl);
            pgemm_kernel<4><<<dim3(NGU / 128, BT / 128), 256, SM_PGEMM>>>(
                hh, hl, wguh + ogu, wgul + ogu, nullptr, nullptr, gh, gl, BT, NGU, 512);
            pgemm_kernel<2><<<dim3(8, BT / 128), 256, SM_PGEMM>>>(
                gh, gl, wdh + od, wdl + od, nullptr, x, nullptr, nullptr, BT, 1024, 1408);
        }
        scatter_kernel<<<BT, 256>>>(x, tok, hidden);
    }
}

// round 15
// speedup vs baseline: 3.3311x; 1.0133x over previous
#include <cuda_runtime.h>
#include <cuda_bf16.h>
#include <math.h>
#include <stdint.h>

// ---------------- problem constants ----------------
#define BATCH 2
#define SEQ   4096
#define DIM   1024
#define NHEAD 16
#define KVHEAD 4
#define HEADD 64
#define FFD   2816
#define NSEG  256
#define SEGLEN 16
#define KSEG  76
#define KTOK  (KSEG*SEGLEN)      // 1216
#define BT    (BATCH*KTOK)       // 2432 = 19*128
#define NLAYER 12
#define NBLK  2
#define BPL   6
#define RANKR 16
#define NQRY  8
#define NQKV  1536
#define NGU   5632
#define TPH   (KTOK/2)           // 608 token pairs per batch
// attention split-softmax config
#define QSPLIT 11                // qt >= QSPLIT gets 2 kt-chunks
#define NQS    8                 // number of split qts (11..18)
#define NCID   (QSPLIT + 2*NQS)  // 27 chunk slots per (h,b)

// ---------------- scratch (device globals; no allocs allowed) ----------------
__device__ float g_x   [BT*DIM];
__device__ float g_qkv [BT*NQKV];
__device__ float g_pool[BATCH*NSEG*DIM];
__device__ float g_scores[BATCH*NSEG];
__device__ int   g_tok [BATCH*KTOK];
__device__ float g_bqkv[NLAYER*NQKV];

// pre-packed bf16 hi/lo pair weights: [L][K/2][N] u32 (u32 = bf16 pair along K)
__device__ uint32_t g_wqkvh[NLAYER*512*NQKV], g_wqkvl[NLAYER*512*NQKV];
__device__ uint32_t g_woh  [NLAYER*512*1024], g_wol  [NLAYER*512*1024];
__device__ uint32_t g_wguh [NLAYER*512*NGU],  g_wgul [NLAYER*512*NGU];   // gate/up col-interleaved
__device__ uint32_t g_wdh  [NLAYER*1408*1024],g_wdl  [NLAYER*1408*1024];
// activation pair buffers [M][K/2]
__device__ uint32_t g_hh[BT*DIM/2],  g_hl[BT*DIM/2];
__device__ uint32_t g_oh[BT*DIM/2],  g_ol[BT*DIM/2];
__device__ uint32_t g_gh[BT*FFD/2],  g_gl[BT*FFD/2];
// attention pre-split planes
__device__ uint32_t g_qhp[BT*512],  g_qlp[BT*512];
__device__ uint32_t g_khp[BT*128],  g_klp[BT*128];
__device__ uint32_t g_vth[BATCH*KVHEAD*HEADD*TPH], g_vtl[BATCH*KVHEAD*HEADD*TPH];
// split-softmax partials: slots = B*NHEAD*NQS*2 = 512
__device__ float g_pacc[512*64*64];
__device__ float g_pml [512*64*2];

// ---------------- split helper ----------------
__device__ __forceinline__ void split_pair(float x0, float x1, uint32_t& hp, uint32_t& lp) {
    uint32_t h;
    asm("cvt.rn.bf16x2.f32 %0, %1, %2;" : "=r"(h) : "f"(x1), "f"(x0));
    float h0 = __uint_as_float(h << 16);
    float h1 = __uint_as_float(h & 0xFFFF0000u);
    float l0 = x0 - h0, l1 = x1 - h1;
    uint32_t l;
    asm("cvt.rn.bf16x2.f32 %0, %1, %2;" : "=r"(l) : "f"(l1), "f"(l0));
    hp = h; lp = l;
}
__device__ __forceinline__ uint32_t smem_u32(const void* p) {
    uint32_t a;
    asm("{ .reg .u64 t; cvta.to.shared.u64 t, %1; cvt.u32.u64 %0, t; }" : "=r"(a) : "l"(p));
    return a;
}
__device__ __forceinline__ void cpasync16(uint32_t dst, const void* src) {
    asm volatile("cp.async.cg.shared.global [%0], [%1], 16;" :: "r"(dst), "l"(src));
}
#define CP_COMMIT() asm volatile("cp.async.commit_group;" ::: "memory")
#define CP_WAIT1()  asm volatile("cp.async.wait_group 1;" ::: "memory")
#define CP_WAIT0()  asm volatile("cp.async.wait_group 0;" ::: "memory")

// ---------------- weight prepacks ----------------
__global__ void prepack_kernel(const float* __restrict__ src,
                               uint32_t* __restrict__ dh, uint32_t* __restrict__ dl,
                               int n4row, int N) {
    int idx = blockIdx.x * 256 + threadIdx.x;
    int p = idx / n4row, c = (idx - p * n4row) * 4;
    const float* r0 = src + (size_t)(2 * p) * N + c;
    float4 a = *(const float4*)r0;
    float4 b = *(const float4*)(r0 + N);
    uint4 h, l;
    split_pair(a.x, b.x, h.x, l.x);
    split_pair(a.y, b.y, h.y, l.y);
    split_pair(a.z, b.z, h.z, l.z);
    split_pair(a.w, b.w, h.w, l.w);
    *(uint4*)(dh + (size_t)idx * 4) = h;
    *(uint4*)(dl + (size_t)idx * 4) = l;
}

__global__ void prepack_qkv_kernel(const float* __restrict__ wq,
                                   const float* __restrict__ wk,
                                   const float* __restrict__ wv,
                                   uint32_t* __restrict__ dh, uint32_t* __restrict__ dl) {
    int idx = blockIdx.x * 256 + threadIdx.x;
    int l = idx / (512 * 384);
    int rem = idx - l * (512 * 384);
    int p = rem / 384, col = (rem - p * 384) * 4;
    const float *s0;
    int srcN;
    if (col < 1024)      { s0 = wq + ((size_t)(l * 1024 + 2 * p)) * 1024 + col;          srcN = 1024; }
    else if (col < 1280) { s0 = wk + ((size_t)(l * 1024 + 2 * p)) * 256 + (col - 1024);  srcN = 256; }
    else                 { s0 = wv + ((size_t)(l * 1024 + 2 * p)) * 256 + (col - 1280);  srcN = 256; }
    float4 a = *(const float4*)s0;
    float4 b = *(const float4*)(s0 + srcN);
    uint4 h, l4;
    split_pair(a.x, b.x, h.x, l4.x);
    split_pair(a.y, b.y, h.y, l4.y);
    split_pair(a.z, b.z, h.z, l4.z);
    split_pair(a.w, b.w, h.w, l4.w);
    *(uint4*)(dh + (size_t)idx * 4) = h;
    *(uint4*)(dl + (size_t)idx * 4) = l4;
}

__global__ void prepack_gu_kernel(const float* __restrict__ wg,
                                  const float* __restrict__ wu,
                                  uint32_t* __restrict__ dh, uint32_t* __restrict__ dl) {
    int idx = blockIdx.x * 256 + threadIdx.x;
    int l = idx / (512 * 1408);
    int rem = idx - l * (512 * 1408);
    int p = rem / 1408, q = rem - p * 1408;
    size_t row0 = (size_t)(l * 1024 + 2 * p);
    const float* g0 = wg + row0 * 2816 + 2 * q;
    const float* u0 = wu + row0 * 2816 + 2 * q;
    float2 ga = *(const float2*)g0;
    float2 gb = *(const float2*)(g0 + 2816);
    float2 ua = *(const float2*)u0;
    float2 ub = *(const float2*)(u0 + 2816);
    uint4 h, l4;
    split_pair(ga.x, gb.x, h.x, l4.x);
    split_pair(ga.y, gb.y, h.y, l4.y);
    split_pair(ua.x, ub.x, h.z, l4.z);
    split_pair(ua.y, ub.y, h.w, l4.w);
    *(uint4*)(dh + (size_t)idx * 4) = h;
    *(uint4*)(dl + (size_t)idx * 4) = l4;
}

__global__ void fuse_bias_kernel(const float* __restrict__ bq,
                                 const float* __restrict__ bk,
                                 const float* __restrict__ bv,
                                 float* __restrict__ dst) {
    int i = blockIdx.x * 256 + threadIdx.x;
    int l = i / NQKV, j = i - l * NQKV;
    float v = (j < 1024) ? bq[l * 1024 + j]
            : (j < 1280) ? bk[l * 256 + j - 1024]
                         : bv[l * 256 + j - 1280];
    dst[i] = v;
}

// ---------------- embed / pool / router / select / scatter ----------------
__global__ void embed_kernel(const int* __restrict__ ids,
                             const float* __restrict__ emb,
                             float* __restrict__ hidden) {
    int row = blockIdx.x;
    int id  = ids[row];
    const float4* src = (const float4*)(emb + (size_t)id * DIM);
    float4* dst = (float4*)(hidden + (size_t)row * DIM);
    dst[threadIdx.x] = src[threadIdx.x];
}

__global__ void pool_kernel(const float* __restrict__ hidden,
                            float* __restrict__ pooled) {
    int b = blockIdx.x >> 8, n = blockIdx.x & 255;
    const float* base = hidden + ((size_t)b * SEQ + n * SEGLEN) * DIM + threadIdx.x * 4;
    float4 acc = make_float4(0.f, 0.f, 0.f, 0.f);
#pragma unroll
    for (int t = 0; t < SEGLEN; t++) {
        float4 v = *(const float4*)(base + (size_t)t * DIM);
        acc.x += v.x; acc.y += v.y; acc.z += v.z; acc.w += v.w;
    }
    const float s = 1.f / SEGLEN;
    acc.x *= s; acc.y *= s; acc.z *= s; acc.w *= s;
    *(float4*)(pooled + ((size_t)b * NSEG + n) * DIM + threadIdx.x * 4) = acc;
}

__global__ void router_kernel(const float* __restrict__ pooled,
                              const float* __restrict__ rk,
                              const float* __restrict__ rq,
                              float* __restrict__ scores) {
    int n = blockIdx.x, b = blockIdx.y;
    const float* p = pooled + ((size_t)b * NSEG + n) * DIM;
    __shared__ float part[128];
    int tid = threadIdx.x;
    int r = tid & 15, g = tid >> 4;
    float sum = 0.f;
    int d0 = g * 128;
    for (int d = d0; d < d0 + 128; d++) sum += p[d] * rk[d * RANKR + r];
    part[tid] = sum;
    __syncthreads();
    if (tid < RANKR) {
        float key = 0.f;
        for (int gg = 0; gg < 8; gg++) key += part[gg * 16 + tid];
        part[tid] = key;
    }
    __syncthreads();
    if (tid == 0) {
        float best = -1e30f;
        for (int qq = 0; qq < NQRY; qq++) {
            float dv = 0.f;
            for (int rr = 0; rr < RANKR; rr++) dv += rq[qq * RANKR + rr] * part[rr];
            best = fmaxf(best, dv);
        }
        scores[b * NSEG + n] = best;
    }
}

__global__ void select_kernel(const float* __restrict__ scores,
                              int* __restrict__ tok) {
    int b = blockIdx.x;
    __shared__ float s[NSEG];
    __shared__ int pf[NSEG];
    int i = threadIdx.x;
    float mine = scores[b * NSEG + i];
    s[i] = mine;
    __syncthreads();
    int rank = 0;
    for (int j = 0; j < NSEG; j++) {
        float o = s[j];
        rank += (o > mine) || (o == mine && j < i);
    }
    int sel = (rank < KSEG) ? 1 : 0;
    pf[i] = sel;
    __syncthreads();
    for (int off = 1; off < NSEG; off <<= 1) {
        int add = (i >= off) ? pf[i - off] : 0;
        __syncthreads();
        pf[i] += add;
        __syncthreads();
    }
    if (sel) {
        int p = pf[i] - 1;
        int* dst = tok + b * KTOK + p * SEGLEN;
        int base = i * SEGLEN;
#pragma unroll
        for (int t = 0; t < SEGLEN; t++) dst[t] = base + t;
    }
}

__global__ void scatter_kernel(const float* __restrict__ x,
                               const int* __restrict__ tok,
                               float* __restrict__ hidden) {
    int row = blockIdx.x;
    int b = row / KTOK;
    int tk = tok[row];
    const float4* src = (const float4*)(x + (size_t)row * DIM);
    float4* dst = (float4*)(hidden + ((size_t)b * SEQ + tk) * DIM);
    dst[threadIdx.x] = src[threadIdx.x];
}

// ---------------- RMSNorm ----------------
__device__ __forceinline__ void rms_body(float4 v, const float* w, int row, int t,
                                         uint32_t* oh, uint32_t* ol) {
    float ss = v.x * v.x + v.y * v.y + v.z * v.z + v.w * v.w;
#pragma unroll
    for (int d = 16; d >= 1; d >>= 1) ss += __shfl_xor_sync(0xffffffffu, ss, d);
    __shared__ float ws[8];
    __shared__ float tot;
    if ((t & 31) == 0) ws[t >> 5] = ss;
    __syncthreads();
    if (t == 0) {
        float a = 0.f;
        for (int wgi = 0; wgi < 8; wgi++) a += ws[wgi];
        tot = a;
    }
    __syncthreads();
    float inv = rsqrtf(tot * (1.f / DIM) + 1e-6f);
    float4 wv = ((const float4*)w)[t];
    float o0 = v.x * inv * wv.x, o1 = v.y * inv * wv.y;
    float o2 = v.z * inv * wv.z, o3 = v.w * inv * wv.w;
    uint32_t h0, l0, h1, l1;
    split_pair(o0, o1, h0, l0);
    split_pair(o2, o3, h1, l1);
    size_t base = (size_t)row * (DIM / 2) + t * 2;
    *(uint2*)&oh[base] = make_uint2(h0, h1);
    *(uint2*)&ol[base] = make_uint2(l0, l1);
}

__global__ void rmsnorm_kernel(const float* __restrict__ x,
                               const float* __restrict__ w,
                               uint32_t* __restrict__ oh,
                               uint32_t* __restrict__ ol) {
    int row = blockIdx.x, t = threadIdx.x;
    float4 v = ((const float4*)(x + (size_t)row * DIM))[t];
    rms_body(v, w, row, t, oh, ol);
}

__global__ void gather_norm_kernel(const float* __restrict__ hidden,
                                   const int* __restrict__ tok,
                                   const float* __restrict__ w,
                                   float* __restrict__ x,
                                   uint32_t* __restrict__ oh,
                                   uint32_t* __restrict__ ol) {
    int row = blockIdx.x, t = threadIdx.x;
    int b = row / KTOK;
    int tk = tok[row];
    float4 v = ((const float4*)(hidden + ((size_t)b * SEQ + tk) * DIM))[t];
    ((float4*)(x + (size_t)row * DIM))[t] = v;
    rms_body(v, w, row, t, oh, ol);
}

// ---------------- prep_attn: RoPE + pre-split Q/K/V into pair planes ----------------
__global__ void __launch_bounds__(128)
prep_attn_kernel(const float* __restrict__ qkv, const int* __restrict__ tok,
                 uint32_t* __restrict__ qh, uint32_t* __restrict__ ql,
                 uint32_t* __restrict__ khp, uint32_t* __restrict__ klp,
                 uint32_t* __restrict__ vth, uint32_t* __restrict__ vtl) {
    __shared__ float q[2][1024], kk[2][256], vv[2][256];
    int p = blockIdx.x;
    int b = p / TPH;
    int lp = p - b * TPH;
    int r0 = b * KTOK + lp * 2;
    int tid = threadIdx.x;
    for (int i = tid; i < 768; i += 128) {
        int row = i / 384, c = (i % 384) * 4;
        float4 v = *(const float4*)&qkv[(size_t)(r0 + row) * NQKV + c];
        if (c < 1024)      *(float4*)&q[row][c] = v;
        else if (c < 1280) *(float4*)&kk[row][c - 1024] = v;
        else               *(float4*)&vv[row][c - 1280] = v;
    }
    __syncthreads();
    float pos0 = (float)tok[r0], pos1 = (float)tok[r0 + 1];
    for (int t = tid; t < 1280; t += 128) {
        if (t < 1024) {
            int row = t >> 9, rr = t & 511, hh = rr >> 5, i = rr & 31;
            float inv = __powf(10000.f, -(float)(2 * i) / 64.f);
            float ang = (row ? pos1 : pos0) * inv;
            float sn, cs; sincosf(ang, &sn, &cs);
            float* qp = &q[row][hh * 64];
            float x1 = qp[i], x2 = qp[i + 32];
            qp[i]      = x1 * cs - x2 * sn;
            qp[i + 32] = x2 * cs + x1 * sn;
        } else {
            int t2 = t - 1024;
            int row = t2 >> 7, rr = t2 & 127, hh = rr >> 5, i = rr & 31;
            float inv = __powf(10000.f, -(float)(2 * i) / 64.f);
            float ang = (row ? pos1 : pos0) * inv;
            float sn, cs; sincosf(ang, &sn, &cs);
            float* kp = &kk[row][hh * 64];
            float x1 = kp[i], x2 = kp[i + 32];
            kp[i]      = x1 * cs - x2 * sn;
            kp[i + 32] = x2 * cs + x1 * sn;
        }
    }
    __syncthreads();
    for (int t = tid; t < 1024; t += 128) {
        int row = t >> 9, j = t & 511;
        uint32_t h, l;
        split_pair(q[row][2 * j] * 0.125f, q[row][2 * j + 1] * 0.125f, h, l);
        size_t o = (size_t)(r0 + row) * 512 + j;
        qh[o] = h; ql[o] = l;
    }
    for (int t = tid; t < 256; t += 128) {
        int row = t >> 7, j = t & 127;
        uint32_t h, l;
        split_pair(kk[row][2 * j], kk[row][2 * j + 1], h, l);
        size_t o = (size_t)(r0 + row) * 128 + j;
        khp[o] = h; klp[o] = l;
    }
    for (int t = tid; t < 256; t += 128) {
        int kvh = t >> 6, d = t & 63;
        uint32_t h, l;
        split_pair(vv[0][kvh * 64 + d], vv[1][kvh * 64 + d], h, l);
        size_t o = (size_t)((b * KVHEAD + kvh) * HEADD + d) * TPH + lp;
        vth[o] = h; vtl[o] = l;
    }
}

// ---------------- bf16 MMA primitive ----------------
__device__ __forceinline__ void mma_bf16(float c[4], const uint32_t a[4], const uint32_t b[2]) {
    asm volatile(
        "mma.sync.aligned.m16n8k16.row.col.f32.bf16.bf16.f32 "
        "{%0,%1,%2,%3}, {%4,%5,%6,%7}, {%8,%9}, {%0,%1,%2,%3};\n"
        : "+f"(c[0]), "+f"(c[1]), "+f"(c[2]), "+f"(c[3])
        : "r"(a[0]), "r"(a[1]), "r"(a[2]), "r"(a[3]), "r"(b[0]), "r"(b[1]));
}

// ---------------- pair-format split-bf16 (3xMMA) GEMM, cp.async 2-stage ---------
#define ASU 20
#define BSU 136
#define A_STG (128 * ASU)
#define B_STG (16 * BSU)
#define STG_U32 (2 * A_STG + 2 * B_STG)
#define SM_PGEMM (2 * STG_U32 * 4)

template <int FLAGS>
__global__ void __launch_bounds__(256, 2)
pgemm_kernel(const uint32_t* __restrict__ Ahp, const uint32_t* __restrict__ Alp,
             const uint32_t* __restrict__ Whp, const uint32_t* __restrict__ Wlp,
             const float* __restrict__ bias,
             float* __restrict__ C,
             uint32_t* __restrict__ Dh, uint32_t* __restrict__ Dl,
             int M, int N, int K2) {
    extern __shared__ uint32_t sgm[];
    uint32_t sb = smem_u32(sgm);
    int tid = threadIdx.x, lane = tid & 31, warp = tid >> 5;
    int warpM = warp & 1, warpN = warp >> 1;
    int m0 = blockIdx.y * 128, n0 = blockIdx.x * 128;
    int gid = lane >> 2, tig = lane & 3;
    int NT = K2 / 16;

    int arow0 = tid >> 2, apc0 = (tid & 3) * 4;
    int arow1 = (tid + 256) >> 2, apc1 = ((tid + 256) & 3) * 4;
    int pr0 = tid >> 5, cg0 = (tid & 31) * 4;
    int pr1 = (tid + 256) >> 5, cg1 = ((tid + 256) & 31) * 4;

    float c[4][4][4];
#pragma unroll
    for (int i = 0; i < 4; i++)
#pragma unroll
        for (int j = 0; j < 4; j++)
#pragma unroll
            for (int f = 0; f < 4; f++) c[i][j][f] = 0.f;

#define ISSUE_TILE(kt, buf) do {                                               \
        uint32_t st = sb + (buf) * (STG_U32 * 4);                              \
        int p0 = (kt) * 16;                                                    \
        size_t a0 = (size_t)(m0 + arow0) * K2 + p0 + apc0;                     \
        uint32_t sa0 = st + (arow0 * ASU + apc0) * 4;                          \
        cpasync16(sa0, &Ahp[a0]);                                              \
        cpasync16(sa0 + A_STG * 4, &Alp[a0]);                                  \
        size_t a1 = (size_t)(m0 + arow1) * K2 + p0 + apc1;                     \
        uint32_t sa1 = st + (arow1 * ASU + apc1) * 4;                          \
        cpasync16(sa1, &Ahp[a1]);                                              \
        cpasync16(sa1 + A_STG * 4, &Alp[a1]);                                  \
        size_t b0 = (size_t)(p0 + pr0) * N + n0 + cg0;                         \
        uint32_t sb0 = st + (2 * A_STG + pr0 * BSU + cg0) * 4;                 \
        cpasync16(sb0, &Whp[b0]);                                              \
        cpasync16(sb0 + B_STG * 4, &Wlp[b0]);                                  \
        size_t b1 = (size_t)(p0 + pr1) * N + n0 + cg1;                         \
        uint32_t sb1 = st + (2 * A_STG + pr1 * BSU + cg1) * 4;                 \
        cpasync16(sb1, &Whp[b1]);                                              \
        cpasync16(sb1 + B_STG * 4, &Wlp[b1]);                                  \
        CP_COMMIT();                                                           \
    } while (0)

    ISSUE_TILE(0, 0);
    if (NT > 1) ISSUE_TILE(1, 1);

    for (int kt = 0; kt < NT; kt++) {
        int buf = kt & 1;
        if (kt + 1 < NT) CP_WAIT1(); else CP_WAIT0();
        __syncthreads();
        uint32_t* sAh = sgm + buf * STG_U32;
        uint32_t* sAl = sAh + A_STG;
        uint32_t* sBh = sAl + A_STG;
        uint32_t* sBl = sBh + B_STG;
#pragma unroll
        for (int kk = 0; kk < 2; kk++) {
            int kp = kk * 8;
            uint32_t bh[4][2], bl[4][2];
#pragma unroll
            for (int nt = 0; nt < 4; nt++) {
                int cb = warpN * 32 + nt * 8 + gid;
                bh[nt][0] = sBh[(kp + tig) * BSU + cb];
                bh[nt][1] = sBh[(kp + tig + 4) * BSU + cb];
                bl[nt][0] = sBl[(kp + tig) * BSU + cb];
                bl[nt][1] = sBl[(kp + tig + 4) * BSU + cb];
            }
#pragma unroll
            for (int mt = 0; mt < 4; mt++) {
                int rb = warpM * 64 + mt * 16 + gid;
                uint32_t ah[4], al[4];
                ah[0] = sAh[rb * ASU + kp + tig];
                ah[1] = sAh[(rb + 8) * ASU + kp + tig];
                ah[2] = sAh[rb * ASU + kp + tig + 4];
                ah[3] = sAh[(rb + 8) * ASU + kp + tig + 4];
                al[0] = sAl[rb * ASU + kp + tig];
                al[1] = sAl[(rb + 8) * ASU + kp + tig];
                al[2] = sAl[rb * ASU + kp + tig + 4];
                al[3] = sAl[(rb + 8) * ASU + kp + tig + 4];
#pragma unroll
                for (int nt = 0; nt < 4; nt++) {
                    mma_bf16(c[mt][nt], ah, bh[nt]);
                    mma_bf16(c[mt][nt], al, bh[nt]);
                    mma_bf16(c[mt][nt], ah, bl[nt]);
                }
            }
        }
        __syncthreads();
        if (kt + 2 < NT) ISSUE_TILE(kt + 2, buf);
    }
#undef ISSUE_TILE
    // ---- epilogue ----
    if (FLAGS == 4) {
#pragma unroll
        for (int mt = 0; mt < 4; mt++) {
#pragma unroll
            for (int half = 0; half < 2; half++) {
                int row = m0 + warpM * 64 + mt * 16 + gid + half * 8;
#pragma unroll
                for (int nt = 0; nt < 4; nt++) {
                    float v0 = c[mt][nt][half * 2 + 0];
                    float v1 = c[mt][nt][half * 2 + 1];
                    float p0 = __shfl_xor_sync(0xffffffffu, v0, 1);
                    float p1 = __shfl_xor_sync(0xffffffffu, v1, 1);
                    if ((tig & 1) == 0) {
                        float o0 = v0 / (1.f + __expf(-v0)) * p0;
                        float o1 = v1 / (1.f + __expf(-v1)) * p1;
                        int c0 = n0 + warpN * 32 + nt * 8 + 2 * tig;
                        int q = c0 >> 2;
                        uint32_t hv, lv;
                        split_pair(o0, o1, hv, lv);
                        size_t o = (size_t)row * (FFD / 2) + q;
                        Dh[o] = hv; Dl[o] = lv;
                    }
                }
            }
        }
    } else {
#pragma unroll
        for (int mt = 0; mt < 4; mt++) {
#pragma unroll
            for (int half = 0; half < 2; half++) {
                int row = m0 + warpM * 64 + mt * 16 + gid + half * 8;
                float* Crow = C + (size_t)row * N + n0 + warpN * 32;
#pragma unroll
                for (int nt = 0; nt < 4; nt++) {
                    int col = nt * 8 + tig * 2;
                    float2 r;
                    r.x = c[mt][nt][half * 2 + 0];
                    r.y = c[mt][nt][half * 2 + 1];
                    if (FLAGS & 1) {
                        float2 bb = *(const float2*)&bias[n0 + warpN * 32 + col];
                        r.x += bb.x; r.y += bb.y;
                    }
                    if (FLAGS & 2) {
                        float2 cc = *(const float2*)&Crow[col];
                        r.x += cc.x; r.y += cc.y;
                    }
                    *(float2*)&Crow[col] = r;
                }
            }
        }
    }
}

// ---------------- tensor-core flash attention (chunked split-softmax) ----------------
#define ATSU 36
__global__ void __launch_bounds__(128)
attn_mma_kernel(const uint32_t* __restrict__ qhp, const uint32_t* __restrict__ qlp,
                const uint32_t* __restrict__ khp, const uint32_t* __restrict__ klp,
                const uint32_t* __restrict__ vth, const uint32_t* __restrict__ vtl,
                uint32_t* __restrict__ oh, uint32_t* __restrict__ ol,
                float* __restrict__ pacc, float* __restrict__ pml) {
    __shared__ uint32_t sm0[64 * ATSU], sm1[64 * ATSU];
    __shared__ uint32_t sm2[64 * ATSU], sm3[64 * ATSU];
    int cid = blockIdx.x, h = blockIdx.y, b = blockIdx.z;
    int kh = h >> 2;
    int qt, ktLo, ktHi, chunk, full;
    if (cid < QSPLIT) { qt = cid; ktLo = 0; ktHi = qt + 1; chunk = 0; full = 1; }
    else {
        int t = cid - QSPLIT;
        qt = QSPLIT + (t >> 1);
        chunk = t & 1;
        int mid = (qt + 1) >> 1;
        ktLo = chunk ? mid : 0;
        ktHi = chunk ? qt + 1 : mid;
        full = 0;
    }
    int tid = threadIdx.x, lane = tid & 31, warp = tid >> 5;
    int gid = lane >> 2, tig = lane & 3;

    // Q fill
    for (int i = tid; i < 1024; i += 128) {
        int plane = i >> 9, rem = i & 511, row = rem >> 3, ch = (rem & 7) * 4;
        const uint32_t* src = plane ? qlp : qhp;
        uint4 v = *(const uint4*)&src[(size_t)(b * KTOK + qt * 64 + row) * 512 + h * 32 + ch];
        uint32_t* dst = plane ? sm1 : sm0;
        *(uint4*)&dst[row * ATSU + ch] = v;
    }
    __syncthreads();
    uint32_t qh[4][4], ql[4][4];
    {
        int r0 = warp * 16 + gid, r1 = r0 + 8;
#pragma unroll
        for (int kc = 0; kc < 4; kc++) {
            int p = kc * 8 + tig;
            qh[kc][0] = sm0[r0 * ATSU + p];
            qh[kc][1] = sm0[r1 * ATSU + p];
            qh[kc][2] = sm0[r0 * ATSU + p + 4];
            qh[kc][3] = sm0[r1 * ATSU + p + 4];
            ql[kc][0] = sm1[r0 * ATSU + p];
            ql[kc][1] = sm1[r1 * ATSU + p];
            ql[kc][2] = sm1[r0 * ATSU + p + 4];
            ql[kc][3] = sm1[r1 * ATSU + p + 4];
        }
    }

    float accO[8][4];
#pragma unroll
    for (int nt = 0; nt < 8; nt++)
#pragma unroll
        for (int f = 0; f < 4; f++) accO[nt][f] = 0.f;
    float m0r = -1e30f, m1r = -1e30f, l0r = 0.f, l1r = 0.f;

    for (int kt = ktLo; kt < ktHi; kt++) {
        __syncthreads();
        for (int i = tid; i < 1024; i += 128) {
            int plane = i >> 9, rem = i & 511, row = rem >> 3, ch = (rem & 7) * 4;
            const uint32_t* src = plane ? klp : khp;
            uint4 v = *(const uint4*)&src[(size_t)(b * KTOK + kt * 64 + row) * 128 + kh * 32 + ch];
            uint32_t* dst = plane ? sm1 : sm0;
            *(uint4*)&dst[row * ATSU + ch] = v;
        }
        for (int i = tid; i < 1024; i += 128) {
            int plane = i >> 9, rem = i & 511, d = rem >> 3, ch = (rem & 7) * 4;
            const uint32_t* src = plane ? vtl : vth;
            uint4 v = *(const uint4*)&src[(size_t)((b * KVHEAD + kh) * HEADD + d) * TPH + kt * 32 + ch];
            uint32_t* dst = plane ? sm3 : sm2;
            *(uint4*)&dst[d * ATSU + ch] = v;
        }
        __syncthreads();

        float s[8][4];
#pragma unroll
        for (int nt = 0; nt < 8; nt++)
#pragma unroll
            for (int f = 0; f < 4; f++) s[nt][f] = 0.f;
#pragma unroll
        for (int kc = 0; kc < 4; kc++) {
#pragma unroll
            for (int nt = 0; nt < 8; nt++) {
                int tok = nt * 8 + gid;
                uint32_t bh[2], bl[2];
                bh[0] = sm0[tok * ATSU + kc * 8 + tig];
                bh[1] = sm0[tok * ATSU + kc * 8 + tig + 4];
                bl[0] = sm1[tok * ATSU + kc * 8 + tig];
                bl[1] = sm1[tok * ATSU + kc * 8 + tig + 4];
                mma_bf16(s[nt], qh[kc], bh);
                mma_bf16(s[nt], ql[kc], bh);
                mma_bf16(s[nt], qh[kc], bl);
            }
        }
        if (kt == qt) {
            int r0 = warp * 16 + gid, r1 = r0 + 8;
#pragma unroll
            for (int nt = 0; nt < 8; nt++) {
                int c0 = nt * 8 + 2 * tig, c1 = c0 + 1;
                if (c0 > r0) s[nt][0] = -1e30f;
                if (c1 > r0) s[nt][1] = -1e30f;
                if (c0 > r1) s[nt][2] = -1e30f;
                if (c1 > r1) s[nt][3] = -1e30f;
            }
        }
        float mx0 = -1e30f, mx1 = -1e30f;
#pragma unroll
        for (int nt = 0; nt < 8; nt++) {
            mx0 = fmaxf(mx0, fmaxf(s[nt][0], s[nt][1]));
            mx1 = fmaxf(mx1, fmaxf(s[nt][2], s[nt][3]));
        }
        mx0 = fmaxf(mx0, __shfl_xor_sync(0xffffffffu, mx0, 1));
        mx0 = fmaxf(mx0, __shfl_xor_sync(0xffffffffu, mx0, 2));
        mx1 = fmaxf(mx1, __shfl_xor_sync(0xffffffffu, mx1, 1));
        mx1 = fmaxf(mx1, __shfl_xor_sync(0xffffffffu, mx1, 2));
        float mn0 = fmaxf(m0r, mx0), mn1 = fmaxf(m1r, mx1);
        float cor0 = __expf(m0r - mn0), cor1 = __expf(m1r - mn1);
        float ps0 = 0.f, ps1 = 0.f;
#pragma unroll
        for (int nt = 0; nt < 8; nt++) {
            s[nt][0] = __expf(s[nt][0] - mn0);
            s[nt][1] = __expf(s[nt][1] - mn0);
            s[nt][2] = __expf(s[nt][2] - mn1);
            s[nt][3] = __expf(s[nt][3] - mn1);
            ps0 += s[nt][0] + s[nt][1];
            ps1 += s[nt][2] + s[nt][3];
        }
        ps0 += __shfl_xor_sync(0xffffffffu, ps0, 1);
        ps0 += __shfl_xor_sync(0xffffffffu, ps0, 2);
        ps1 += __shfl_xor_sync(0xffffffffu, ps1, 1);
        ps1 += __shfl_xor_sync(0xffffffffu, ps1, 2);
        l0r = l0r * cor0 + ps0;  m0r = mn0;
        l1r = l1r * cor1 + ps1;  m1r = mn1;
#pragma unroll
        for (int nt = 0; nt < 8; nt++) {
            accO[nt][0] *= cor0; accO[nt][1] *= cor0;
            accO[nt][2] *= cor1; accO[nt][3] *= cor1;
        }
#pragma unroll
        for (int kc = 0; kc < 4; kc++) {
            uint32_t ph[4], pl[4];
            split_pair(s[2 * kc][0],     s[2 * kc][1],     ph[0], pl[0]);
            split_pair(s[2 * kc][2],     s[2 * kc][3],     ph[1], pl[1]);
            split_pair(s[2 * kc + 1][0], s[2 * kc + 1][1], ph[2], pl[2]);
            split_pair(s[2 * kc + 1][2], s[2 * kc + 1][3], ph[3], pl[3]);
#pragma unroll
            for (int nt = 0; nt < 8; nt++) {
                int d = nt * 8 + gid;
                uint32_t vh[2], vl[2];
                vh[0] = sm2[d * ATSU + kc * 8 + tig];
                vh[1] = sm2[d * ATSU + kc * 8 + tig + 4];
                vl[0] = sm3[d * ATSU + kc * 8 + tig];
                vl[1] = sm3[d * ATSU + kc * 8 + tig + 4];
                mma_bf16(accO[nt], ph, vh);
                mma_bf16(accO[nt], pl, vh);
                mma_bf16(accO[nt], ph, vl);
            }
        }
    }
    int rl0 = warp * 16 + gid, rl1 = rl0 + 8;
    if (full) {
        float i0 = 1.f / l0r, i1 = 1.f / l1r;
        int row0 = b * KTOK + qt * 64 + rl0;
#pragma unroll
        for (int nt = 0; nt < 8; nt++) {
            int dp = (h * HEADD + nt * 8 + 2 * tig) >> 1;
            uint32_t hv, lv;
            split_pair(accO[nt][0] * i0, accO[nt][1] * i0, hv, lv);
            oh[(size_t)row0 * 512 + dp] = hv;
            ol[(size_t)row0 * 512 + dp] = lv;
            split_pair(accO[nt][2] * i1, accO[nt][3] * i1, hv, lv);
            oh[(size_t)(row0 + 8) * 512 + dp] = hv;
            ol[(size_t)(row0 + 8) * 512 + dp] = lv;
        }
    } else {
        int s = ((b * NHEAD + h) * NQS + (qt - QSPLIT)) * 2 + chunk;
        float* acc = pacc + (size_t)s * 64 * 64;
#pragma unroll
        for (int nt = 0; nt < 8; nt++) {
            int d = nt * 8 + 2 * tig;
            *(float2*)&acc[rl0 * 64 + d] = make_float2(accO[nt][0], accO[nt][1]);
            *(float2*)&acc[rl1 * 64 + d] = make_float2(accO[nt][2], accO[nt][3]);
        }
        if (tig == 0) {
            float* ml = pml + (size_t)s * 128;
            *(float2*)&ml[rl0 * 2] = make_float2(m0r, l0r);
            *(float2*)&ml[rl1 * 2] = make_float2(m1r, l1r);
        }
    }
}

// ---------------- attn merge (combine 2 chunk partials per split qt) ------------
__global__ void __launch_bounds__(128)
attn_merge_kernel(const float* __restrict__ pacc, const float* __restrict__ pml,
                  uint32_t* __restrict__ oh, uint32_t* __restrict__ ol) {
    int qt = QSPLIT + blockIdx.x;
    int h = blockIdx.y, b = blockIdx.z;
    int sbase = ((b * NHEAD + h) * NQS + (qt - QSPLIT)) * 2;
    const float* a0 = pacc + (size_t)(sbase + 0) * 64 * 64;
    const float* a1 = pacc + (size_t)(sbase + 1) * 64 * 64;
    const float* ml0 = pml + (size_t)(sbase + 0) * 128;
    const float* ml1 = pml + (size_t)(sbase + 1) * 128;
    int tid = threadIdx.x;
    for (int t = tid; t < 2048; t += 128) {
        int r = t >> 5, dp = t & 31;
        float2 q0 = *(const float2*)&ml0[r * 2];
        float2 q1 = *(const float2*)&ml1[r * 2];
        float M = fmaxf(q0.x, q1.x);
        float w0 = __expf(q0.x - M), w1 = __expf(q1.x - M);
        float inv = 1.f / (w0 * q0.y + w1 * q1.y);
        float2 v0 = *(const float2*)&a0[r * 64 + 2 * dp];
        float2 v1 = *(const float2*)&a1[r * 64 + 2 * dp];
        float o0 = (w0 * v0.x + w1 * v1.x) * inv;
        float o1 = (w0 * v0.y + w1 * v1.y) * inv;
        uint32_t hv, lv;
        split_pair(o0, o1, hv, lv);
        size_t row = (size_t)(b * KTOK + qt * 64 + r);
        oh[row * 512 + h * 32 + dp] = hv;
        ol[row * 512 + h * 32 + dp] = lv;
    }
}

// ---------------- launch ----------------
extern "C" void kernel_launch(void* const* d_in, const int* in_sizes, int n_in,
                              void* d_out, int out_size) {
    const int*   ids      = (const int*)d_in[0];
    const float* emb      = (const float*)d_in[1];
    const float* router_k = (const float*)d_in[2];
    const float* router_q = (const float*)d_in[3];
    const float* ln1      = (const float*)d_in[4];
    const float* ln2      = (const float*)d_in[5];
    const float* wq       = (const float*)d_in[6];
    const float* bq       = (const float*)d_in[7];
    const float* wk       = (const float*)d_in[8];
    const float* bk       = (const float*)d_in[9];
    const float* wv       = (const float*)d_in[10];
    const float* bv       = (const float*)d_in[11];
    const float* wo       = (const float*)d_in[12];
    const float* wg       = (const float*)d_in[13];
    const float* wu       = (const float*)d_in[14];
    const float* wd       = (const float*)d_in[15];
    float* hidden = (float*)d_out;

    float *x, *qkv, *pooled, *scores, *bqkv, *pacc, *pml;
    int* tok;
    uint32_t *wqkvh, *wqkvl, *woh, *wol, *wguh, *wgul, *wdh, *wdl;
    uint32_t *hh, *hl, *oh, *ol, *gh, *gl;
    uint32_t *qhp, *qlp, *khp, *klp, *vth, *vtl;
    cudaGetSymbolAddress((void**)&x, g_x);
    cudaGetSymbolAddress((void**)&qkv, g_qkv);
    cudaGetSymbolAddress((void**)&pooled, g_pool);
    cudaGetSymbolAddress((void**)&scores, g_scores);
    cudaGetSymbolAddress((void**)&tok, g_tok);
    cudaGetSymbolAddress((void**)&bqkv, g_bqkv);
    cudaGetSymbolAddress((void**)&wqkvh, g_wqkvh); cudaGetSymbolAddress((void**)&wqkvl, g_wqkvl);
    cudaGetSymbolAddress((void**)&woh, g_woh);     cudaGetSymbolAddress((void**)&wol, g_wol);
    cudaGetSymbolAddress((void**)&wguh, g_wguh);   cudaGetSymbolAddress((void**)&wgul, g_wgul);
    cudaGetSymbolAddress((void**)&wdh, g_wdh);     cudaGetSymbolAddress((void**)&wdl, g_wdl);
    cudaGetSymbolAddress((void**)&hh, g_hh);       cudaGetSymbolAddress((void**)&hl, g_hl);
    cudaGetSymbolAddress((void**)&oh, g_oh);       cudaGetSymbolAddress((void**)&ol, g_ol);
    cudaGetSymbolAddress((void**)&gh, g_gh);       cudaGetSymbolAddress((void**)&gl, g_gl);
    cudaGetSymbolAddress((void**)&qhp, g_qhp);     cudaGetSymbolAddress((void**)&qlp, g_qlp);
    cudaGetSymbolAddress((void**)&khp, g_khp);     cudaGetSymbolAddress((void**)&klp, g_klp);
    cudaGetSymbolAddress((void**)&vth, g_vth);     cudaGetSymbolAddress((void**)&vtl, g_vtl);
    cudaGetSymbolAddress((void**)&pacc, g_pacc);   cudaGetSymbolAddress((void**)&pml, g_pml);

    cudaFuncSetAttribute(pgemm_kernel<0>, cudaFuncAttributeMaxDynamicSharedMemorySize, SM_PGEMM);
    cudaFuncSetAttribute(pgemm_kernel<1>, cudaFuncAttributeMaxDynamicSharedMemorySize, SM_PGEMM);
    cudaFuncSetAttribute(pgemm_kernel<2>, cudaFuncAttributeMaxDynamicSharedMemorySize, SM_PGEMM);
    cudaFuncSetAttribute(pgemm_kernel<4>, cudaFuncAttributeMaxDynamicSharedMemorySize, SM_PGEMM);

    embed_kernel<<<BATCH * SEQ, 256>>>(ids, emb, hidden);

    // ---- weight prepacks ----
    prepack_gu_kernel<<<NLAYER * 512 * 1408 / 256, 256>>>(wg, wu, wguh, wgul);
    prepack_qkv_kernel<<<NLAYER * 512 * 384 / 256, 256>>>(wq, wk, wv, wqkvh, wqkvl);
    prepack_kernel<<<NLAYER * 512 * 1024 / 1024, 256>>>(wo, woh, wol, 256, 1024);
    prepack_kernel<<<NLAYER * 1408 * 1024 / 1024, 256>>>(wd, wdh, wdl, 256, 1024);
    fuse_bias_kernel<<<NLAYER * NQKV / 256, 256>>>(bq, bk, bv, bqkv);

    for (int blk = 0; blk < NBLK; blk++) {
        int li0 = blk * BPL;
        pool_kernel<<<BATCH * NSEG, 256>>>(hidden, pooled);
        router_kernel<<<dim3(NSEG, BATCH), 128>>>(
            pooled, router_k + (size_t)blk * DIM * RANKR,
            router_q + (size_t)blk * NQRY * RANKR, scores);
        select_kernel<<<BATCH, 256>>>(scores, tok);
        gather_norm_kernel<<<BT, 256>>>(hidden, tok, ln1 + (size_t)li0 * DIM, x, hh, hl);

        for (int j = 0; j < BPL; j++) {
            int li = li0 + j;
            size_t oqkv = (size_t)li * 512 * NQKV;
            size_t oo   = (size_t)li * 512 * 1024;
            size_t ogu  = (size_t)li * 512 * NGU;
            size_t od   = (size_t)li * 1408 * 1024;

            if (j > 0)
                rmsnorm_kernel<<<BT, 256>>>(x, ln1 + (size_t)li * DIM, hh, hl);
            pgemm_kernel<1><<<dim3(NQKV / 128, BT / 128), 256, SM_PGEMM>>>(
                hh, hl, wqkvh + oqkv, wqkvl + oqkv, bqkv + (size_t)li * NQKV,
                qkv, nullptr, nullptr, BT, NQKV, 512);
            prep_attn_kernel<<<BT / 2, 128>>>(qkv, tok, qhp, qlp, khp, klp, vth, vtl);
            attn_mma_kernel<<<dim3(NCID, NHEAD, BATCH), 128>>>(
                qhp, qlp, khp, klp, vth, vtl, oh, ol, pacc, pml);
            attn_merge_kernel<<<dim3(NQS, NHEAD, BATCH), 128>>>(pacc, pml, oh, ol);
            pgemm_kernel<2><<<dim3(8, BT / 128), 256, SM_PGEMM>>>(
                oh, ol, woh + oo, wol + oo, nullptr, x, nullptr, nullptr, BT, 1024, 512);
            rmsnorm_kernel<<<BT, 256>>>(x, ln2 + (size_t)li * DIM, hh, hl);
            pgemm_kernel<4><<<dim3(NGU / 128, BT / 128), 256, SM_PGEMM>>>(
                hh, hl, wguh + ogu, wgul + ogu, nullptr, nullptr, gh, gl, BT, NGU, 512);
            pgemm_kernel<2><<<dim3(8, BT / 128), 256, SM_PGEMM>>>(
                gh, gl, wdh + od, wdl + od, nullptr, x, nullptr, nullptr, BT, 1024, 1408);
        }
        scatter_kernel<<<BT, 256>>>(x, tok, hidden);
    }
}

// round 16
// speedup vs baseline: 3.3426x; 1.0034x over previous
#include <cuda_runtime.h>
#include <cuda_bf16.h>
#include <math.h>
#include <stdint.h>

// ---------------- problem constants ----------------
#define BATCH 2
#define SEQ   4096
#define DIM   1024
#define NHEAD 16
#define KVHEAD 4
#define HEADD 64
#define FFD   2816
#define NSEG  256
#define SEGLEN 16
#define KSEG  76
#define KTOK  (KSEG*SEGLEN)      // 1216
#define BT    (BATCH*KTOK)       // 2432 = 19*128 = 38*64
#define NLAYER 12
#define NBLK  2
#define BPL   6
#define RANKR 16
#define NQRY  8
#define NQKV  1536
#define NGU   5632
#define TPH   (KTOK/2)           // 608 token pairs per batch
// attention split-softmax config
#define QSPLIT 11
#define NQS    8
#define NCID   (QSPLIT + 2*NQS)  // 27

// ---------------- scratch (device globals; no allocs allowed) ----------------
__device__ float g_x   [BT*DIM];
__device__ float g_vbuf[BT*256];
__device__ float g_pool[BATCH*NSEG*DIM];
__device__ float g_scores[BATCH*NSEG];
__device__ int   g_tok [BATCH*KTOK];
__device__ float g_bqkv[NLAYER*NQKV];   // permuted q/k bias

// pre-packed bf16 hi/lo pair weights: [L][K/2][N] u32
__device__ uint32_t g_wqkvh[NLAYER*512*NQKV], g_wqkvl[NLAYER*512*NQKV];  // q/k cols rope-interleaved
__device__ uint32_t g_woh  [NLAYER*512*1024], g_wol  [NLAYER*512*1024];
__device__ uint32_t g_wguh [NLAYER*512*NGU],  g_wgul [NLAYER*512*NGU];   // gate/up col-interleaved
__device__ uint32_t g_wdh  [NLAYER*1408*1024],g_wdl  [NLAYER*1408*1024];
// activation pair buffers [M][K/2]
__device__ uint32_t g_hh[BT*DIM/2],  g_hl[BT*DIM/2];
__device__ uint32_t g_oh[BT*DIM/2],  g_ol[BT*DIM/2];
__device__ uint32_t g_gh[BT*FFD/2],  g_gl[BT*FFD/2];
// attention pre-split planes
__device__ uint32_t g_qhp[BT*512],  g_qlp[BT*512];
__device__ uint32_t g_khp[BT*128],  g_klp[BT*128];
__device__ uint32_t g_vth[BATCH*KVHEAD*HEADD*TPH], g_vtl[BATCH*KVHEAD*HEADD*TPH];
// split-softmax partials
__device__ float g_pacc[512*64*64];
__device__ float g_pml [512*64*2];

// ---------------- helpers ----------------
__device__ __forceinline__ void split_pair(float x0, float x1, uint32_t& hp, uint32_t& lp) {
    uint32_t h;
    asm("cvt.rn.bf16x2.f32 %0, %1, %2;" : "=r"(h) : "f"(x1), "f"(x0));
    float h0 = __uint_as_float(h << 16);
    float h1 = __uint_as_float(h & 0xFFFF0000u);
    float l0 = x0 - h0, l1 = x1 - h1;
    uint32_t l;
    asm("cvt.rn.bf16x2.f32 %0, %1, %2;" : "=r"(l) : "f"(l1), "f"(l0));
    hp = h; lp = l;
}
__device__ __forceinline__ uint32_t smem_u32(const void* p) {
    uint32_t a;
    asm("{ .reg .u64 t; cvta.to.shared.u64 t, %1; cvt.u32.u64 %0, t; }" : "=r"(a) : "l"(p));
    return a;
}
__device__ __forceinline__ void cpasync16(uint32_t dst, const void* src) {
    asm volatile("cp.async.cg.shared.global [%0], [%1], 16;" :: "r"(dst), "l"(src));
}
#define CP_COMMIT() asm volatile("cp.async.commit_group;" ::: "memory")
#define CP_WAIT1()  asm volatile("cp.async.wait_group 1;" ::: "memory")
#define CP_WAIT0()  asm volatile("cp.async.wait_group 0;" ::: "memory")

// rope column permutation: new col c (within 64-wide head) -> old col
__device__ __forceinline__ int rope_perm(int c) {
    int h = c >> 6, r = c & 63, i = r >> 1;
    return h * 64 + ((r & 1) ? (i + 32) : i);
}

// ---------------- weight prepacks ----------------
__global__ void prepack_kernel(const float* __restrict__ src,
                               uint32_t* __restrict__ dh, uint32_t* __restrict__ dl,
                               int n4row, int N) {
    int idx = blockIdx.x * 256 + threadIdx.x;
    int p = idx / n4row, c = (idx - p * n4row) * 4;
    const float* r0 = src + (size_t)(2 * p) * N + c;
    float4 a = *(const float4*)r0;
    float4 b = *(const float4*)(r0 + N);
    uint4 h, l;
    split_pair(a.x, b.x, h.x, l.x);
    split_pair(a.y, b.y, h.y, l.y);
    split_pair(a.z, b.z, h.z, l.z);
    split_pair(a.w, b.w, h.w, l.w);
    *(uint4*)(dh + (size_t)idx * 4) = h;
    *(uint4*)(dl + (size_t)idx * 4) = l;
}

// fused QKV with rope column interleave on q/k
__global__ void prepack_qkv_kernel(const float* __restrict__ wq,
                                   const float* __restrict__ wk,
                                   const float* __restrict__ wv,
                                   uint32_t* __restrict__ dh, uint32_t* __restrict__ dl) {
    int idx = blockIdx.x * 256 + threadIdx.x;       // uint4 over L*512*384
    int l = idx / (512 * 384);
    int rem = idx - l * (512 * 384);
    int p = rem / 384, col0 = (rem - p * 384) * 4;
    uint4 h, l4;
    uint32_t* hp = (uint32_t*)&h;
    uint32_t* lp = (uint32_t*)&l4;
#pragma unroll
    for (int e = 0; e < 4; e++) {
        int nc = col0 + e;
        const float* s0;
        if (nc < 1024)      s0 = wq + ((size_t)(l * 1024 + 2 * p)) * 1024 + rope_perm(nc);
        else if (nc < 1280) s0 = wk + ((size_t)(l * 1024 + 2 * p)) * 256 + rope_perm(nc - 1024);
        else                s0 = wv + ((size_t)(l * 1024 + 2 * p)) * 256 + (nc - 1280);
        int srcN = (nc < 1024) ? 1024 : 256;
        split_pair(s0[0], s0[srcN], hp[e], lp[e]);
    }
    *(uint4*)(dh + (size_t)idx * 4) = h;
    *(uint4*)(dl + (size_t)idx * 4) = l4;
}

__global__ void prepack_gu_kernel(const float* __restrict__ wg,
                                  const float* __restrict__ wu,
                                  uint32_t* __restrict__ dh, uint32_t* __restrict__ dl) {
    int idx = blockIdx.x * 256 + threadIdx.x;
    int l = idx / (512 * 1408);
    int rem = idx - l * (512 * 1408);
    int p = rem / 1408, q = rem - p * 1408;
    size_t row0 = (size_t)(l * 1024 + 2 * p);
    const float* g0 = wg + row0 * 2816 + 2 * q;
    const float* u0 = wu + row0 * 2816 + 2 * q;
    float2 ga = *(const float2*)g0;
    float2 gb = *(const float2*)(g0 + 2816);
    float2 ua = *(const float2*)u0;
    float2 ub = *(const float2*)(u0 + 2816);
    uint4 h, l4;
    split_pair(ga.x, gb.x, h.x, l4.x);
    split_pair(ga.y, gb.y, h.y, l4.y);
    split_pair(ua.x, ub.x, h.z, l4.z);
    split_pair(ua.y, ub.y, h.w, l4.w);
    *(uint4*)(dh + (size_t)idx * 4) = h;
    *(uint4*)(dl + (size_t)idx * 4) = l4;
}

__global__ void fuse_bias_kernel(const float* __restrict__ bq,
                                 const float* __restrict__ bk,
                                 const float* __restrict__ bv,
                                 float* __restrict__ dst) {
    int i = blockIdx.x * 256 + threadIdx.x;
    int l = i / NQKV, j = i - l * NQKV;
    float v;
    if (j < 1024)      v = bq[l * 1024 + rope_perm(j)];
    else if (j < 1280) v = bk[l * 256 + rope_perm(j - 1024)];
    else               v = bv[l * 256 + j - 1280];
    dst[i] = v;
}

// ---------------- embed / pool / router / select / scatter ----------------
__global__ void embed_kernel(const int* __restrict__ ids,
                             const float* __restrict__ emb,
                             float* __restrict__ hidden) {
    int row = blockIdx.x;
    int id  = ids[row];
    const float4* src = (const float4*)(emb + (size_t)id * DIM);
    float4* dst = (float4*)(hidden + (size_t)row * DIM);
    dst[threadIdx.x] = src[threadIdx.x];
}

__global__ void pool_kernel(const float* __restrict__ hidden,
                            float* __restrict__ pooled) {
    int b = blockIdx.x >> 8, n = blockIdx.x & 255;
    const float* base = hidden + ((size_t)b * SEQ + n * SEGLEN) * DIM + threadIdx.x * 4;
    float4 acc = make_float4(0.f, 0.f, 0.f, 0.f);
#pragma unroll
    for (int t = 0; t < SEGLEN; t++) {
        float4 v = *(const float4*)(base + (size_t)t * DIM);
        acc.x += v.x; acc.y += v.y; acc.z += v.z; acc.w += v.w;
    }
    const float s = 1.f / SEGLEN;
    acc.x *= s; acc.y *= s; acc.z *= s; acc.w *= s;
    *(float4*)(pooled + ((size_t)b * NSEG + n) * DIM + threadIdx.x * 4) = acc;
}

__global__ void router_kernel(const float* __restrict__ pooled,
                              const float* __restrict__ rk,
                              const float* __restrict__ rq,
                              float* __restrict__ scores) {
    int n = blockIdx.x, b = blockIdx.y;
    const float* p = pooled + ((size_t)b * NSEG + n) * DIM;
    __shared__ float part[128];
    int tid = threadIdx.x;
    int r = tid & 15, g = tid >> 4;
    float sum = 0.f;
    int d0 = g * 128;
    for (int d = d0; d < d0 + 128; d++) sum += p[d] * rk[d * RANKR + r];
    part[tid] = sum;
    __syncthreads();
    if (tid < RANKR) {
        float key = 0.f;
        for (int gg = 0; gg < 8; gg++) key += part[gg * 16 + tid];
        part[tid] = key;
    }
    __syncthreads();
    if (tid == 0) {
        float best = -1e30f;
        for (int qq = 0; qq < NQRY; qq++) {
            float dv = 0.f;
            for (int rr = 0; rr < RANKR; rr++) dv += rq[qq * RANKR + rr] * part[rr];
            best = fmaxf(best, dv);
        }
        scores[b * NSEG + n] = best;
    }
}

__global__ void select_kernel(const float* __restrict__ scores,
                              int* __restrict__ tok) {
    int b = blockIdx.x;
    __shared__ float s[NSEG];
    __shared__ int pf[NSEG];
    int i = threadIdx.x;
    float mine = scores[b * NSEG + i];
    s[i] = mine;
    __syncthreads();
    int rank = 0;
    for (int j = 0; j < NSEG; j++) {
        float o = s[j];
        rank += (o > mine) || (o == mine && j < i);
    }
    int sel = (rank < KSEG) ? 1 : 0;
    pf[i] = sel;
    __syncthreads();
    for (int off = 1; off < NSEG; off <<= 1) {
        int add = (i >= off) ? pf[i - off] : 0;
        __syncthreads();
        pf[i] += add;
        __syncthreads();
    }
    if (sel) {
        int p = pf[i] - 1;
        int* dst = tok + b * KTOK + p * SEGLEN;
        int base = i * SEGLEN;
#pragma unroll
        for (int t = 0; t < SEGLEN; t++) dst[t] = base + t;
    }
}

__global__ void scatter_kernel(const float* __restrict__ x,
                               const int* __restrict__ tok,
                               float* __restrict__ hidden) {
    int row = blockIdx.x;
    int b = row / KTOK;
    int tk = tok[row];
    const float4* src = (const float4*)(x + (size_t)row * DIM);
    float4* dst = (float4*)(hidden + ((size_t)b * SEQ + tk) * DIM);
    dst[threadIdx.x] = src[threadIdx.x];
}

// ---------------- RMSNorm ----------------
__device__ __forceinline__ void rms_body(float4 v, const float* w, int row, int t,
                                         uint32_t* oh, uint32_t* ol) {
    float ss = v.x * v.x + v.y * v.y + v.z * v.z + v.w * v.w;
#pragma unroll
    for (int d = 16; d >= 1; d >>= 1) ss += __shfl_xor_sync(0xffffffffu, ss, d);
    __shared__ float ws[8];
    __shared__ float tot;
    if ((t & 31) == 0) ws[t >> 5] = ss;
    __syncthreads();
    if (t == 0) {
        float a = 0.f;
        for (int wgi = 0; wgi < 8; wgi++) a += ws[wgi];
        tot = a;
    }
    __syncthreads();
    float inv = rsqrtf(tot * (1.f / DIM) + 1e-6f);
    float4 wv = ((const float4*)w)[t];
    float o0 = v.x * inv * wv.x, o1 = v.y * inv * wv.y;
    float o2 = v.z * inv * wv.z, o3 = v.w * inv * wv.w;
    uint32_t h0, l0, h1, l1;
    split_pair(o0, o1, h0, l0);
    split_pair(o2, o3, h1, l1);
    size_t base = (size_t)row * (DIM / 2) + t * 2;
    *(uint2*)&oh[base] = make_uint2(h0, h1);
    *(uint2*)&ol[base] = make_uint2(l0, l1);
}

__global__ void rmsnorm_kernel(const float* __restrict__ x,
                               const float* __restrict__ w,
                               uint32_t* __restrict__ oh,
                               uint32_t* __restrict__ ol) {
    int row = blockIdx.x, t = threadIdx.x;
    float4 v = ((const float4*)(x + (size_t)row * DIM))[t];
    rms_body(v, w, row, t, oh, ol);
}

__global__ void gather_norm_kernel(const float* __restrict__ hidden,
                                   const int* __restrict__ tok,
                                   const float* __restrict__ w,
                                   float* __restrict__ x,
                                   uint32_t* __restrict__ oh,
                                   uint32_t* __restrict__ ol) {
    int row = blockIdx.x, t = threadIdx.x;
    int b = row / KTOK;
    int tk = tok[row];
    float4 v = ((const float4*)(hidden + ((size_t)b * SEQ + tk) * DIM))[t];
    ((float4*)(x + (size_t)row * DIM))[t] = v;
    rms_body(v, w, row, t, oh, ol);
}

// ---------------- prep_v: transpose V rows into [d][tokpair] pair planes --------
__global__ void __launch_bounds__(256)
prep_v_kernel(const float* __restrict__ vbuf,
              uint32_t* __restrict__ vth, uint32_t* __restrict__ vtl) {
    int p = blockIdx.x;                 // BT/2 token pairs
    int b = p / TPH;
    int lp = p - b * TPH;
    int r0 = b * KTOK + lp * 2;
    int t = threadIdx.x;                // 256 = KVHEAD*HEADD
    int kvh = t >> 6, d = t & 63;
    float v0 = vbuf[(size_t)r0 * 256 + t];
    float v1 = vbuf[(size_t)(r0 + 1) * 256 + t];
    uint32_t h, l;
    split_pair(v0, v1, h, l);
    size_t o = (size_t)((b * KVHEAD + kvh) * HEADD + d) * TPH + lp;
    vth[o] = h; vtl[o] = l;
}

// ---------------- bf16 MMA primitive ----------------
__device__ __forceinline__ void mma_bf16(float c[4], const uint32_t a[4], const uint32_t b[2]) {
    asm volatile(
        "mma.sync.aligned.m16n8k16.row.col.f32.bf16.bf16.f32 "
        "{%0,%1,%2,%3}, {%4,%5,%6,%7}, {%8,%9}, {%0,%1,%2,%3};\n"
        : "+f"(c[0]), "+f"(c[1]), "+f"(c[2]), "+f"(c[3])
        : "r"(a[0]), "r"(a[1]), "r"(a[2]), "r"(a[3]), "r"(b[0]), "r"(b[1]));
}

// ---------------- pair-format split-bf16 (3xMMA) GEMM, cp.async 2-stage ---------
// FLAGS: 0 plain, 1 +bias, 2 +residual, 4 silu-pair epilogue, 8 qkv+rope epilogue
// MT: number of 32-row M groups (4 -> 128-row tile, 2 -> 64-row tile)
#define ASU 20
#define BSU 136
#define B_STG (16 * BSU)

template <int FLAGS, int MT>
__global__ void __launch_bounds__(256, 2)
pgemm_kernel(const uint32_t* __restrict__ Ahp, const uint32_t* __restrict__ Alp,
             const uint32_t* __restrict__ Whp, const uint32_t* __restrict__ Wlp,
             const float* __restrict__ bias,
             float* __restrict__ C,
             uint32_t* __restrict__ Dh, uint32_t* __restrict__ Dl,
             uint32_t* __restrict__ Eh, uint32_t* __restrict__ El,
             const int* __restrict__ tok,
             int M, int N, int K2) {
    constexpr int MROWS = MT * 32;
    constexpr int A_STG = MROWS * ASU;
    constexpr int ACH = MROWS * 4;          // uint4 chunks per A plane
    constexpr int STG_U32 = 2 * A_STG + 2 * B_STG;
    extern __shared__ uint32_t sgm[];
    uint32_t sb = smem_u32(sgm);
    int tid = threadIdx.x, lane = tid & 31, warp = tid >> 5;
    int warpM = warp & 1, warpN = warp >> 1;
    int m0 = blockIdx.y * MROWS, n0 = blockIdx.x * 128;
    int gid = lane >> 2, tig = lane & 3;
    int NT = K2 / 16;

    int pr0 = tid >> 5, cg0 = (tid & 31) * 4;
    int pr1 = (tid + 256) >> 5, cg1 = ((tid + 256) & 31) * 4;

    float c[MT][4][4];
#pragma unroll
    for (int i = 0; i < MT; i++)
#pragma unroll
        for (int j = 0; j < 4; j++)
#pragma unroll
            for (int f = 0; f < 4; f++) c[i][j][f] = 0.f;

#define ISSUE_TILE(kt, buf) do {                                               \
        uint32_t st = sb + (buf) * (STG_U32 * 4);                              \
        int p0 = (kt) * 16;                                                    \
        _Pragma("unroll")                                                      \
        for (int ii = 0; ii < ACH / 256; ii++) {                               \
            int ch = tid + 256 * ii;                                           \
            int arow = ch >> 2, apc = (ch & 3) * 4;                            \
            size_t ga = (size_t)(m0 + arow) * K2 + p0 + apc;                   \
            uint32_t sa = st + (arow * ASU + apc) * 4;                         \
            cpasync16(sa, &Ahp[ga]);                                           \
            cpasync16(sa + A_STG * 4, &Alp[ga]);                               \
        }                                                                      \
        size_t b0 = (size_t)(p0 + pr0) * N + n0 + cg0;                         \
        uint32_t sb0 = st + (2 * A_STG + pr0 * BSU + cg0) * 4;                 \
        cpasync16(sb0, &Whp[b0]);                                              \
        cpasync16(sb0 + B_STG * 4, &Wlp[b0]);                                  \
        size_t b1 = (size_t)(p0 + pr1) * N + n0 + cg1;                         \
        uint32_t sb1 = st + (2 * A_STG + pr1 * BSU + cg1) * 4;                 \
        cpasync16(sb1, &Whp[b1]);                                              \
        cpasync16(sb1 + B_STG * 4, &Wlp[b1]);                                  \
        CP_COMMIT();                                                           \
    } while (0)

    ISSUE_TILE(0, 0);
    if (NT > 1) ISSUE_TILE(1, 1);

    for (int kt = 0; kt < NT; kt++) {
        int buf = kt & 1;
        if (kt + 1 < NT) CP_WAIT1(); else CP_WAIT0();
        __syncthreads();
        uint32_t* sAh = sgm + buf * STG_U32;
        uint32_t* sAl = sAh + A_STG;
        uint32_t* sBh = sAl + A_STG;
        uint32_t* sBl = sBh + B_STG;
#pragma unroll
        for (int kk = 0; kk < 2; kk++) {
            int kp = kk * 8;
            uint32_t bh[4][2], bl[4][2];
#pragma unroll
            for (int nt = 0; nt < 4; nt++) {
                int cb = warpN * 32 + nt * 8 + gid;
                bh[nt][0] = sBh[(kp + tig) * BSU + cb];
                bh[nt][1] = sBh[(kp + tig + 4) * BSU + cb];
                bl[nt][0] = sBl[(kp + tig) * BSU + cb];
                bl[nt][1] = sBl[(kp + tig + 4) * BSU + cb];
            }
#pragma unroll
            for (int mt = 0; mt < MT; mt++) {
                int rb = warpM * (MT * 16) + mt * 16 + gid;
                uint32_t ah[4], al[4];
                ah[0] = sAh[rb * ASU + kp + tig];
                ah[1] = sAh[(rb + 8) * ASU + kp + tig];
                ah[2] = sAh[rb * ASU + kp + tig + 4];
                ah[3] = sAh[(rb + 8) * ASU + kp + tig + 4];
                al[0] = sAl[rb * ASU + kp + tig];
                al[1] = sAl[(rb + 8) * ASU + kp + tig];
                al[2] = sAl[rb * ASU + kp + tig + 4];
                al[3] = sAl[(rb + 8) * ASU + kp + tig + 4];
#pragma unroll
                for (int nt = 0; nt < 4; nt++) {
                    mma_bf16(c[mt][nt], ah, bh[nt]);
                    mma_bf16(c[mt][nt], al, bh[nt]);
                    mma_bf16(c[mt][nt], ah, bl[nt]);
                }
            }
        }
        __syncthreads();
        if (kt + 2 < NT) ISSUE_TILE(kt + 2, buf);
    }
#undef ISSUE_TILE
    // ---- epilogue ----
    if (FLAGS == 8) {
        // qkv: bias + in-register RoPE (cols pre-interleaved) -> q/k pair planes; v -> fp32 buf
#pragma unroll
        for (int mt = 0; mt < MT; mt++) {
#pragma unroll
            for (int half = 0; half < 2; half++) {
                int row = m0 + warpM * (MT * 16) + mt * 16 + gid + half * 8;
                float fpos = (float)tok[row];
#pragma unroll
                for (int nt = 0; nt < 4; nt++) {
                    int col = n0 + warpN * 32 + nt * 8 + tig * 2;
                    float2 bb = *(const float2*)&bias[col];
                    float v0 = c[mt][nt][half * 2 + 0] + bb.x;
                    float v1 = c[mt][nt][half * 2 + 1] + bb.y;
                    if (col < 1280) {
                        int i = (col & 63) >> 1;
                        float invf = __powf(10000.f, -(float)(2 * i) / 64.f);
                        float sn, cs;
                        sincosf(fpos * invf, &sn, &cs);
                        float o0 = v0 * cs - v1 * sn;
                        float o1 = v1 * cs + v0 * sn;
                        uint32_t hv, lv;
                        if (col < 1024) {
                            split_pair(o0 * 0.125f, o1 * 0.125f, hv, lv);
                            size_t o = (size_t)row * 512 + (col >> 1);
                            Dh[o] = hv; Dl[o] = lv;
                        } else {
                            split_pair(o0, o1, hv, lv);
                            size_t o = (size_t)row * 128 + ((col - 1024) >> 1);
                            Eh[o] = hv; El[o] = lv;
                        }
                    } else {
                        *(float2*)&C[(size_t)row * 256 + (col - 1280)] = make_float2(v0, v1);
                    }
                }
            }
        }
    } else if (FLAGS == 4) {
#pragma unroll
        for (int mt = 0; mt < MT; mt++) {
#pragma unroll
            for (int half = 0; half < 2; half++) {
                int row = m0 + warpM * (MT * 16) + mt * 16 + gid + half * 8;
#pragma unroll
                for (int nt = 0; nt < 4; nt++) {
                    float v0 = c[mt][nt][half * 2 + 0];
                    float v1 = c[mt][nt][half * 2 + 1];
                    float p0 = __shfl_xor_sync(0xffffffffu, v0, 1);
                    float p1 = __shfl_xor_sync(0xffffffffu, v1, 1);
                    if ((tig & 1) == 0) {
                        float o0 = v0 / (1.f + __expf(-v0)) * p0;
                        float o1 = v1 / (1.f + __expf(-v1)) * p1;
                        int c0 = n0 + warpN * 32 + nt * 8 + 2 * tig;
                        int q = c0 >> 2;
                        uint32_t hv, lv;
                        split_pair(o0, o1, hv, lv);
                        size_t o = (size_t)row * (FFD / 2) + q;
                        Dh[o] = hv; Dl[o] = lv;
                    }
                }
            }
        }
    } else {
#pragma unroll
        for (int mt = 0; mt < MT; mt++) {
#pragma unroll
            for (int half = 0; half < 2; half++) {
                int row = m0 + warpM * (MT * 16) + mt * 16 + gid + half * 8;
                float* Crow = C + (size_t)row * N + n0 + warpN * 32;
#pragma unroll
                for (int nt = 0; nt < 4; nt++) {
                    int col = nt * 8 + tig * 2;
                    float2 r;
                    r.x = c[mt][nt][half * 2 + 0];
                    r.y = c[mt][nt][half * 2 + 1];
                    if (FLAGS & 1) {
                        float2 bb = *(const float2*)&bias[n0 + warpN * 32 + col];
                        r.x += bb.x; r.y += bb.y;
                    }
                    if (FLAGS & 2) {
                        float2 cc = *(const float2*)&Crow[col];
                        r.x += cc.x; r.y += cc.y;
                    }
                    *(float2*)&Crow[col] = r;
                }
            }
        }
    }
}
#define SM_PGEMM4 (2 * (2 * 128 * ASU + 2 * B_STG) * 4)
#define SM_PGEMM2 (2 * (2 * 64 * ASU + 2 * B_STG) * 4)

// ---------------- tensor-core flash attention (chunked split-softmax) ----------------
#define ATSU 36
__global__ void __launch_bounds__(128)
attn_mma_kernel(const uint32_t* __restrict__ qhp, const uint32_t* __restrict__ qlp,
                const uint32_t* __restrict__ khp, const uint32_t* __restrict__ klp,
                const uint32_t* __restrict__ vth, const uint32_t* __restrict__ vtl,
                uint32_t* __restrict__ oh, uint32_t* __restrict__ ol,
                float* __restrict__ pacc, float* __restrict__ pml) {
    __shared__ uint32_t sm0[64 * ATSU], sm1[64 * ATSU];
    __shared__ uint32_t sm2[64 * ATSU], sm3[64 * ATSU];
    int cid = blockIdx.x, h = blockIdx.y, b = blockIdx.z;
    int kh = h >> 2;
    int qt, ktLo, ktHi, chunk, full;
    if (cid < QSPLIT) { qt = cid; ktLo = 0; ktHi = qt + 1; chunk = 0; full = 1; }
    else {
        int t = cid - QSPLIT;
        qt = QSPLIT + (t >> 1);
        chunk = t & 1;
        int mid = (qt + 1) >> 1;
        ktLo = chunk ? mid : 0;
        ktHi = chunk ? qt + 1 : mid;
        full = 0;
    }
    int tid = threadIdx.x, lane = tid & 31, warp = tid >> 5;
    int gid = lane >> 2, tig = lane & 3;

    for (int i = tid; i < 1024; i += 128) {
        int plane = i >> 9, rem = i & 511, row = rem >> 3, ch = (rem & 7) * 4;
        const uint32_t* src = plane ? qlp : qhp;
        uint4 v = *(const uint4*)&src[(size_t)(b * KTOK + qt * 64 + row) * 512 + h * 32 + ch];
        uint32_t* dst = plane ? sm1 : sm0;
        *(uint4*)&dst[row * ATSU + ch] = v;
    }
    __syncthreads();
    uint32_t qh[4][4], ql[4][4];
    {
        int r0 = warp * 16 + gid, r1 = r0 + 8;
#pragma unroll
        for (int kc = 0; kc < 4; kc++) {
            int p = kc * 8 + tig;
            qh[kc][0] = sm0[r0 * ATSU + p];
            qh[kc][1] = sm0[r1 * ATSU + p];
            qh[kc][2] = sm0[r0 * ATSU + p + 4];
            qh[kc][3] = sm0[r1 * ATSU + p + 4];
            ql[kc][0] = sm1[r0 * ATSU + p];
            ql[kc][1] = sm1[r1 * ATSU + p];
            ql[kc][2] = sm1[r0 * ATSU + p + 4];
            ql[kc][3] = sm1[r1 * ATSU + p + 4];
        }
    }

    float accO[8][4];
#pragma unroll
    for (int nt = 0; nt < 8; nt++)
#pragma unroll
        for (int f = 0; f < 4; f++) accO[nt][f] = 0.f;
    float m0r = -1e30f, m1r = -1e30f, l0r = 0.f, l1r = 0.f;

    for (int kt = ktLo; kt < ktHi; kt++) {
        __syncthreads();
        for (int i = tid; i < 1024; i += 128) {
            int plane = i >> 9, rem = i & 511, row = rem >> 3, ch = (rem & 7) * 4;
            const uint32_t* src = plane ? klp : khp;
            uint4 v = *(const uint4*)&src[(size_t)(b * KTOK + kt * 64 + row) * 128 + kh * 32 + ch];
            uint32_t* dst = plane ? sm1 : sm0;
            *(uint4*)&dst[row * ATSU + ch] = v;
        }
        for (int i = tid; i < 1024; i += 128) {
            int plane = i >> 9, rem = i & 511, d = rem >> 3, ch = (rem & 7) * 4;
            const uint32_t* src = plane ? vtl : vth;
            uint4 v = *(const uint4*)&src[(size_t)((b * KVHEAD + kh) * HEADD + d) * TPH + kt * 32 + ch];
            uint32_t* dst = plane ? sm3 : sm2;
            *(uint4*)&dst[d * ATSU + ch] = v;
        }
        __syncthreads();

        float s[8][4];
#pragma unroll
        for (int nt = 0; nt < 8; nt++)
#pragma unroll
            for (int f = 0; f < 4; f++) s[nt][f] = 0.f;
#pragma unroll
        for (int kc = 0; kc < 4; kc++) {
#pragma unroll
            for (int nt = 0; nt < 8; nt++) {
                int tok2 = nt * 8 + gid;
                uint32_t bh[2], bl[2];
                bh[0] = sm0[tok2 * ATSU + kc * 8 + tig];
                bh[1] = sm0[tok2 * ATSU + kc * 8 + tig + 4];
                bl[0] = sm1[tok2 * ATSU + kc * 8 + tig];
                bl[1] = sm1[tok2 * ATSU + kc * 8 + tig + 4];
                mma_bf16(s[nt], qh[kc], bh);
                mma_bf16(s[nt], ql[kc], bh);
                mma_bf16(s[nt], qh[kc], bl);
            }
        }
        if (kt == qt) {
            int r0 = warp * 16 + gid, r1 = r0 + 8;
#pragma unroll
            for (int nt = 0; nt < 8; nt++) {
                int c0 = nt * 8 + 2 * tig, c1 = c0 + 1;
                if (c0 > r0) s[nt][0] = -1e30f;
                if (c1 > r0) s[nt][1] = -1e30f;
                if (c0 > r1) s[nt][2] = -1e30f;
                if (c1 > r1) s[nt][3] = -1e30f;
            }
        }
        float mx0 = -1e30f, mx1 = -1e30f;
#pragma unroll
        for (int nt = 0; nt < 8; nt++) {
            mx0 = fmaxf(mx0, fmaxf(s[nt][0], s[nt][1]));
            mx1 = fmaxf(mx1, fmaxf(s[nt][2], s[nt][3]));
        }
        mx0 = fmaxf(mx0, __shfl_xor_sync(0xffffffffu, mx0, 1));
        mx0 = fmaxf(mx0, __shfl_xor_sync(0xffffffffu, mx0, 2));
        mx1 = fmaxf(mx1, __shfl_xor_sync(0xffffffffu, mx1, 1));
        mx1 = fmaxf(mx1, __shfl_xor_sync(0xffffffffu, mx1, 2));
        float mn0 = fmaxf(m0r, mx0), mn1 = fmaxf(m1r, mx1);
        float cor0 = __expf(m0r - mn0), cor1 = __expf(m1r - mn1);
        float ps0 = 0.f, ps1 = 0.f;
#pragma unroll
        for (int nt = 0; nt < 8; nt++) {
            s[nt][0] = __expf(s[nt][0] - mn0);
            s[nt][1] = __expf(s[nt][1] - mn0);
            s[nt][2] = __expf(s[nt][2] - mn1);
            s[nt][3] = __expf(s[nt][3] - mn1);
            ps0 += s[nt][0] + s[nt][1];
            ps1 += s[nt][2] + s[nt][3];
        }
        ps0 += __shfl_xor_sync(0xffffffffu, ps0, 1);
        ps0 += __shfl_xor_sync(0xffffffffu, ps0, 2);
        ps1 += __shfl_xor_sync(0xffffffffu, ps1, 1);
        ps1 += __shfl_xor_sync(0xffffffffu, ps1, 2);
        l0r = l0r * cor0 + ps0;  m0r = mn0;
        l1r = l1r * cor1 + ps1;  m1r = mn1;
#pragma unroll
        for (int nt = 0; nt < 8; nt++) {
            accO[nt][0] *= cor0; accO[nt][1] *= cor0;
            accO[nt][2] *= cor1; accO[nt][3] *= cor1;
        }
#pragma unroll
        for (int kc = 0; kc < 4; kc++) {
            uint32_t ph[4], pl[4];
            split_pair(s[2 * kc][0],     s[2 * kc][1],     ph[0], pl[0]);
            split_pair(s[2 * kc][2],     s[2 * kc][3],     ph[1], pl[1]);
            split_pair(s[2 * kc + 1][0], s[2 * kc + 1][1], ph[2], pl[2]);
            split_pair(s[2 * kc + 1][2], s[2 * kc + 1][3], ph[3], pl[3]);
#pragma unroll
            for (int nt = 0; nt < 8; nt++) {
                int d = nt * 8 + gid;
                uint32_t vh[2], vl[2];
                vh[0] = sm2[d * ATSU + kc * 8 + tig];
                vh[1] = sm2[d * ATSU + kc * 8 + tig + 4];
                vl[0] = sm3[d * ATSU + kc * 8 + tig];
                vl[1] = sm3[d * ATSU + kc * 8 + tig + 4];
                mma_bf16(accO[nt], ph, vh);
                mma_bf16(accO[nt], pl, vh);
                mma_bf16(accO[nt], ph, vl);
            }
        }
    }
    int rl0 = warp * 16 + gid, rl1 = rl0 + 8;
    if (full) {
        float i0 = 1.f / l0r, i1 = 1.f / l1r;
        int row0 = b * KTOK + qt * 64 + rl0;
#pragma unroll
        for (int nt = 0; nt < 8; nt++) {
            int dp = (h * HEADD + nt * 8 + 2 * tig) >> 1;
            uint32_t hv, lv;
            split_pair(accO[nt][0] * i0, accO[nt][1] * i0, hv, lv);
            oh[(size_t)row0 * 512 + dp] = hv;
            ol[(size_t)row0 * 512 + dp] = lv;
            split_pair(accO[nt][2] * i1, accO[nt][3] * i1, hv, lv);
            oh[(size_t)(row0 + 8) * 512 + dp] = hv;
            ol[(size_t)(row0 + 8) * 512 + dp] = lv;
        }
    } else {
        int s = ((b * NHEAD + h) * NQS + (qt - QSPLIT)) * 2 + chunk;
        float* acc = pacc + (size_t)s * 64 * 64;
#pragma unroll
        for (int nt = 0; nt < 8; nt++) {
            int d = nt * 8 + 2 * tig;
            *(float2*)&acc[rl0 * 64 + d] = make_float2(accO[nt][0], accO[nt][1]);
            *(float2*)&acc[rl1 * 64 + d] = make_float2(accO[nt][2], accO[nt][3]);
        }
        if (tig == 0) {
            float* ml = pml + (size_t)s * 128;
            *(float2*)&ml[rl0 * 2] = make_float2(m0r, l0r);
            *(float2*)&ml[rl1 * 2] = make_float2(m1r, l1r);
        }
    }
}

// ---------------- attn merge ----------------
__global__ void __launch_bounds__(128)
attn_merge_kernel(const float* __restrict__ pacc, const float* __restrict__ pml,
                  uint32_t* __restrict__ oh, uint32_t* __restrict__ ol) {
    int qt = QSPLIT + blockIdx.x;
    int h = blockIdx.y, b = blockIdx.z;
    int sbase = ((b * NHEAD + h) * NQS + (qt - QSPLIT)) * 2;
    const float* a0 = pacc + (size_t)(sbase + 0) * 64 * 64;
    const float* a1 = pacc + (size_t)(sbase + 1) * 64 * 64;
    const float* ml0 = pml + (size_t)(sbase + 0) * 128;
    const float* ml1 = pml + (size_t)(sbase + 1) * 128;
    int tid = threadIdx.x;
    for (int t = tid; t < 2048; t += 128) {
        int r = t >> 5, dp = t & 31;
        float2 q0 = *(const float2*)&ml0[r * 2];
        float2 q1 = *(const float2*)&ml1[r * 2];
        float M = fmaxf(q0.x, q1.x);
        float w0 = __expf(q0.x - M), w1 = __expf(q1.x - M);
        float inv = 1.f / (w0 * q0.y + w1 * q1.y);
        float2 v0 = *(const float2*)&a0[r * 64 + 2 * dp];
        float2 v1 = *(const float2*)&a1[r * 64 + 2 * dp];
        float o0 = (w0 * v0.x + w1 * v1.x) * inv;
        float o1 = (w0 * v0.y + w1 * v1.y) * inv;
        uint32_t hv, lv;
        split_pair(o0, o1, hv, lv);
        size_t row = (size_t)(b * KTOK + qt * 64 + r);
        oh[row * 512 + h * 32 + dp] = hv;
        ol[row * 512 + h * 32 + dp] = lv;
    }
}

// ---------------- launch ----------------
extern "C" void kernel_launch(void* const* d_in, const int* in_sizes, int n_in,
                              void* d_out, int out_size) {
    const int*   ids      = (const int*)d_in[0];
    const float* emb      = (const float*)d_in[1];
    const float* router_k = (const float*)d_in[2];
    const float* router_q = (const float*)d_in[3];
    const float* ln1      = (const float*)d_in[4];
    const float* ln2      = (const float*)d_in[5];
    const float* wq       = (const float*)d_in[6];
    const float* bq       = (const float*)d_in[7];
    const float* wk       = (const float*)d_in[8];
    const float* bk       = (const float*)d_in[9];
    const float* wv       = (const float*)d_in[10];
    const float* bv       = (const float*)d_in[11];
    const float* wo       = (const float*)d_in[12];
    const float* wg       = (const float*)d_in[13];
    const float* wu       = (const float*)d_in[14];
    const float* wd       = (const float*)d_in[15];
    float* hidden = (float*)d_out;

    float *x, *vbuf, *pooled, *scores, *bqkv, *pacc, *pml;
    int* tok;
    uint32_t *wqkvh, *wqkvl, *woh, *wol, *wguh, *wgul, *wdh, *wdl;
    uint32_t *hh, *hl, *oh, *ol, *gh, *gl;
    uint32_t *qhp, *qlp, *khp, *klp, *vth, *vtl;
    cudaGetSymbolAddress((void**)&x, g_x);
    cudaGetSymbolAddress((void**)&vbuf, g_vbuf);
    cudaGetSymbolAddress((void**)&pooled, g_pool);
    cudaGetSymbolAddress((void**)&scores, g_scores);
    cudaGetSymbolAddress((void**)&tok, g_tok);
    cudaGetSymbolAddress((void**)&bqkv, g_bqkv);
    cudaGetSymbolAddress((void**)&wqkvh, g_wqkvh); cudaGetSymbolAddress((void**)&wqkvl, g_wqkvl);
    cudaGetSymbolAddress((void**)&woh, g_woh);     cudaGetSymbolAddress((void**)&wol, g_wol);
    cudaGetSymbolAddress((void**)&wguh, g_wguh);   cudaGetSymbolAddress((void**)&wgul, g_wgul);
    cudaGetSymbolAddress((void**)&wdh, g_wdh);     cudaGetSymbolAddress((void**)&wdl, g_wdl);
    cudaGetSymbolAddress((void**)&hh, g_hh);       cudaGetSymbolAddress((void**)&hl, g_hl);
    cudaGetSymbolAddress((void**)&oh, g_oh);       cudaGetSymbolAddress((void**)&ol, g_ol);
    cudaGetSymbolAddress((void**)&gh, g_gh);       cudaGetSymbolAddress((void**)&gl, g_gl);
    cudaGetSymbolAddress((void**)&qhp, g_qhp);     cudaGetSymbolAddress((void**)&qlp, g_qlp);
    cudaGetSymbolAddress((void**)&khp, g_khp);     cudaGetSymbolAddress((void**)&klp, g_klp);
    cudaGetSymbolAddress((void**)&vth, g_vth);     cudaGetSymbolAddress((void**)&vtl, g_vtl);
    cudaGetSymbolAddress((void**)&pacc, g_pacc);   cudaGetSymbolAddress((void**)&pml, g_pml);

    cudaFuncSetAttribute((const void*)pgemm_kernel<8,4>, cudaFuncAttributeMaxDynamicSharedMemorySize, SM_PGEMM4);
    cudaFuncSetAttribute((const void*)pgemm_kernel<4,4>, cudaFuncAttributeMaxDynamicSharedMemorySize, SM_PGEMM4);
    cudaFuncSetAttribute((const void*)pgemm_kernel<2,2>, cudaFuncAttributeMaxDynamicSharedMemorySize, SM_PGEMM2);

    embed_kernel<<<BATCH * SEQ, 256>>>(ids, emb, hidden);

    // ---- weight prepacks ----
    prepack_gu_kernel<<<NLAYER * 512 * 1408 / 256, 256>>>(wg, wu, wguh, wgul);
    prepack_qkv_kernel<<<NLAYER * 512 * 384 / 256, 256>>>(wq, wk, wv, wqkvh, wqkvl);
    prepack_kernel<<<NLAYER * 512 * 1024 / 1024, 256>>>(wo, woh, wol, 256, 1024);
    prepack_kernel<<<NLAYER * 1408 * 1024 / 1024, 256>>>(wd, wdh, wdl, 256, 1024);
    fuse_bias_kernel<<<NLAYER * NQKV / 256, 256>>>(bq, bk, bv, bqkv);

    for (int blk = 0; blk < NBLK; blk++) {
        int li0 = blk * BPL;
        pool_kernel<<<BATCH * NSEG, 256>>>(hidden, pooled);
        router_kernel<<<dim3(NSEG, BATCH), 128>>>(
            pooled, router_k + (size_t)blk * DIM * RANKR,
            router_q + (size_t)blk * NQRY * RANKR, scores);
        select_kernel<<<BATCH, 256>>>(scores, tok);
        gather_norm_kernel<<<BT, 256>>>(hidden, tok, ln1 + (size_t)li0 * DIM, x, hh, hl);

        for (int j = 0; j < BPL; j++) {
            int li = li0 + j;
            size_t oqkv = (size_t)li * 512 * NQKV;
            size_t oo   = (size_t)li * 512 * 1024;
            size_t ogu  = (size_t)li * 512 * NGU;
            size_t od   = (size_t)li * 1408 * 1024;

            if (j > 0)
                rmsnorm_kernel<<<BT, 256>>>(x, ln1 + (size_t)li * DIM, hh, hl);
            pgemm_kernel<8,4><<<dim3(NQKV / 128, BT / 128), 256, SM_PGEMM4>>>(
                hh, hl, wqkvh + oqkv, wqkvl + oqkv, bqkv + (size_t)li * NQKV,
                vbuf, qhp, qlp, khp, klp, tok, BT, NQKV, 512);
            prep_v_kernel<<<BT / 2, 256>>>(vbuf, vth, vtl);
            attn_mma_kernel<<<dim3(NCID, NHEAD, BATCH), 128>>>(
                qhp, qlp, khp, klp, vth, vtl, oh, ol, pacc, pml);
            attn_merge_kernel<<<dim3(NQS, NHEAD, BATCH), 128>>>(pacc, pml, oh, ol);
            pgemm_kernel<2,2><<<dim3(8, BT / 64), 256, SM_PGEMM2>>>(
                oh, ol, woh + oo, wol + oo, nullptr, x, nullptr, nullptr, nullptr, nullptr,
                nullptr, BT, 1024, 512);
            rmsnorm_kernel<<<BT, 256>>>(x, ln2 + (size_t)li * DIM, hh, hl);
            pgemm_kernel<4,4><<<dim3(NGU / 128, BT / 128), 256, SM_PGEMM4>>>(
                hh, hl, wguh + ogu, wgul + ogu, nullptr, nullptr, gh, gl, nullptr, nullptr,
                nullptr, BT, NGU, 512);
            pgemm_kernel<2,2><<<dim3(8, BT / 64), 256, SM_PGEMM2>>>(
                gh, gl, wdh + od, wdl + od, nullptr, x, nullptr, nullptr, nullptr, nullptr,
                nullptr, BT, 1024, 1408);
        }
        scatter_kernel<<<BT, 256>>>(x, tok, hidden);
    }
}

// round 17
// speedup vs baseline: 3.3443x; 1.0005x over previous
#include <cuda_runtime.h>
#include <cuda_bf16.h>
#include <math.h>
#include <stdint.h>

// ---------------- problem constants ----------------
#define BATCH 2
#define SEQ   4096
#define DIM   1024
#define NHEAD 16
#define KVHEAD 4
#define HEADD 64
#define FFD   2816
#define NSEG  256
#define SEGLEN 16
#define KSEG  76
#define KTOK  (KSEG*SEGLEN)      // 1216
#define BT    (BATCH*KTOK)       // 2432
#define NLAYER 12
#define NBLK  2
#define BPL   6
#define RANKR 16
#define NQRY  8
#define NQKV  1536
#define NGU   5632
#define TPH   (KTOK/2)
#define QSPLIT 11
#define NQS    8
#define NCID   (QSPLIT + 2*NQS)

// ---------------- scratch ----------------
__device__ float g_x   [BT*DIM];
__device__ float g_vbuf[BT*256];
__device__ float g_pool[BATCH*NSEG*DIM];
__device__ float g_scores[BATCH*NSEG];
__device__ int   g_tok [BATCH*KTOK];
__device__ float g_bqkv[NLAYER*NQKV];

__device__ uint32_t g_wqkvh[NLAYER*512*NQKV], g_wqkvl[NLAYER*512*NQKV];
__device__ uint32_t g_woh  [NLAYER*512*1024], g_wol  [NLAYER*512*1024];
__device__ uint32_t g_wguh [NLAYER*512*NGU],  g_wgul [NLAYER*512*NGU];
__device__ uint32_t g_wdh  [NLAYER*1408*1024],g_wdl  [NLAYER*1408*1024];
__device__ uint32_t g_hh[BT*DIM/2],  g_hl[BT*DIM/2];
__device__ uint32_t g_oh[BT*DIM/2],  g_ol[BT*DIM/2];
__device__ uint32_t g_gh[BT*FFD/2],  g_gl[BT*FFD/2];
__device__ uint32_t g_qhp[BT*512],  g_qlp[BT*512];
__device__ uint32_t g_khp[BT*128],  g_klp[BT*128];
__device__ uint32_t g_vth[BATCH*KVHEAD*HEADD*TPH], g_vtl[BATCH*KVHEAD*HEADD*TPH];
__device__ float g_pacc[512*64*64];
__device__ float g_pml [512*64*2];

// ---------------- helpers ----------------
__device__ __forceinline__ void split_pair(float x0, float x1, uint32_t& hp, uint32_t& lp) {
    uint32_t h;
    asm("cvt.rn.bf16x2.f32 %0, %1, %2;" : "=r"(h) : "f"(x1), "f"(x0));
    float h0 = __uint_as_float(h << 16);
    float h1 = __uint_as_float(h & 0xFFFF0000u);
    float l0 = x0 - h0, l1 = x1 - h1;
    uint32_t l;
    asm("cvt.rn.bf16x2.f32 %0, %1, %2;" : "=r"(l) : "f"(l1), "f"(l0));
    hp = h; lp = l;
}
__device__ __forceinline__ uint32_t smem_u32(const void* p) {
    uint32_t a;
    asm("{ .reg .u64 t; cvta.to.shared.u64 t, %1; cvt.u32.u64 %0, t; }" : "=r"(a) : "l"(p));
    return a;
}
__device__ __forceinline__ void cpasync16(uint32_t dst, const void* src) {
    asm volatile("cp.async.cg.shared.global [%0], [%1], 16;" :: "r"(dst), "l"(src));
}
#define CP_COMMIT() asm volatile("cp.async.commit_group;" ::: "memory")
#define CP_WAIT1()  asm volatile("cp.async.wait_group 1;" ::: "memory")
#define CP_WAIT0()  asm volatile("cp.async.wait_group 0;" ::: "memory")

__device__ __forceinline__ int rope_perm(int c) {
    int h = c >> 6, r = c & 63, i = r >> 1;
    return h * 64 + ((r & 1) ? (i + 32) : i);
}

// ---------------- weight prepacks ----------------
__global__ void prepack_kernel(const float* __restrict__ src,
                               uint32_t* __restrict__ dh, uint32_t* __restrict__ dl,
                               int n4row, int N) {
    int idx = blockIdx.x * 256 + threadIdx.x;
    int p = idx / n4row, c = (idx - p * n4row) * 4;
    const float* r0 = src + (size_t)(2 * p) * N + c;
    float4 a = *(const float4*)r0;
    float4 b = *(const float4*)(r0 + N);
    uint4 h, l;
    split_pair(a.x, b.x, h.x, l.x);
    split_pair(a.y, b.y, h.y, l.y);
    split_pair(a.z, b.z, h.z, l.z);
    split_pair(a.w, b.w, h.w, l.w);
    *(uint4*)(dh + (size_t)idx * 4) = h;
    *(uint4*)(dl + (size_t)idx * 4) = l;
}

__global__ void prepack_qkv_kernel(const float* __restrict__ wq,
                                   const float* __restrict__ wk,
                                   const float* __restrict__ wv,
                                   uint32_t* __restrict__ dh, uint32_t* __restrict__ dl) {
    int idx = blockIdx.x * 256 + threadIdx.x;
    int l = idx / (512 * 384);
    int rem = idx - l * (512 * 384);
    int p = rem / 384, col0 = (rem - p * 384) * 4;
    uint4 h, l4;
    uint32_t* hp = (uint32_t*)&h;
    uint32_t* lp = (uint32_t*)&l4;
#pragma unroll
    for (int e = 0; e < 4; e++) {
        int nc = col0 + e;
        const float* s0;
        if (nc < 1024)      s0 = wq + ((size_t)(l * 1024 + 2 * p)) * 1024 + rope_perm(nc);
        else if (nc < 1280) s0 = wk + ((size_t)(l * 1024 + 2 * p)) * 256 + rope_perm(nc - 1024);
        else                s0 = wv + ((size_t)(l * 1024 + 2 * p)) * 256 + (nc - 1280);
        int srcN = (nc < 1024) ? 1024 : 256;
        split_pair(s0[0], s0[srcN], hp[e], lp[e]);
    }
    *(uint4*)(dh + (size_t)idx * 4) = h;
    *(uint4*)(dl + (size_t)idx * 4) = l4;
}

__global__ void prepack_gu_kernel(const float* __restrict__ wg,
                                  const float* __restrict__ wu,
                                  uint32_t* __restrict__ dh, uint32_t* __restrict__ dl) {
    int idx = blockIdx.x * 256 + threadIdx.x;
    int l = idx / (512 * 1408);
    int rem = idx - l * (512 * 1408);
    int p = rem / 1408, q = rem - p * 1408;
    size_t row0 = (size_t)(l * 1024 + 2 * p);
    const float* g0 = wg + row0 * 2816 + 2 * q;
    const float* u0 = wu + row0 * 2816 + 2 * q;
    float2 ga = *(const float2*)g0;
    float2 gb = *(const float2*)(g0 + 2816);
    float2 ua = *(const float2*)u0;
    float2 ub = *(const float2*)(u0 + 2816);
    uint4 h, l4;
    split_pair(ga.x, gb.x, h.x, l4.x);
    split_pair(ga.y, gb.y, h.y, l4.y);
    split_pair(ua.x, ub.x, h.z, l4.z);
    split_pair(ua.y, ub.y, h.w, l4.w);
    *(uint4*)(dh + (size_t)idx * 4) = h;
    *(uint4*)(dl + (size_t)idx * 4) = l4;
}

__global__ void fuse_bias_kernel(const float* __restrict__ bq,
                                 const float* __restrict__ bk,
                                 const float* __restrict__ bv,
                                 float* __restrict__ dst) {
    int i = blockIdx.x * 256 + threadIdx.x;
    int l = i / NQKV, j = i - l * NQKV;
    float v;
    if (j < 1024)      v = bq[l * 1024 + rope_perm(j)];
    else if (j < 1280) v = bk[l * 256 + rope_perm(j - 1024)];
    else               v = bv[l * 256 + j - 1280];
    dst[i] = v;
}

// ---------------- embed / pool / router / select / scatter ----------------
__global__ void embed_kernel(const int* __restrict__ ids,
                             const float* __restrict__ emb,
                             float* __restrict__ hidden) {
    int row = blockIdx.x;
    int id  = ids[row];
    const float4* src = (const float4*)(emb + (size_t)id * DIM);
    float4* dst = (float4*)(hidden + (size_t)row * DIM);
    dst[threadIdx.x] = src[threadIdx.x];
}

__global__ void pool_kernel(const float* __restrict__ hidden,
                            float* __restrict__ pooled) {
    int b = blockIdx.x >> 8, n = blockIdx.x & 255;
    const float* base = hidden + ((size_t)b * SEQ + n * SEGLEN) * DIM + threadIdx.x * 4;
    float4 acc = make_float4(0.f, 0.f, 0.f, 0.f);
#pragma unroll
    for (int t = 0; t < SEGLEN; t++) {
        float4 v = *(const float4*)(base + (size_t)t * DIM);
        acc.x += v.x; acc.y += v.y; acc.z += v.z; acc.w += v.w;
    }
    const float s = 1.f / SEGLEN;
    acc.x *= s; acc.y *= s; acc.z *= s; acc.w *= s;
    *(float4*)(pooled + ((size_t)b * NSEG + n) * DIM + threadIdx.x * 4) = acc;
}

__global__ void router_kernel(const float* __restrict__ pooled,
                              const float* __restrict__ rk,
                              const float* __restrict__ rq,
                              float* __restrict__ scores) {
    int n = blockIdx.x, b = blockIdx.y;
    const float* p = pooled + ((size_t)b * NSEG + n) * DIM;
    __shared__ float part[128];
    int tid = threadIdx.x;
    int r = tid & 15, g = tid >> 4;
    float sum = 0.f;
    int d0 = g * 128;
    for (int d = d0; d < d0 + 128; d++) sum += p[d] * rk[d * RANKR + r];
    part[tid] = sum;
    __syncthreads();
    if (tid < RANKR) {
        float key = 0.f;
        for (int gg = 0; gg < 8; gg++) key += part[gg * 16 + tid];
        part[tid] = key;
    }
    __syncthreads();
    if (tid == 0) {
        float best = -1e30f;
        for (int qq = 0; qq < NQRY; qq++) {
            float dv = 0.f;
            for (int rr = 0; rr < RANKR; rr++) dv += rq[qq * RANKR + rr] * part[rr];
            best = fmaxf(best, dv);
        }
        scores[b * NSEG + n] = best;
    }
}

__global__ void select_kernel(const float* __restrict__ scores,
                              int* __restrict__ tok) {
    int b = blockIdx.x;
    __shared__ float s[NSEG];
    __shared__ int pf[NSEG];
    int i = threadIdx.x;
    float mine = scores[b * NSEG + i];
    s[i] = mine;
    __syncthreads();
    int rank = 0;
    for (int j = 0; j < NSEG; j++) {
        float o = s[j];
        rank += (o > mine) || (o == mine && j < i);
    }
    int sel = (rank < KSEG) ? 1 : 0;
    pf[i] = sel;
    __syncthreads();
    for (int off = 1; off < NSEG; off <<= 1) {
        int add = (i >= off) ? pf[i - off] : 0;
        __syncthreads();
        pf[i] += add;
        __syncthreads();
    }
    if (sel) {
        int p = pf[i] - 1;
        int* dst = tok + b * KTOK + p * SEGLEN;
        int base = i * SEGLEN;
#pragma unroll
        for (int t = 0; t < SEGLEN; t++) dst[t] = base + t;
    }
}

__global__ void scatter_kernel(const float* __restrict__ x,
                               const int* __restrict__ tok,
                               float* __restrict__ hidden) {
    int row = blockIdx.x;
    int b = row / KTOK;
    int tk = tok[row];
    const float4* src = (const float4*)(x + (size_t)row * DIM);
    float4* dst = (float4*)(hidden + ((size_t)b * SEQ + tk) * DIM);
    dst[threadIdx.x] = src[threadIdx.x];
}

// ---------------- RMSNorm ----------------
__device__ __forceinline__ void rms_body(float4 v, const float* w, int row, int t,
                                         uint32_t* oh, uint32_t* ol) {
    float ss = v.x * v.x + v.y * v.y + v.z * v.z + v.w * v.w;
#pragma unroll
    for (int d = 16; d >= 1; d >>= 1) ss += __shfl_xor_sync(0xffffffffu, ss, d);
    __shared__ float ws[8];
    __shared__ float tot;
    if ((t & 31) == 0) ws[t >> 5] = ss;
    __syncthreads();
    if (t == 0) {
        float a = 0.f;
        for (int wgi = 0; wgi < 8; wgi++) a += ws[wgi];
        tot = a;
    }
    __syncthreads();
    float inv = rsqrtf(tot * (1.f / DIM) + 1e-6f);
    float4 wv = ((const float4*)w)[t];
    float o0 = v.x * inv * wv.x, o1 = v.y * inv * wv.y;
    float o2 = v.z * inv * wv.z, o3 = v.w * inv * wv.w;
    uint32_t h0, l0, h1, l1;
    split_pair(o0, o1, h0, l0);
    split_pair(o2, o3, h1, l1);
    size_t base = (size_t)row * (DIM / 2) + t * 2;
    *(uint2*)&oh[base] = make_uint2(h0, h1);
    *(uint2*)&ol[base] = make_uint2(l0, l1);
}

__global__ void rmsnorm_kernel(const float* __restrict__ x,
                               const float* __restrict__ w,
                               uint32_t* __restrict__ oh,
                               uint32_t* __restrict__ ol) {
    int row = blockIdx.x, t = threadIdx.x;
    float4 v = ((const float4*)(x + (size_t)row * DIM))[t];
    rms_body(v, w, row, t, oh, ol);
}

__global__ void gather_norm_kernel(const float* __restrict__ hidden,
                                   const int* __restrict__ tok,
                                   const float* __restrict__ w,
                                   float* __restrict__ x,
                                   uint32_t* __restrict__ oh,
                                   uint32_t* __restrict__ ol) {
    int row = blockIdx.x, t = threadIdx.x;
    int b = row / KTOK;
    int tk = tok[row];
    float4 v = ((const float4*)(hidden + ((size_t)b * SEQ + tk) * DIM))[t];
    ((float4*)(x + (size_t)row * DIM))[t] = v;
    rms_body(v, w, row, t, oh, ol);
}

// ---------------- prep_v ----------------
__global__ void __launch_bounds__(256)
prep_v_kernel(const float* __restrict__ vbuf,
              uint32_t* __restrict__ vth, uint32_t* __restrict__ vtl) {
    int p = blockIdx.x;
    int b = p / TPH;
    int lp = p - b * TPH;
    int r0 = b * KTOK + lp * 2;
    int t = threadIdx.x;
    int kvh = t >> 6, d = t & 63;
    float v0 = vbuf[(size_t)r0 * 256 + t];
    float v1 = vbuf[(size_t)(r0 + 1) * 256 + t];
    uint32_t h, l;
    split_pair(v0, v1, h, l);
    size_t o = (size_t)((b * KVHEAD + kvh) * HEADD + d) * TPH + lp;
    vth[o] = h; vtl[o] = l;
}

// ---------------- bf16 MMA primitive ----------------
__device__ __forceinline__ void mma_bf16(float c[4], const uint32_t a[4], const uint32_t b[2]) {
    asm volatile(
        "mma.sync.aligned.m16n8k16.row.col.f32.bf16.bf16.f32 "
        "{%0,%1,%2,%3}, {%4,%5,%6,%7}, {%8,%9}, {%0,%1,%2,%3};\n"
        : "+f"(c[0]), "+f"(c[1]), "+f"(c[2]), "+f"(c[3])
        : "r"(a[0]), "r"(a[1]), "r"(a[2]), "r"(a[3]), "r"(b[0]), "r"(b[1]));
}

// ---------------- pair-format split-bf16 (3xMMA) GEMM, cp.async 2-stage ---------
// MMA issue order: 3 passes over nt so no back-to-back same-accumulator MMAs.
#define ASU 20
#define BSU 136
#define B_STG (16 * BSU)

template <int FLAGS, int MT>
__global__ void __launch_bounds__(256, 2)
pgemm_kernel(const uint32_t* __restrict__ Ahp, const uint32_t* __restrict__ Alp,
             const uint32_t* __restrict__ Whp, const uint32_t* __restrict__ Wlp,
             const float* __restrict__ bias,
             float* __restrict__ C,
             uint32_t* __restrict__ Dh, uint32_t* __restrict__ Dl,
             uint32_t* __restrict__ Eh, uint32_t* __restrict__ El,
             const int* __restrict__ tok,
             int M, int N, int K2) {
    constexpr int MROWS = MT * 32;
    constexpr int A_STG = MROWS * ASU;
    constexpr int ACH = MROWS * 4;
    constexpr int STG_U32 = 2 * A_STG + 2 * B_STG;
    extern __shared__ uint32_t sgm[];
    uint32_t sb = smem_u32(sgm);
    int tid = threadIdx.x, lane = tid & 31, warp = tid >> 5;
    int warpM = warp & 1, warpN = warp >> 1;
    int m0 = blockIdx.y * MROWS, n0 = blockIdx.x * 128;
    int gid = lane >> 2, tig = lane & 3;
    int NT = K2 / 16;

    int pr0 = tid >> 5, cg0 = (tid & 31) * 4;
    int pr1 = (tid + 256) >> 5, cg1 = ((tid + 256) & 31) * 4;

    float c[MT][4][4];
#pragma unroll
    for (int i = 0; i < MT; i++)
#pragma unroll
        for (int j = 0; j < 4; j++)
#pragma unroll
            for (int f = 0; f < 4; f++) c[i][j][f] = 0.f;

#define ISSUE_TILE(kt, buf) do {                                               \
        uint32_t st = sb + (buf) * (STG_U32 * 4);                              \
        int p0 = (kt) * 16;                                                    \
        _Pragma("unroll")                                                      \
        for (int ii = 0; ii < ACH / 256; ii++) {                               \
            int ch = tid + 256 * ii;                                           \
            int arow = ch >> 2, apc = (ch & 3) * 4;                            \
            size_t ga = (size_t)(m0 + arow) * K2 + p0 + apc;                   \
            uint32_t sa = st + (arow * ASU + apc) * 4;                         \
            cpasync16(sa, &Ahp[ga]);                                           \
            cpasync16(sa + A_STG * 4, &Alp[ga]);                               \
        }                                                                      \
        size_t b0 = (size_t)(p0 + pr0) * N + n0 + cg0;                         \
        uint32_t sb0 = st + (2 * A_STG + pr0 * BSU + cg0) * 4;                 \
        cpasync16(sb0, &Whp[b0]);                                              \
        cpasync16(sb0 + B_STG * 4, &Wlp[b0]);                                  \
        size_t b1 = (size_t)(p0 + pr1) * N + n0 + cg1;                         \
        uint32_t sb1 = st + (2 * A_STG + pr1 * BSU + cg1) * 4;                 \
        cpasync16(sb1, &Whp[b1]);                                              \
        cpasync16(sb1 + B_STG * 4, &Wlp[b1]);                                  \
        CP_COMMIT();                                                           \
    } while (0)

    ISSUE_TILE(0, 0);
    if (NT > 1) ISSUE_TILE(1, 1);

    for (int kt = 0; kt < NT; kt++) {
        int buf = kt & 1;
        if (kt + 1 < NT) CP_WAIT1(); else CP_WAIT0();
        __syncthreads();
        uint32_t* sAh = sgm + buf * STG_U32;
        uint32_t* sAl = sAh + A_STG;
        uint32_t* sBh = sAl + A_STG;
        uint32_t* sBl = sBh + B_STG;
#pragma unroll
        for (int kk = 0; kk < 2; kk++) {
            int kp = kk * 8;
            uint32_t bh[4][2], bl[4][2];
#pragma unroll
            for (int nt = 0; nt < 4; nt++) {
                int cb = warpN * 32 + nt * 8 + gid;
                bh[nt][0] = sBh[(kp + tig) * BSU + cb];
                bh[nt][1] = sBh[(kp + tig + 4) * BSU + cb];
                bl[nt][0] = sBl[(kp + tig) * BSU + cb];
                bl[nt][1] = sBl[(kp + tig + 4) * BSU + cb];
            }
#pragma unroll
            for (int mt = 0; mt < MT; mt++) {
                int rb = warpM * (MT * 16) + mt * 16 + gid;
                uint32_t ah[4], al[4];
                ah[0] = sAh[rb * ASU + kp + tig];
                ah[1] = sAh[(rb + 8) * ASU + kp + tig];
                ah[2] = sAh[rb * ASU + kp + tig + 4];
                ah[3] = sAh[(rb + 8) * ASU + kp + tig + 4];
                al[0] = sAl[rb * ASU + kp + tig];
                al[1] = sAl[(rb + 8) * ASU + kp + tig];
                al[2] = sAl[rb * ASU + kp + tig + 4];
                al[3] = sAl[(rb + 8) * ASU + kp + tig + 4];
                // 3 passes: dependency distance 4 (was 1)
#pragma unroll
                for (int nt = 0; nt < 4; nt++) mma_bf16(c[mt][nt], ah, bh[nt]);
#pragma unroll
                for (int nt = 0; nt < 4; nt++) mma_bf16(c[mt][nt], al, bh[nt]);
#pragma unroll
                for (int nt = 0; nt < 4; nt++) mma_bf16(c[mt][nt], ah, bl[nt]);
            }
        }
        __syncthreads();
        if (kt + 2 < NT) ISSUE_TILE(kt + 2, buf);
    }
#undef ISSUE_TILE
    // ---- epilogue ----
    if (FLAGS == 8) {
#pragma unroll
        for (int mt = 0; mt < MT; mt++) {
#pragma unroll
            for (int half = 0; half < 2; half++) {
                int row = m0 + warpM * (MT * 16) + mt * 16 + gid + half * 8;
                float fpos = (float)tok[row];
#pragma unroll
                for (int nt = 0; nt < 4; nt++) {
                    int col = n0 + warpN * 32 + nt * 8 + tig * 2;
                    float2 bb = *(const float2*)&bias[col];
                    float v0 = c[mt][nt][half * 2 + 0] + bb.x;
                    float v1 = c[mt][nt][half * 2 + 1] + bb.y;
                    if (col < 1280) {
                        int i = (col & 63) >> 1;
                        float invf = __powf(10000.f, -(float)(2 * i) / 64.f);
                        float sn, cs;
                        sincosf(fpos * invf, &sn, &cs);
                        float o0 = v0 * cs - v1 * sn;
                        float o1 = v1 * cs + v0 * sn;
                        uint32_t hv, lv;
                        if (col < 1024) {
                            split_pair(o0 * 0.125f, o1 * 0.125f, hv, lv);
                            size_t o = (size_t)row * 512 + (col >> 1);
                            Dh[o] = hv; Dl[o] = lv;
                        } else {
                            split_pair(o0, o1, hv, lv);
                            size_t o = (size_t)row * 128 + ((col - 1024) >> 1);
                            Eh[o] = hv; El[o] = lv;
                        }
                    } else {
                        *(float2*)&C[(size_t)row * 256 + (col - 1280)] = make_float2(v0, v1);
                    }
                }
            }
        }
    } else if (FLAGS == 4) {
#pragma unroll
        for (int mt = 0; mt < MT; mt++) {
#pragma unroll
            for (int half = 0; half < 2; half++) {
                int row = m0 + warpM * (MT * 16) + mt * 16 + gid + half * 8;
#pragma unroll
                for (int nt = 0; nt < 4; nt++) {
                    float v0 = c[mt][nt][half * 2 + 0];
                    float v1 = c[mt][nt][half * 2 + 1];
                    float p0 = __shfl_xor_sync(0xffffffffu, v0, 1);
                    float p1 = __shfl_xor_sync(0xffffffffu, v1, 1);
                    if ((tig & 1) == 0) {
                        float o0 = v0 / (1.f + __expf(-v0)) * p0;
                        float o1 = v1 / (1.f + __expf(-v1)) * p1;
                        int c0 = n0 + warpN * 32 + nt * 8 + 2 * tig;
                        int q = c0 >> 2;
                        uint32_t hv, lv;
                        split_pair(o0, o1, hv, lv);
                        size_t o = (size_t)row * (FFD / 2) + q;
                        Dh[o] = hv; Dl[o] = lv;
                    }
                }
            }
        }
    } else {
#pragma unroll
        for (int mt = 0; mt < MT; mt++) {
#pragma unroll
            for (int half = 0; half < 2; half++) {
                int row = m0 + warpM * (MT * 16) + mt * 16 + gid + half * 8;
                float* Crow = C + (size_t)row * N + n0 + warpN * 32;
#pragma unroll
                for (int nt = 0; nt < 4; nt++) {
                    int col = nt * 8 + tig * 2;
                    float2 r;
                    r.x = c[mt][nt][half * 2 + 0];
                    r.y = c[mt][nt][half * 2 + 1];
                    if (FLAGS & 1) {
                        float2 bb = *(const float2*)&bias[n0 + warpN * 32 + col];
                        r.x += bb.x; r.y += bb.y;
                    }
                    if (FLAGS & 2) {
                        float2 cc = *(const float2*)&Crow[col];
                        r.x += cc.x; r.y += cc.y;
                    }
                    *(float2*)&Crow[col] = r;
                }
            }
        }
    }
}
#define SM_PGEMM4 (2 * (2 * 128 * ASU + 2 * B_STG) * 4)
#define SM_PGEMM2 (2 * (2 * 64 * ASU + 2 * B_STG) * 4)

// ---------------- tensor-core flash attention (chunked split-softmax) ----------------
#define ATSU 36
__global__ void __launch_bounds__(128)
attn_mma_kernel(const uint32_t* __restrict__ qhp, const uint32_t* __restrict__ qlp,
                const uint32_t* __restrict__ khp, const uint32_t* __restrict__ klp,
                const uint32_t* __restrict__ vth, const uint32_t* __restrict__ vtl,
                uint32_t* __restrict__ oh, uint32_t* __restrict__ ol,
                float* __restrict__ pacc, float* __restrict__ pml) {
    __shared__ uint32_t sm0[64 * ATSU], sm1[64 * ATSU];
    __shared__ uint32_t sm2[64 * ATSU], sm3[64 * ATSU];
    int cid = blockIdx.x, h = blockIdx.y, b = blockIdx.z;
    int kh = h >> 2;
    int qt, ktLo, ktHi, chunk, full;
    if (cid < QSPLIT) { qt = cid; ktLo = 0; ktHi = qt + 1; chunk = 0; full = 1; }
    else {
        int t = cid - QSPLIT;
        qt = QSPLIT + (t >> 1);
        chunk = t & 1;
        int mid = (qt + 1) >> 1;
        ktLo = chunk ? mid : 0;
        ktHi = chunk ? qt + 1 : mid;
        full = 0;
    }
    int tid = threadIdx.x, lane = tid & 31, warp = tid >> 5;
    int gid = lane >> 2, tig = lane & 3;

    for (int i = tid; i < 1024; i += 128) {
        int plane = i >> 9, rem = i & 511, row = rem >> 3, ch = (rem & 7) * 4;
        const uint32_t* src = plane ? qlp : qhp;
        uint4 v = *(const uint4*)&src[(size_t)(b * KTOK + qt * 64 + row) * 512 + h * 32 + ch];
        uint32_t* dst = plane ? sm1 : sm0;
        *(uint4*)&dst[row * ATSU + ch] = v;
    }
    __syncthreads();
    uint32_t qh[4][4], ql[4][4];
    {
        int r0 = warp * 16 + gid, r1 = r0 + 8;
#pragma unroll
        for (int kc = 0; kc < 4; kc++) {
            int p = kc * 8 + tig;
            qh[kc][0] = sm0[r0 * ATSU + p];
            qh[kc][1] = sm0[r1 * ATSU + p];
            qh[kc][2] = sm0[r0 * ATSU + p + 4];
            qh[kc][3] = sm0[r1 * ATSU + p + 4];
            ql[kc][0] = sm1[r0 * ATSU + p];
            ql[kc][1] = sm1[r1 * ATSU + p];
            ql[kc][2] = sm1[r0 * ATSU + p + 4];
            ql[kc][3] = sm1[r1 * ATSU + p + 4];
        }
    }

    float accO[8][4];
#pragma unroll
    for (int nt = 0; nt < 8; nt++)
#pragma unroll
        for (int f = 0; f < 4; f++) accO[nt][f] = 0.f;
    float m0r = -1e30f, m1r = -1e30f, l0r = 0.f, l1r = 0.f;

    for (int kt = ktLo; kt < ktHi; kt++) {
        __syncthreads();
        for (int i = tid; i < 1024; i += 128) {
            int plane = i >> 9, rem = i & 511, row = rem >> 3, ch = (rem & 7) * 4;
            const uint32_t* src = plane ? klp : khp;
            uint4 v = *(const uint4*)&src[(size_t)(b * KTOK + kt * 64 + row) * 128 + kh * 32 + ch];
            uint32_t* dst = plane ? sm1 : sm0;
            *(uint4*)&dst[row * ATSU + ch] = v;
        }
        for (int i = tid; i < 1024; i += 128) {
            int plane = i >> 9, rem = i & 511, d = rem >> 3, ch = (rem & 7) * 4;
            const uint32_t* src = plane ? vtl : vth;
            uint4 v = *(const uint4*)&src[(size_t)((b * KVHEAD + kh) * HEADD + d) * TPH + kt * 32 + ch];
            uint32_t* dst = plane ? sm3 : sm2;
            *(uint4*)&dst[d * ATSU + ch] = v;
        }
        __syncthreads();

        float s[8][4];
#pragma unroll
        for (int nt = 0; nt < 8; nt++)
#pragma unroll
            for (int f = 0; f < 4; f++) s[nt][f] = 0.f;
#pragma unroll
        for (int kc = 0; kc < 4; kc++) {
            uint32_t bh[8][2], bl[8][2];
#pragma unroll
            for (int nt = 0; nt < 8; nt++) {
                int tok2 = nt * 8 + gid;
                bh[nt][0] = sm0[tok2 * ATSU + kc * 8 + tig];
                bh[nt][1] = sm0[tok2 * ATSU + kc * 8 + tig + 4];
                bl[nt][0] = sm1[tok2 * ATSU + kc * 8 + tig];
                bl[nt][1] = sm1[tok2 * ATSU + kc * 8 + tig + 4];
            }
            // 3 passes: dependency distance 8
#pragma unroll
            for (int nt = 0; nt < 8; nt++) mma_bf16(s[nt], qh[kc], bh[nt]);
#pragma unroll
            for (int nt = 0; nt < 8; nt++) mma_bf16(s[nt], ql[kc], bh[nt]);
#pragma unroll
            for (int nt = 0; nt < 8; nt++) mma_bf16(s[nt], qh[kc], bl[nt]);
        }
        if (kt == qt) {
            int r0 = warp * 16 + gid, r1 = r0 + 8;
#pragma unroll
            for (int nt = 0; nt < 8; nt++) {
                int c0 = nt * 8 + 2 * tig, c1 = c0 + 1;
                if (c0 > r0) s[nt][0] = -1e30f;
                if (c1 > r0) s[nt][1] = -1e30f;
                if (c0 > r1) s[nt][2] = -1e30f;
                if (c1 > r1) s[nt][3] = -1e30f;
            }
        }
        float mx0 = -1e30f, mx1 = -1e30f;
#pragma unroll
        for (int nt = 0; nt < 8; nt++) {
            mx0 = fmaxf(mx0, fmaxf(s[nt][0], s[nt][1]));
            mx1 = fmaxf(mx1, fmaxf(s[nt][2], s[nt][3]));
        }
        mx0 = fmaxf(mx0, __shfl_xor_sync(0xffffffffu, mx0, 1));
        mx0 = fmaxf(mx0, __shfl_xor_sync(0xffffffffu, mx0, 2));
        mx1 = fmaxf(mx1, __shfl_xor_sync(0xffffffffu, mx1, 1));
        mx1 = fmaxf(mx1, __shfl_xor_sync(0xffffffffu, mx1, 2));
        float mn0 = fmaxf(m0r, mx0), mn1 = fmaxf(m1r, mx1);
        float cor0 = __expf(m0r - mn0), cor1 = __expf(m1r - mn1);
        float ps0 = 0.f, ps1 = 0.f;
#pragma unroll
        for (int nt = 0; nt < 8; nt++) {
            s[nt][0] = __expf(s[nt][0] - mn0);
            s[nt][1] = __expf(s[nt][1] - mn0);
            s[nt][2] = __expf(s[nt][2] - mn1);
            s[nt][3] = __expf(s[nt][3] - mn1);
            ps0 += s[nt][0] + s[nt][1];
            ps1 += s[nt][2] + s[nt][3];
        }
        ps0 += __shfl_xor_sync(0xffffffffu, ps0, 1);
        ps0 += __shfl_xor_sync(0xffffffffu, ps0, 2);
        ps1 += __shfl_xor_sync(0xffffffffu, ps1, 1);
        ps1 += __shfl_xor_sync(0xffffffffu, ps1, 2);
        l0r = l0r * cor0 + ps0;  m0r = mn0;
        l1r = l1r * cor1 + ps1;  m1r = mn1;
#pragma unroll
        for (int nt = 0; nt < 8; nt++) {
            accO[nt][0] *= cor0; accO[nt][1] *= cor0;
            accO[nt][2] *= cor1; accO[nt][3] *= cor1;
        }
#pragma unroll
        for (int kc = 0; kc < 4; kc++) {
            uint32_t ph[4], pl[4];
            split_pair(s[2 * kc][0],     s[2 * kc][1],     ph[0], pl[0]);
            split_pair(s[2 * kc][2],     s[2 * kc][3],     ph[1], pl[1]);
            split_pair(s[2 * kc + 1][0], s[2 * kc + 1][1], ph[2], pl[2]);
            split_pair(s[2 * kc + 1][2], s[2 * kc + 1][3], ph[3], pl[3]);
            uint32_t vh[8][2], vl[8][2];
#pragma unroll
            for (int nt = 0; nt < 8; nt++) {
                int d = nt * 8 + gid;
                vh[nt][0] = sm2[d * ATSU + kc * 8 + tig];
                vh[nt][1] = sm2[d * ATSU + kc * 8 + tig + 4];
                vl[nt][0] = sm3[d * ATSU + kc * 8 + tig];
                vl[nt][1] = sm3[d * ATSU + kc * 8 + tig + 4];
            }
            // 3 passes: dependency distance 8
#pragma unroll
            for (int nt = 0; nt < 8; nt++) mma_bf16(accO[nt], ph, vh[nt]);
#pragma unroll
            for (int nt = 0; nt < 8; nt++) mma_bf16(accO[nt], pl, vh[nt]);
#pragma unroll
            for (int nt = 0; nt < 8; nt++) mma_bf16(accO[nt], ph, vl[nt]);
        }
    }
    int rl0 = warp * 16 + gid, rl1 = rl0 + 8;
    if (full) {
        float i0 = 1.f / l0r, i1 = 1.f / l1r;
        int row0 = b * KTOK + qt * 64 + rl0;
#pragma unroll
        for (int nt = 0; nt < 8; nt++) {
            int dp = (h * HEADD + nt * 8 + 2 * tig) >> 1;
            uint32_t hv, lv;
            split_pair(accO[nt][0] * i0, accO[nt][1] * i0, hv, lv);
            oh[(size_t)row0 * 512 + dp] = hv;
            ol[(size_t)row0 * 512 + dp] = lv;
            split_pair(accO[nt][2] * i1, accO[nt][3] * i1, hv, lv);
            oh[(size_t)(row0 + 8) * 512 + dp] = hv;
            ol[(size_t)(row0 + 8) * 512 + dp] = lv;
        }
    } else {
        int s2 = ((b * NHEAD + h) * NQS + (qt - QSPLIT)) * 2 + chunk;
        float* acc = pacc + (size_t)s2 * 64 * 64;
#pragma unroll
        for (int nt = 0; nt < 8; nt++) {
            int d = nt * 8 + 2 * tig;
            *(float2*)&acc[rl0 * 64 + d] = make_float2(accO[nt][0], accO[nt][1]);
            *(float2*)&acc[rl1 * 64 + d] = make_float2(accO[nt][2], accO[nt][3]);
        }
        if (tig == 0) {
            float* ml = pml + (size_t)s2 * 128;
            *(float2*)&ml[rl0 * 2] = make_float2(m0r, l0r);
            *(float2*)&ml[rl1 * 2] = make_float2(m1r, l1r);
        }
    }
}

// ---------------- attn merge ----------------
__global__ void __launch_bounds__(128)
attn_merge_kernel(const float* __restrict__ pacc, const float* __restrict__ pml,
                  uint32_t* __restrict__ oh, uint32_t* __restrict__ ol) {
    int qt = QSPLIT + blockIdx.x;
    int h = blockIdx.y, b = blockIdx.z;
    int sbase = ((b * NHEAD + h) * NQS + (qt - QSPLIT)) * 2;
    const float* a0 = pacc + (size_t)(sbase + 0) * 64 * 64;
    const float* a1 = pacc + (size_t)(sbase + 1) * 64 * 64;
    const float* ml0 = pml + (size_t)(sbase + 0) * 128;
    const float* ml1 = pml + (size_t)(sbase + 1) * 128;
    int tid = threadIdx.x;
    for (int t = tid; t < 2048; t += 128) {
        int r = t >> 5, dp = t & 31;
        float2 q0 = *(const float2*)&ml0[r * 2];
        float2 q1 = *(const float2*)&ml1[r * 2];
        float M = fmaxf(q0.x, q1.x);
        float w0 = __expf(q0.x - M), w1 = __expf(q1.x - M);
        float inv = 1.f / (w0 * q0.y + w1 * q1.y);
        float2 v0 = *(const float2*)&a0[r * 64 + 2 * dp];
        float2 v1 = *(const float2*)&a1[r * 64 + 2 * dp];
        float o0 = (w0 * v0.x + w1 * v1.x) * inv;
        float o1 = (w0 * v0.y + w1 * v1.y) * inv;
        uint32_t hv, lv;
        split_pair(o0, o1, hv, lv);
        size_t row = (size_t)(b * KTOK + qt * 64 + r);
        oh[row * 512 + h * 32 + dp] = hv;
        ol[row * 512 + h * 32 + dp] = lv;
    }
}

// ---------------- launch ----------------
extern "C" void kernel_launch(void* const* d_in, const int* in_sizes, int n_in,
                              void* d_out, int out_size) {
    const int*   ids      = (const int*)d_in[0];
    const float* emb      = (const float*)d_in[1];
    const float* router_k = (const float*)d_in[2];
    const float* router_q = (const float*)d_in[3];
    const float* ln1      = (const float*)d_in[4];
    const float* ln2      = (const float*)d_in[5];
    const float* wq       = (const float*)d_in[6];
    const float* bq       = (const float*)d_in[7];
    const float* wk       = (const float*)d_in[8];
    const float* bk       = (const float*)d_in[9];
    const float* wv       = (const float*)d_in[10];
    const float* bv       = (const float*)d_in[11];
    const float* wo       = (const float*)d_in[12];
    const float* wg       = (const float*)d_in[13];
    const float* wu       = (const float*)d_in[14];
    const float* wd       = (const float*)d_in[15];
    float* hidden = (float*)d_out;

    float *x, *vbuf, *pooled, *scores, *bqkv, *pacc, *pml;
    int* tok;
    uint32_t *wqkvh, *wqkvl, *woh, *wol, *wguh, *wgul, *wdh, *wdl;
    uint32_t *hh, *hl, *oh, *ol, *gh, *gl;
    uint32_t *qhp, *qlp, *khp, *klp, *vth, *vtl;
    cudaGetSymbolAddress((void**)&x, g_x);
    cudaGetSymbolAddress((void**)&vbuf, g_vbuf);
    cudaGetSymbolAddress((void**)&pooled, g_pool);
    cudaGetSymbolAddress((void**)&scores, g_scores);
    cudaGetSymbolAddress((void**)&tok, g_tok);
    cudaGetSymbolAddress((void**)&bqkv, g_bqkv);
    cudaGetSymbolAddress((void**)&wqkvh, g_wqkvh); cudaGetSymbolAddress((void**)&wqkvl, g_wqkvl);
    cudaGetSymbolAddress((void**)&woh, g_woh);     cudaGetSymbolAddress((void**)&wol, g_wol);
    cudaGetSymbolAddress((void**)&wguh, g_wguh);   cudaGetSymbolAddress((void**)&wgul, g_wgul);
    cudaGetSymbolAddress((void**)&wdh, g_wdh);     cudaGetSymbolAddress((void**)&wdl, g_wdl);
    cudaGetSymbolAddress((void**)&hh, g_hh);       cudaGetSymbolAddress((void**)&hl, g_hl);
    cudaGetSymbolAddress((void**)&oh, g_oh);       cudaGetSymbolAddress((void**)&ol, g_ol);
    cudaGetSymbolAddress((void**)&gh, g_gh);       cudaGetSymbolAddress((void**)&gl, g_gl);
    cudaGetSymbolAddress((void**)&qhp, g_qhp);     cudaGetSymbolAddress((void**)&qlp, g_qlp);
    cudaGetSymbolAddress((void**)&khp, g_khp);     cudaGetSymbolAddress((void**)&klp, g_klp);
    cudaGetSymbolAddress((void**)&vth, g_vth);     cudaGetSymbolAddress((void**)&vtl, g_vtl);
    cudaGetSymbolAddress((void**)&pacc, g_pacc);   cudaGetSymbolAddress((void**)&pml, g_pml);

    cudaFuncSetAttribute((const void*)pgemm_kernel<8,4>, cudaFuncAttributeMaxDynamicSharedMemorySize, SM_PGEMM4);
    cudaFuncSetAttribute((const void*)pgemm_kernel<4,4>, cudaFuncAttributeMaxDynamicSharedMemorySize, SM_PGEMM4);
    cudaFuncSetAttribute((const void*)pgemm_kernel<2,2>, cudaFuncAttributeMaxDynamicSharedMemorySize, SM_PGEMM2);

    embed_kernel<<<BATCH * SEQ, 256>>>(ids, emb, hidden);

    prepack_gu_kernel<<<NLAYER * 512 * 1408 / 256, 256>>>(wg, wu, wguh, wgul);
    prepack_qkv_kernel<<<NLAYER * 512 * 384 / 256, 256>>>(wq, wk, wv, wqkvh, wqkvl);
    prepack_kernel<<<NLAYER * 512 * 1024 / 1024, 256>>>(wo, woh, wol, 256, 1024);
    prepack_kernel<<<NLAYER * 1408 * 1024 / 1024, 256>>>(wd, wdh, wdl, 256, 1024);
    fuse_bias_kernel<<<NLAYER * NQKV / 256, 256>>>(bq, bk, bv, bqkv);

    for (int blk = 0; blk < NBLK; blk++) {
        int li0 = blk * BPL;
        pool_kernel<<<BATCH * NSEG, 256>>>(hidden, pooled);
        router_kernel<<<dim3(NSEG, BATCH), 128>>>(
            pooled, router_k + (size_t)blk * DIM * RANKR,
            router_q + (size_t)blk * NQRY * RANKR, scores);
        select_kernel<<<BATCH, 256>>>(scores, tok);
        gather_norm_kernel<<<BT, 256>>>(hidden, tok, ln1 + (size_t)li0 * DIM, x, hh, hl);

        for (int j = 0; j < BPL; j++) {
            int li = li0 + j;
            size_t oqkv = (size_t)li * 512 * NQKV;
            size_t oo   = (size_t)li * 512 * 1024;
            size_t ogu  = (size_t)li * 512 * NGU;
            size_t od   = (size_t)li * 1408 * 1024;

            if (j > 0)
                rmsnorm_kernel<<<BT, 256>>>(x, ln1 + (size_t)li * DIM, hh, hl);
            pgemm_kernel<8,4><<<dim3(NQKV / 128, BT / 128), 256, SM_PGEMM4>>>(
                hh, hl, wqkvh + oqkv, wqkvl + oqkv, bqkv + (size_t)li * NQKV,
                vbuf, qhp, qlp, khp, klp, tok, BT, NQKV, 512);
            prep_v_kernel<<<BT / 2, 256>>>(vbuf, vth, vtl);
            attn_mma_kernel<<<dim3(NCID, NHEAD, BATCH), 128>>>(
                qhp, qlp, khp, klp, vth, vtl, oh, ol, pacc, pml);
            attn_merge_kernel<<<dim3(NQS, NHEAD, BATCH), 128>>>(pacc, pml, oh, ol);
            pgemm_kernel<2,2><<<dim3(8, BT / 64), 256, SM_PGEMM2>>>(
                oh, ol, woh + oo, wol + oo, nullptr, x, nullptr, nullptr, nullptr, nullptr,
                nullptr, BT, 1024, 512);
            rmsnorm_kernel<<<BT, 256>>>(x, ln2 + (size_t)li * DIM, hh, hl);
            pgemm_kernel<4,4><<<dim3(NGU / 128, BT / 128), 256, SM_PGEMM4>>>(
                hh, hl, wguh + ogu, wgul + ogu, nullptr, nullptr, gh, gl, nullptr, nullptr,
                nullptr, BT, NGU, 512);
            pgemm_kernel<2,2><<<dim3(8, BT / 64), 256, SM_PGEMM2>>>(
                gh, gl, wdh + od, wdl + od, nullptr, x, nullptr, nullptr, nullptr, nullptr,
                nullptr, BT, 1024, 1408);
        }
        scatter_kernel<<<BT, 256>>>(x, tok, hidden);
    }
}